// round 6
// baseline (speedup 1.0000x reference)
#include <cuda_runtime.h>
#include <cuda_bf16.h>
#include <math.h>
#include <stdint.h>

// Problem constants
#define B_SZ 2
#define SEQ 2048
#define DMODEL 2048
#define NHEAD 16
#define DHEAD 128
#define MTOT (B_SZ * SEQ)   // 4096

// ---------------- scratch (device globals; no allocation allowed) ---------------
__device__ float g_q[(size_t)MTOT * DMODEL];
__device__ float g_k[(size_t)MTOT * DMODEL];

__device__ __nv_bfloat16 g_xh[(size_t)MTOT * DMODEL];
__device__ __nv_bfloat16 g_xl[(size_t)MTOT * DMODEL];
__device__ __nv_bfloat16 g_oh[(size_t)MTOT * DMODEL];
__device__ __nv_bfloat16 g_ol[(size_t)MTOT * DMODEL];
__device__ __nv_bfloat16 g_kh[(size_t)MTOT * DMODEL];
__device__ __nv_bfloat16 g_kl[(size_t)MTOT * DMODEL];
__device__ __nv_bfloat16 g_vh[(size_t)MTOT * DMODEL];
__device__ __nv_bfloat16 g_vl[(size_t)MTOT * DMODEL];
__device__ __nv_bfloat16 g_wqh[(size_t)DMODEL * DMODEL];
__device__ __nv_bfloat16 g_wql[(size_t)DMODEL * DMODEL];
__device__ __nv_bfloat16 g_wkh[(size_t)DMODEL * DMODEL];
__device__ __nv_bfloat16 g_wkl[(size_t)DMODEL * DMODEL];
__device__ __nv_bfloat16 g_wvh[(size_t)DMODEL * DMODEL];
__device__ __nv_bfloat16 g_wvl[(size_t)DMODEL * DMODEL];
__device__ __nv_bfloat16 g_woh[(size_t)DMODEL * DMODEL];
__device__ __nv_bfloat16 g_wol[(size_t)DMODEL * DMODEL];

// ================= helpers ======================================================
__device__ __forceinline__ uint32_t smem_to_u32(const void* p) {
    uint32_t a;
    asm("{ .reg .u64 t; cvta.to.shared.u64 t, %1; cvt.u32.u64 %0, t; }" : "=r"(a) : "l"(p));
    return a;
}
#define CP_ASYNC16(dst, src) \
    asm volatile("cp.async.cg.shared.global [%0], [%1], 16;" :: "r"(dst), "l"(src) : "memory")
#define CP_COMMIT() asm volatile("cp.async.commit_group;" ::: "memory")
#define CP_WAIT(n)  asm volatile("cp.async.wait_group %0;" :: "n"(n) : "memory")

__device__ __forceinline__ void ldsm_x4(uint32_t& r0, uint32_t& r1, uint32_t& r2, uint32_t& r3,
                                        uint32_t addr) {
    asm volatile("ldmatrix.sync.aligned.m8n8.x4.shared.b16 {%0,%1,%2,%3}, [%4];"
                 : "=r"(r0), "=r"(r1), "=r"(r2), "=r"(r3) : "r"(addr));
}
__device__ __forceinline__ void ldsm_x4_t(uint32_t& r0, uint32_t& r1, uint32_t& r2, uint32_t& r3,
                                          uint32_t addr) {
    asm volatile("ldmatrix.sync.aligned.m8n8.x4.trans.shared.b16 {%0,%1,%2,%3}, [%4];"
                 : "=r"(r0), "=r"(r1), "=r"(r2), "=r"(r3) : "r"(addr));
}
__device__ __forceinline__ void mma_bf16(float* c, const uint32_t* a, const uint32_t* b) {
    asm volatile(
        "mma.sync.aligned.m16n8k16.row.col.f32.bf16.bf16.f32 "
        "{%0,%1,%2,%3}, {%4,%5,%6,%7}, {%8,%9}, {%0,%1,%2,%3};"
        : "+f"(c[0]), "+f"(c[1]), "+f"(c[2]), "+f"(c[3])
        : "r"(a[0]), "r"(a[1]), "r"(a[2]), "r"(a[3]), "r"(b[0]), "r"(b[1]));
}
__device__ __forceinline__ uint32_t pack_bf16x2(float lo, float hi) {
    uint32_t r;
    asm("cvt.rn.bf16x2.f32 %0, %1, %2;" : "=r"(r) : "f"(hi), "f"(lo));
    return r;
}
// pack (v0,v1) into hi bf16x2 + residual-lo bf16x2
__device__ __forceinline__ void split_pair(float v0, float v1, uint32_t& h, uint32_t& l) {
    h = pack_bf16x2(v0, v1);
    __nv_bfloat162 hb = *(__nv_bfloat162*)&h;
    l = pack_bf16x2(v0 - __bfloat162float(hb.x), v1 - __bfloat162float(hb.y));
}

// ================= fp32 -> bf16 hi/lo split (x) =================================
__global__ void __launch_bounds__(256) split_bf16(const float* __restrict__ in,
                                                  __nv_bfloat16* __restrict__ hi,
                                                  __nv_bfloat16* __restrict__ lo,
                                                  int n4) {
    int i = blockIdx.x * blockDim.x + threadIdx.x;
    if (i >= n4) return;
    float4 v = ((const float4*)in)[i];
    uint32_t h0, l0, h1, l1;
    split_pair(v.x, v.y, h0, l0);
    split_pair(v.z, v.w, h1, l1);
    ((uint32_t*)hi)[2 * i]     = h0;
    ((uint32_t*)hi)[2 * i + 1] = h1;
    ((uint32_t*)lo)[2 * i]     = l0;
    ((uint32_t*)lo)[2 * i + 1] = l1;
}

// ================= fused split of 4 weight matrices =============================
__global__ void __launch_bounds__(256) split_weights(const float* __restrict__ w0,
                                                     const float* __restrict__ w1,
                                                     const float* __restrict__ w2,
                                                     const float* __restrict__ w3) {
    const int NW4 = DMODEL * DMODEL / 4;
    int gi = blockIdx.x * blockDim.x + threadIdx.x;
    int which = gi / NW4;
    int i = gi - which * NW4;
    const float* in;
    __nv_bfloat16 *hi, *lo;
    switch (which) {
        case 0:  in = w0; hi = g_wqh; lo = g_wql; break;
        case 1:  in = w1; hi = g_wkh; lo = g_wkl; break;
        case 2:  in = w2; hi = g_wvh; lo = g_wvl; break;
        default: in = w3; hi = g_woh; lo = g_wol; break;
    }
    float4 v = ((const float4*)in)[i];
    uint32_t h0, l0, h1, l1;
    split_pair(v.x, v.y, h0, l0);
    split_pair(v.z, v.w, h1, l1);
    ((uint32_t*)hi)[2 * i]     = h0;
    ((uint32_t*)hi)[2 * i + 1] = h1;
    ((uint32_t*)lo)[2 * i]     = l0;
    ((uint32_t*)lo)[2 * i + 1] = l1;
}

// ================= HMMA GEMM core (shared by QKV and O) =========================
#define GBM 128
#define GBN 128
#define GBK 32
#define PITCHB 80
#define TILE_B (128 * PITCHB)
#define STAGE_B (4 * TILE_B)
#define GSMEM (2 * STAGE_B)

// computes 128x128 tile acc for C = A @ B^T at (m0, n0)
template <typename EPI>
__device__ __forceinline__ void gemm_body(const __nv_bfloat16* Ah, const __nv_bfloat16* Al,
                                          const __nv_bfloat16* Bh, const __nv_bfloat16* Bl,
                                          int m0, int n0, int Kd, char* smem, EPI epi) {
    const uint32_t sbase = smem_to_u32(smem);
    const int tid = threadIdx.x;
    const int wid = tid >> 5;
    const int lid = tid & 31;

    const int wm = (wid >> 2) * 64;
    const int wn = (wid & 3) * 32;

    const int lrow = (lid & 7) + ((lid >> 3) & 1) * 8;
    const int lcolb = ((lid >> 4) & 1) * 16;

    const __nv_bfloat16* srcs[4] = {
        Ah + (size_t)m0 * Kd, Al + (size_t)m0 * Kd,
        Bh + (size_t)n0 * Kd, Bl + (size_t)n0 * Kd };

    const int nchunk = Kd / GBK;

    float acc[4][4][4];
#pragma unroll
    for (int a = 0; a < 4; a++)
#pragma unroll
        for (int b = 0; b < 4; b++)
#pragma unroll
            for (int cc = 0; cc < 4; cc++) acc[a][b][cc] = 0.f;

    auto issue_loads = [&](int c) {
        const int buf = c & 1;
        const uint32_t so = sbase + buf * STAGE_B;
        const int kc = c * GBK;
#pragma unroll
        for (int j = 0; j < 8; j++) {
            int idx = j * 256 + tid;
            int tile = idx >> 9;
            int row = (idx >> 2) & 127;
            int ck = idx & 3;
            const __nv_bfloat16* src = srcs[tile] + (size_t)row * Kd + kc + ck * 8;
            uint32_t dst = so + tile * TILE_B + row * PITCHB + ck * 16;
            CP_ASYNC16(dst, src);
        }
        CP_COMMIT();
    };

    issue_loads(0);

    for (int c = 0; c < nchunk; c++) {
        const int buf = c & 1;
        if (c + 1 < nchunk) {
            issue_loads(c + 1);
            CP_WAIT(1);
        } else {
            CP_WAIT(0);
        }
        __syncthreads();

        const uint32_t so = sbase + buf * STAGE_B;
        const uint32_t t_ah = so + 0 * TILE_B;
        const uint32_t t_al = so + 1 * TILE_B;
        const uint32_t t_bh = so + 2 * TILE_B;
        const uint32_t t_bl = so + 3 * TILE_B;

#pragma unroll
        for (int kk = 0; kk < 2; kk++) {
            const uint32_t kb = kk * 32 + lcolb;

            uint32_t bh[4][2], bl[4][2];
#pragma unroll
            for (int g = 0; g < 2; g++) {
                uint32_t addr = t_bh + (wn + g * 16 + lrow) * PITCHB + kb;
                uint32_t r0, r1, r2, r3;
                ldsm_x4(r0, r1, r2, r3, addr);
                bh[g * 2 + 0][0] = r0; bh[g * 2 + 0][1] = r2;
                bh[g * 2 + 1][0] = r1; bh[g * 2 + 1][1] = r3;
                addr = t_bl + (wn + g * 16 + lrow) * PITCHB + kb;
                ldsm_x4(r0, r1, r2, r3, addr);
                bl[g * 2 + 0][0] = r0; bl[g * 2 + 0][1] = r2;
                bl[g * 2 + 1][0] = r1; bl[g * 2 + 1][1] = r3;
            }

#pragma unroll
            for (int mt = 0; mt < 4; mt++) {
                uint32_t ah[4], al[4];
                uint32_t addr = t_ah + (wm + mt * 16 + lrow) * PITCHB + kb;
                ldsm_x4(ah[0], ah[1], ah[2], ah[3], addr);
                addr = t_al + (wm + mt * 16 + lrow) * PITCHB + kb;
                ldsm_x4(al[0], al[1], al[2], al[3], addr);
#pragma unroll
                for (int nt = 0; nt < 4; nt++) {
                    mma_bf16(acc[mt][nt], ah, bh[nt]);
                    mma_bf16(acc[mt][nt], ah, bl[nt]);
                    mma_bf16(acc[mt][nt], al, bh[nt]);
                }
            }
        }
        __syncthreads();
    }

    const int er = lid >> 2;
    const int ec = (lid & 3) * 2;
#pragma unroll
    for (int mt = 0; mt < 4; mt++) {
#pragma unroll
        for (int nt = 0; nt < 4; nt++) {
            int m = wm + mt * 16 + er;
            int n = wn + nt * 8 + ec;
            epi(m,     n, acc[mt][nt][0], acc[mt][nt][1]);
            epi(m + 8, n, acc[mt][nt][2], acc[mt][nt][3]);
        }
    }
}

// QKV fused GEMM: blockIdx.x selects weight (0..47), Q/K -> fp32, V -> bf16 hi/lo
__global__ void __launch_bounds__(256) gemm_qkv(const __nv_bfloat16* __restrict__ xh,
                                                const __nv_bfloat16* __restrict__ xl) {
    extern __shared__ char smem[];
    const int wsel = blockIdx.x >> 4;
    const int n0 = (blockIdx.x & 15) * GBN;
    const int m0 = blockIdx.y * GBM;

    const __nv_bfloat16* Bh = (wsel == 0) ? g_wqh : (wsel == 1) ? g_wkh : g_wvh;
    const __nv_bfloat16* Bl = (wsel == 0) ? g_wql : (wsel == 1) ? g_wkl : g_wvl;

    if (wsel < 2) {
        float* C = (wsel == 0) ? g_q : g_k;
        gemm_body(xh, xl, Bh, Bl, m0, n0, DMODEL,
                  smem, [&](int m, int n, float v0, float v1) {
            *(float2*)&C[(size_t)(m0 + m) * DMODEL + n0 + n] = make_float2(v0, v1);
        });
    } else {
        gemm_body(xh, xl, Bh, Bl, m0, n0, DMODEL,
                  smem, [&](int m, int n, float v0, float v1) {
            uint32_t h, l;
            split_pair(v0, v1, h, l);
            size_t off = (size_t)(m0 + m) * DMODEL + n0 + n;
            *(uint32_t*)&g_vh[off] = h;
            *(uint32_t*)&g_vl[off] = l;
        });
    }
}

// O projection GEMM: oh/ol @ Wo^T -> fp32 out
__global__ void __launch_bounds__(256) gemm_out(float* __restrict__ out) {
    extern __shared__ char smem[];
    const int n0 = blockIdx.x * GBN;
    const int m0 = blockIdx.y * GBM;
    gemm_body(g_oh, g_ol, g_woh, g_wol, m0, n0, DMODEL,
              smem, [&](int m, int n, float v0, float v1) {
        *(float2*)&out[(size_t)(m0 + m) * DMODEL + n0 + n] = make_float2(v0, v1);
    });
}

// ---------------- fused RoPE: Q in-place fp32, K -> bf16 hi/lo ------------------
__global__ void rope_qk(float* __restrict__ qd, const float* __restrict__ kd) {
    int idx = blockIdx.x * blockDim.x + threadIdx.x;
    const int pairs_per_head = DHEAD / 2;              // 64
    const int per_tensor = B_SZ * SEQ * NHEAD * pairs_per_head;
    const bool is_k = idx >= per_tensor;
    if (is_k) idx -= per_tensor;

    int i = idx % pairs_per_head;
    int h = (idx / pairs_per_head) % NHEAD;
    int s = (idx / (pairs_per_head * NHEAD)) % SEQ;
    int b = idx / (pairs_per_head * NHEAD * SEQ);

    float inv_freq = powf(10000.0f, -(float)(2 * i) / (float)DHEAD);
    float ang = (float)s * inv_freq;
    float sn, cs;
    sincosf(ang, &sn, &cs);

    size_t off = ((size_t)(b * SEQ + s)) * DMODEL + h * DHEAD + 2 * i;
    if (!is_k) {
        float e = qd[off], o = qd[off + 1];
        qd[off]     = e * cs - o * sn;
        qd[off + 1] = e * sn + o * cs;
    } else {
        float e = kd[off], o = kd[off + 1];
        float r0 = e * cs - o * sn;
        float r1 = e * sn + o * cs;
        uint32_t hh, ll;
        split_pair(r0, r1, hh, ll);
        *(uint32_t*)&g_kh[off] = hh;
        *(uint32_t*)&g_kl[off] = ll;
    }
}

// ================= HMMA flash attention (causal) ================================
#define FBM 128
#define FBN 64
#define FCH (64 * 80)
#define FARR (4 * FCH)
#define FSTAGE (4 * FARR)
#define FSMEM (2 * FSTAGE)       // 163840

__global__ void __launch_bounds__(256) flash_hmma(const float* __restrict__ Qf) {
    extern __shared__ char smem[];
    const uint32_t sbase = smem_to_u32(smem);
    const int tid = threadIdx.x;
    const int wid = tid >> 5;
    const int lid = tid & 31;
    const int qb = blockIdx.x;
    const int h  = blockIdx.y;
    const int b  = blockIdx.z;
    const int q0 = qb * FBM;
    const int wm = wid * 16;

    const int lrow  = (lid & 7) + ((lid >> 3) & 1) * 8;
    const int lcolb = ((lid >> 4) & 1) * 16;
    const int r4  = lid >> 2;
    const int c2  = (lid & 3) * 2;

    const float scale = 0.08838834764831845f;   // 1/sqrt(128)

    uint32_t qh[8][4], ql[8][4];
    {
        const float* qr0 = Qf + ((size_t)(b * SEQ + q0 + wm + r4)) * DMODEL + h * DHEAD;
        const float* qr1 = qr0 + (size_t)8 * DMODEL;
#pragma unroll
        for (int ks = 0; ks < 8; ks++) {
#pragma unroll
            for (int half = 0; half < 2; half++) {
                float2 v0 = *(const float2*)(qr0 + ks * 16 + half * 8 + c2);
                float2 v1 = *(const float2*)(qr1 + ks * 16 + half * 8 + c2);
                uint32_t h0, l0, h1, l1;
                split_pair(v0.x * scale, v0.y * scale, h0, l0);
                split_pair(v1.x * scale, v1.y * scale, h1, l1);
                qh[ks][half * 2 + 0] = h0; qh[ks][half * 2 + 1] = h1;
                ql[ks][half * 2 + 0] = l0; ql[ks][half * 2 + 1] = l1;
            }
        }
    }

    float Oa[16][4];
#pragma unroll
    for (int t = 0; t < 16; t++)
#pragma unroll
        for (int c = 0; c < 4; c++) Oa[t][c] = 0.f;
    float m_i[2] = {-1e30f, -1e30f};
    float l_i[2] = {0.f, 0.f};

    const int ntile = (q0 + FBM) / FBN;

    const __nv_bfloat16* asrc[4] = {
        g_kh + ((size_t)(b * SEQ)) * DMODEL + h * DHEAD,
        g_kl + ((size_t)(b * SEQ)) * DMODEL + h * DHEAD,
        g_vh + ((size_t)(b * SEQ)) * DMODEL + h * DHEAD,
        g_vl + ((size_t)(b * SEQ)) * DMODEL + h * DHEAD };

    auto issue_loads = [&](int t) {
        const uint32_t so = sbase + (t & 1) * FSTAGE;
        const int k0 = t * FBN;
#pragma unroll
        for (int j = 0; j < 16; j++) {
            int idx = j * 256 + tid;
            int arr  = idx >> 10;
            int g    = idx & 1023;
            int row  = g >> 4;
            int gran = g & 15;
            const __nv_bfloat16* src = asrc[arr] + (size_t)(k0 + row) * DMODEL + gran * 8;
            uint32_t dst = so + arr * FARR + (gran >> 2) * FCH + row * 80 + (gran & 3) * 16;
            CP_ASYNC16(dst, src);
        }
        CP_COMMIT();
    };

    issue_loads(0);

    for (int t = 0; t < ntile; t++) {
        if (t + 1 < ntile) {
            issue_loads(t + 1);
            CP_WAIT(1);
        } else {
            CP_WAIT(0);
        }
        __syncthreads();

        const int k0 = t * FBN;
        const bool skip = (k0 > q0 + wm + 15);

        if (!skip) {
            const uint32_t so = sbase + (t & 1) * FSTAGE;
            const uint32_t kh_s = so + 0 * FARR;
            const uint32_t kl_s = so + 1 * FARR;
            const uint32_t vh_s = so + 2 * FARR;
            const uint32_t vl_s = so + 3 * FARR;

            float S[8][4];
#pragma unroll
            for (int j = 0; j < 8; j++)
#pragma unroll
                for (int c = 0; c < 4; c++) S[j][c] = 0.f;

#pragma unroll
            for (int ks = 0; ks < 8; ks++) {
                const uint32_t co = (ks >> 1) * FCH + (ks & 1) * 32 + lcolb;
                uint32_t khf[8][2], klf[8][2];
#pragma unroll
                for (int g = 0; g < 4; g++) {
                    uint32_t r0, r1, r2, r3;
                    ldsm_x4(r0, r1, r2, r3, kh_s + co + (g * 16 + lrow) * 80);
                    khf[g * 2 + 0][0] = r0; khf[g * 2 + 0][1] = r2;
                    khf[g * 2 + 1][0] = r1; khf[g * 2 + 1][1] = r3;
                    ldsm_x4(r0, r1, r2, r3, kl_s + co + (g * 16 + lrow) * 80);
                    klf[g * 2 + 0][0] = r0; klf[g * 2 + 0][1] = r2;
                    klf[g * 2 + 1][0] = r1; klf[g * 2 + 1][1] = r3;
                }
#pragma unroll
                for (int j = 0; j < 8; j++) {
                    mma_bf16(S[j], qh[ks], khf[j]);
                    mma_bf16(S[j], qh[ks], klf[j]);
                    mma_bf16(S[j], ql[ks], khf[j]);
                }
            }

            const int qg0 = q0 + wm + r4;
            const int qg1 = qg0 + 8;
            if (k0 + FBN - 1 > q0 + wm) {
#pragma unroll
                for (int j = 0; j < 8; j++) {
                    int kc = k0 + j * 8 + c2;
                    if (kc     > qg0) S[j][0] = -1e30f;
                    if (kc + 1 > qg0) S[j][1] = -1e30f;
                    if (kc     > qg1) S[j][2] = -1e30f;
                    if (kc + 1 > qg1) S[j][3] = -1e30f;
                }
            }

            float mx0 = -1e30f, mx1 = -1e30f;
#pragma unroll
            for (int j = 0; j < 8; j++) {
                mx0 = fmaxf(mx0, fmaxf(S[j][0], S[j][1]));
                mx1 = fmaxf(mx1, fmaxf(S[j][2], S[j][3]));
            }
            mx0 = fmaxf(mx0, __shfl_xor_sync(0xffffffffu, mx0, 1));
            mx0 = fmaxf(mx0, __shfl_xor_sync(0xffffffffu, mx0, 2));
            mx1 = fmaxf(mx1, __shfl_xor_sync(0xffffffffu, mx1, 1));
            mx1 = fmaxf(mx1, __shfl_xor_sync(0xffffffffu, mx1, 2));

            float mn0 = fmaxf(m_i[0], mx0);
            float mn1 = fmaxf(m_i[1], mx1);
            float a0 = __expf(m_i[0] - mn0);
            float a1 = __expf(m_i[1] - mn1);

            float s0 = 0.f, s1 = 0.f;
#pragma unroll
            for (int j = 0; j < 8; j++) {
                float e0 = (S[j][0] > -5e29f) ? __expf(S[j][0] - mn0) : 0.f;
                float e1 = (S[j][1] > -5e29f) ? __expf(S[j][1] - mn0) : 0.f;
                float e2 = (S[j][2] > -5e29f) ? __expf(S[j][2] - mn1) : 0.f;
                float e3 = (S[j][3] > -5e29f) ? __expf(S[j][3] - mn1) : 0.f;
                S[j][0] = e0; S[j][1] = e1; S[j][2] = e2; S[j][3] = e3;
                s0 += e0 + e1; s1 += e2 + e3;
            }
            s0 += __shfl_xor_sync(0xffffffffu, s0, 1);
            s0 += __shfl_xor_sync(0xffffffffu, s0, 2);
            s1 += __shfl_xor_sync(0xffffffffu, s1, 1);
            s1 += __shfl_xor_sync(0xffffffffu, s1, 2);

            l_i[0] = l_i[0] * a0 + s0;
            l_i[1] = l_i[1] * a1 + s1;
            m_i[0] = mn0; m_i[1] = mn1;
#pragma unroll
            for (int tt = 0; tt < 16; tt++) {
                Oa[tt][0] *= a0; Oa[tt][1] *= a0;
                Oa[tt][2] *= a1; Oa[tt][3] *= a1;
            }

            uint32_t ph[4][4], pl[4][4];
#pragma unroll
            for (int ks = 0; ks < 4; ks++) {
#pragma unroll
                for (int half = 0; half < 2; half++) {
                    uint32_t h0, l0, h1, l1;
                    split_pair(S[2 * ks + half][0], S[2 * ks + half][1], h0, l0);
                    split_pair(S[2 * ks + half][2], S[2 * ks + half][3], h1, l1);
                    ph[ks][half * 2 + 0] = h0; ph[ks][half * 2 + 1] = h1;
                    pl[ks][half * 2 + 0] = l0; pl[ks][half * 2 + 1] = l1;
                }
            }

#pragma unroll
            for (int ks = 0; ks < 4; ks++) {
#pragma unroll
                for (int tp = 0; tp < 8; tp++) {
                    int dbase = tp * 16;
                    int g2 = lid >> 3;
                    int rr = lid & 7;
                    int seqrow = ks * 16 + (g2 & 1) * 8 + rr;
                    int de = dbase + (g2 >> 1) * 8;
                    uint32_t addr_off = (de >> 5) * FCH + seqrow * 80 + ((de & 31) >> 3) * 16;
                    uint32_t b0, b1, b2, b3;
                    ldsm_x4_t(b0, b1, b2, b3, vh_s + addr_off);
                    uint32_t vhf0[2] = {b0, b1}, vhf1[2] = {b2, b3};
                    ldsm_x4_t(b0, b1, b2, b3, vl_s + addr_off);
                    uint32_t vlf0[2] = {b0, b1}, vlf1[2] = {b2, b3};
                    mma_bf16(Oa[2 * tp],     ph[ks], vhf0);
                    mma_bf16(Oa[2 * tp],     pl[ks], vhf0);
                    mma_bf16(Oa[2 * tp],     ph[ks], vlf0);
                    mma_bf16(Oa[2 * tp + 1], ph[ks], vhf1);
                    mma_bf16(Oa[2 * tp + 1], pl[ks], vhf1);
                    mma_bf16(Oa[2 * tp + 1], ph[ks], vlf1);
                }
            }
        }
        __syncthreads();
    }

    // ---- write out as bf16 hi/lo (feeds gemm_out directly) ----
    float inv0 = 1.0f / l_i[0];
    float inv1 = 1.0f / l_i[1];
    size_t off0 = ((size_t)(b * SEQ + q0 + wm + r4)) * DMODEL + h * DHEAD;
    size_t off1 = off0 + (size_t)8 * DMODEL;
#pragma unroll
    for (int tt = 0; tt < 16; tt++) {
        uint32_t h0, l0, h1, l1;
        split_pair(Oa[tt][0] * inv0, Oa[tt][1] * inv0, h0, l0);
        split_pair(Oa[tt][2] * inv1, Oa[tt][3] * inv1, h1, l1);
        *(uint32_t*)&g_oh[off0 + tt * 8 + c2] = h0;
        *(uint32_t*)&g_ol[off0 + tt * 8 + c2] = l0;
        *(uint32_t*)&g_oh[off1 + tt * 8 + c2] = h1;
        *(uint32_t*)&g_ol[off1 + tt * 8 + c2] = l1;
    }
}

// ---------------- launch --------------------------------------------------------
extern "C" void kernel_launch(void* const* d_in, const int* in_sizes, int n_in,
                              void* d_out, int out_size) {
    const float* x  = (const float*)d_in[0];
    const float* wq = (const float*)d_in[1];
    const float* wk = (const float*)d_in[2];
    const float* wv = (const float*)d_in[3];
    const float* wo = (const float*)d_in[4];
    float* out = (float*)d_out;

    float *q, *k;
    __nv_bfloat16 *xh, *xl;
    cudaGetSymbolAddress((void**)&q, g_q);
    cudaGetSymbolAddress((void**)&k, g_k);
    cudaGetSymbolAddress((void**)&xh, g_xh);
    cudaGetSymbolAddress((void**)&xl, g_xl);

    const int NX4 = MTOT * DMODEL / 4;     // 2097152
    const int NW4 = DMODEL * DMODEL / 4;   // 1048576

    // 1: split x
    split_bf16<<<NX4 / 256, 256>>>(x, xh, xl, NX4);
    // 2: split 4 weights (fused)
    split_weights<<<4 * NW4 / 256, 256>>>(wq, wk, wv, wo);

    // 3: fused QKV GEMM (1536 CTAs)
    cudaFuncSetAttribute(gemm_qkv, cudaFuncAttributeMaxDynamicSharedMemorySize, GSMEM);
    gemm_qkv<<<dim3(3 * DMODEL / GBN, MTOT / GBM), 256, GSMEM>>>(xh, xl);

    // 4: fused rope (Q fp32 in-place, K -> bf16 hi/lo)
    int rope_total = 2 * B_SZ * SEQ * NHEAD * (DHEAD / 2);
    rope_qk<<<rope_total / 256, 256>>>(q, k);

    // 5: flash attention -> bf16 hi/lo O
    cudaFuncSetAttribute(flash_hmma, cudaFuncAttributeMaxDynamicSharedMemorySize, FSMEM);
    flash_hmma<<<dim3(SEQ / FBM, NHEAD, B_SZ), 256, FSMEM>>>(q);

    // 6: output projection (ncu -s 5 captures this one)
    cudaFuncSetAttribute(gemm_out, cudaFuncAttributeMaxDynamicSharedMemorySize, GSMEM);
    gemm_out<<<dim3(DMODEL / GBN, MTOT / GBM), 256, GSMEM>>>(out);
}

// round 7
// speedup vs baseline: 1.0011x; 1.0011x over previous
#include <cuda_runtime.h>
#include <cuda_bf16.h>
#include <math.h>
#include <stdint.h>

// Problem constants
#define B_SZ 2
#define SEQ 2048
#define DMODEL 2048
#define NHEAD 16
#define DHEAD 128
#define MTOT (B_SZ * SEQ)   // 4096

// ---------------- scratch (device globals; no allocation allowed) ---------------
__device__ float g_q[(size_t)MTOT * DMODEL];
__device__ float g_k[(size_t)MTOT * DMODEL];
__device__ float2 g_rope[(size_t)SEQ * (DHEAD / 2)];   // cos/sin LUT

__device__ __nv_bfloat16 g_xh[(size_t)MTOT * DMODEL];
__device__ __nv_bfloat16 g_xl[(size_t)MTOT * DMODEL];
__device__ __nv_bfloat16 g_oh[(size_t)MTOT * DMODEL];
__device__ __nv_bfloat16 g_ol[(size_t)MTOT * DMODEL];
__device__ __nv_bfloat16 g_kh[(size_t)MTOT * DMODEL];
__device__ __nv_bfloat16 g_kl[(size_t)MTOT * DMODEL];
__device__ __nv_bfloat16 g_vh[(size_t)MTOT * DMODEL];
__device__ __nv_bfloat16 g_vl[(size_t)MTOT * DMODEL];
__device__ __nv_bfloat16 g_wqh[(size_t)DMODEL * DMODEL];
__device__ __nv_bfloat16 g_wql[(size_t)DMODEL * DMODEL];
__device__ __nv_bfloat16 g_wkh[(size_t)DMODEL * DMODEL];
__device__ __nv_bfloat16 g_wkl[(size_t)DMODEL * DMODEL];
__device__ __nv_bfloat16 g_wvh[(size_t)DMODEL * DMODEL];
__device__ __nv_bfloat16 g_wvl[(size_t)DMODEL * DMODEL];
__device__ __nv_bfloat16 g_woh[(size_t)DMODEL * DMODEL];
__device__ __nv_bfloat16 g_wol[(size_t)DMODEL * DMODEL];

// ================= helpers ======================================================
__device__ __forceinline__ uint32_t smem_to_u32(const void* p) {
    uint32_t a;
    asm("{ .reg .u64 t; cvta.to.shared.u64 t, %1; cvt.u32.u64 %0, t; }" : "=r"(a) : "l"(p));
    return a;
}
#define CP_ASYNC16(dst, src) \
    asm volatile("cp.async.cg.shared.global [%0], [%1], 16;" :: "r"(dst), "l"(src) : "memory")
#define CP_COMMIT() asm volatile("cp.async.commit_group;" ::: "memory")
#define CP_WAIT(n)  asm volatile("cp.async.wait_group %0;" :: "n"(n) : "memory")

__device__ __forceinline__ void ldsm_x4(uint32_t& r0, uint32_t& r1, uint32_t& r2, uint32_t& r3,
                                        uint32_t addr) {
    asm volatile("ldmatrix.sync.aligned.m8n8.x4.shared.b16 {%0,%1,%2,%3}, [%4];"
                 : "=r"(r0), "=r"(r1), "=r"(r2), "=r"(r3) : "r"(addr));
}
__device__ __forceinline__ void ldsm_x4_t(uint32_t& r0, uint32_t& r1, uint32_t& r2, uint32_t& r3,
                                          uint32_t addr) {
    asm volatile("ldmatrix.sync.aligned.m8n8.x4.trans.shared.b16 {%0,%1,%2,%3}, [%4];"
                 : "=r"(r0), "=r"(r1), "=r"(r2), "=r"(r3) : "r"(addr));
}
__device__ __forceinline__ void mma_bf16(float* c, const uint32_t* a, const uint32_t* b) {
    asm volatile(
        "mma.sync.aligned.m16n8k16.row.col.f32.bf16.bf16.f32 "
        "{%0,%1,%2,%3}, {%4,%5,%6,%7}, {%8,%9}, {%0,%1,%2,%3};"
        : "+f"(c[0]), "+f"(c[1]), "+f"(c[2]), "+f"(c[3])
        : "r"(a[0]), "r"(a[1]), "r"(a[2]), "r"(a[3]), "r"(b[0]), "r"(b[1]));
}
__device__ __forceinline__ uint32_t pack_bf16x2(float lo, float hi) {
    uint32_t r;
    asm("cvt.rn.bf16x2.f32 %0, %1, %2;" : "=r"(r) : "f"(hi), "f"(lo));
    return r;
}
__device__ __forceinline__ void split_pair(float v0, float v1, uint32_t& h, uint32_t& l) {
    h = pack_bf16x2(v0, v1);
    __nv_bfloat162 hb = *(__nv_bfloat162*)&h;
    l = pack_bf16x2(v0 - __bfloat162float(hb.x), v1 - __bfloat162float(hb.y));
}

// ================= fp32 -> bf16 hi/lo split (x) =================================
__global__ void __launch_bounds__(256) split_bf16(const float* __restrict__ in,
                                                  __nv_bfloat16* __restrict__ hi,
                                                  __nv_bfloat16* __restrict__ lo,
                                                  int n4) {
    int i = blockIdx.x * blockDim.x + threadIdx.x;
    if (i >= n4) return;
    float4 v = ((const float4*)in)[i];
    uint32_t h0, l0, h1, l1;
    split_pair(v.x, v.y, h0, l0);
    split_pair(v.z, v.w, h1, l1);
    ((uint32_t*)hi)[2 * i]     = h0;
    ((uint32_t*)hi)[2 * i + 1] = h1;
    ((uint32_t*)lo)[2 * i]     = l0;
    ((uint32_t*)lo)[2 * i + 1] = l1;
}

// ================= fused split of 4 weight matrices =============================
__global__ void __launch_bounds__(256) split_weights(const float* __restrict__ w0,
                                                     const float* __restrict__ w1,
                                                     const float* __restrict__ w2,
                                                     const float* __restrict__ w3) {
    const int NW4 = DMODEL * DMODEL / 4;
    int gi = blockIdx.x * blockDim.x + threadIdx.x;
    int which = gi / NW4;
    int i = gi - which * NW4;
    const float* in;
    __nv_bfloat16 *hi, *lo;
    switch (which) {
        case 0:  in = w0; hi = g_wqh; lo = g_wql; break;
        case 1:  in = w1; hi = g_wkh; lo = g_wkl; break;
        case 2:  in = w2; hi = g_wvh; lo = g_wvl; break;
        default: in = w3; hi = g_woh; lo = g_wol; break;
    }
    float4 v = ((const float4*)in)[i];
    uint32_t h0, l0, h1, l1;
    split_pair(v.x, v.y, h0, l0);
    split_pair(v.z, v.w, h1, l1);
    ((uint32_t*)hi)[2 * i]     = h0;
    ((uint32_t*)hi)[2 * i + 1] = h1;
    ((uint32_t*)lo)[2 * i]     = l0;
    ((uint32_t*)lo)[2 * i + 1] = l1;
}

// ================= rope LUT =====================================================
__global__ void rope_table() {
    int idx = blockIdx.x * blockDim.x + threadIdx.x;   // s*64 + i
    if (idx >= SEQ * (DHEAD / 2)) return;
    int i = idx & 63;
    int s = idx >> 6;
    float inv_freq = powf(10000.0f, -(float)(2 * i) / (float)DHEAD);
    float ang = (float)s * inv_freq;
    float sn, cs;
    sincosf(ang, &sn, &cs);
    g_rope[idx] = make_float2(cs, sn);
}

// ================= HMMA GEMM core ==============================================
#define GBM 128
#define GBN 128
#define GBK 32
#define PITCHB 80
#define TILE_B (128 * PITCHB)
#define STAGE_B (4 * TILE_B)
#define GSMEM (2 * STAGE_B)

template <typename EPI>
__device__ __forceinline__ void gemm_body(const __nv_bfloat16* Ah, const __nv_bfloat16* Al,
                                          const __nv_bfloat16* Bh, const __nv_bfloat16* Bl,
                                          int m0, int n0, int Kd, char* smem, EPI epi) {
    const uint32_t sbase = smem_to_u32(smem);
    const int tid = threadIdx.x;
    const int wid = tid >> 5;
    const int lid = tid & 31;

    const int wm = (wid >> 2) * 64;
    const int wn = (wid & 3) * 32;

    const int lrow = (lid & 7) + ((lid >> 3) & 1) * 8;
    const int lcolb = ((lid >> 4) & 1) * 16;

    const __nv_bfloat16* srcs[4] = {
        Ah + (size_t)m0 * Kd, Al + (size_t)m0 * Kd,
        Bh + (size_t)n0 * Kd, Bl + (size_t)n0 * Kd };

    const int nchunk = Kd / GBK;

    float acc[4][4][4];
#pragma unroll
    for (int a = 0; a < 4; a++)
#pragma unroll
        for (int b = 0; b < 4; b++)
#pragma unroll
            for (int cc = 0; cc < 4; cc++) acc[a][b][cc] = 0.f;

    auto issue_loads = [&](int c) {
        const int buf = c & 1;
        const uint32_t so = sbase + buf * STAGE_B;
        const int kc = c * GBK;
#pragma unroll
        for (int j = 0; j < 8; j++) {
            int idx = j * 256 + tid;
            int tile = idx >> 9;
            int row = (idx >> 2) & 127;
            int ck = idx & 3;
            const __nv_bfloat16* src = srcs[tile] + (size_t)row * Kd + kc + ck * 8;
            uint32_t dst = so + tile * TILE_B + row * PITCHB + ck * 16;
            CP_ASYNC16(dst, src);
        }
        CP_COMMIT();
    };

    issue_loads(0);

    for (int c = 0; c < nchunk; c++) {
        const int buf = c & 1;
        if (c + 1 < nchunk) {
            issue_loads(c + 1);
            CP_WAIT(1);
        } else {
            CP_WAIT(0);
        }
        __syncthreads();

        const uint32_t so = sbase + buf * STAGE_B;
        const uint32_t t_ah = so + 0 * TILE_B;
        const uint32_t t_al = so + 1 * TILE_B;
        const uint32_t t_bh = so + 2 * TILE_B;
        const uint32_t t_bl = so + 3 * TILE_B;

#pragma unroll
        for (int kk = 0; kk < 2; kk++) {
            const uint32_t kb = kk * 32 + lcolb;

            uint32_t bh[4][2], bl[4][2];
#pragma unroll
            for (int g = 0; g < 2; g++) {
                uint32_t addr = t_bh + (wn + g * 16 + lrow) * PITCHB + kb;
                uint32_t r0, r1, r2, r3;
                ldsm_x4(r0, r1, r2, r3, addr);
                bh[g * 2 + 0][0] = r0; bh[g * 2 + 0][1] = r2;
                bh[g * 2 + 1][0] = r1; bh[g * 2 + 1][1] = r3;
                addr = t_bl + (wn + g * 16 + lrow) * PITCHB + kb;
                ldsm_x4(r0, r1, r2, r3, addr);
                bl[g * 2 + 0][0] = r0; bl[g * 2 + 0][1] = r2;
                bl[g * 2 + 1][0] = r1; bl[g * 2 + 1][1] = r3;
            }

#pragma unroll
            for (int mt = 0; mt < 4; mt++) {
                uint32_t ah[4], al[4];
                uint32_t addr = t_ah + (wm + mt * 16 + lrow) * PITCHB + kb;
                ldsm_x4(ah[0], ah[1], ah[2], ah[3], addr);
                addr = t_al + (wm + mt * 16 + lrow) * PITCHB + kb;
                ldsm_x4(al[0], al[1], al[2], al[3], addr);
                // term-major ordering: same-acc MMAs are 4 issues apart (no RAW chain)
#pragma unroll
                for (int nt = 0; nt < 4; nt++) mma_bf16(acc[mt][nt], ah, bh[nt]);
#pragma unroll
                for (int nt = 0; nt < 4; nt++) mma_bf16(acc[mt][nt], ah, bl[nt]);
#pragma unroll
                for (int nt = 0; nt < 4; nt++) mma_bf16(acc[mt][nt], al, bh[nt]);
            }
        }
        __syncthreads();
    }

    const int er = lid >> 2;
    const int ec = (lid & 3) * 2;
#pragma unroll
    for (int mt = 0; mt < 4; mt++) {
#pragma unroll
        for (int nt = 0; nt < 4; nt++) {
            int m = wm + mt * 16 + er;
            int n = wn + nt * 8 + ec;
            epi(m,     n, acc[mt][nt][0], acc[mt][nt][1]);
            epi(m + 8, n, acc[mt][nt][2], acc[mt][nt][3]);
        }
    }
}

// QKV fused GEMM
__global__ void __launch_bounds__(256) gemm_qkv(const __nv_bfloat16* __restrict__ xh,
                                                const __nv_bfloat16* __restrict__ xl) {
    extern __shared__ char smem[];
    const int wsel = blockIdx.x >> 4;
    const int n0 = (blockIdx.x & 15) * GBN;
    const int m0 = blockIdx.y * GBM;

    const __nv_bfloat16* Bh = (wsel == 0) ? g_wqh : (wsel == 1) ? g_wkh : g_wvh;
    const __nv_bfloat16* Bl = (wsel == 0) ? g_wql : (wsel == 1) ? g_wkl : g_wvl;

    if (wsel < 2) {
        float* C = (wsel == 0) ? g_q : g_k;
        gemm_body(xh, xl, Bh, Bl, m0, n0, DMODEL,
                  smem, [&](int m, int n, float v0, float v1) {
            *(float2*)&C[(size_t)(m0 + m) * DMODEL + n0 + n] = make_float2(v0, v1);
        });
    } else {
        gemm_body(xh, xl, Bh, Bl, m0, n0, DMODEL,
                  smem, [&](int m, int n, float v0, float v1) {
            uint32_t h, l;
            split_pair(v0, v1, h, l);
            size_t off = (size_t)(m0 + m) * DMODEL + n0 + n;
            *(uint32_t*)&g_vh[off] = h;
            *(uint32_t*)&g_vl[off] = l;
        });
    }
}

// O projection GEMM
__global__ void __launch_bounds__(256) gemm_out(float* __restrict__ out) {
    extern __shared__ char smem[];
    const int n0 = blockIdx.x * GBN;
    const int m0 = blockIdx.y * GBM;
    gemm_body(g_oh, g_ol, g_woh, g_wol, m0, n0, DMODEL,
              smem, [&](int m, int n, float v0, float v1) {
        *(float2*)&out[(size_t)(m0 + m) * DMODEL + n0 + n] = make_float2(v0, v1);
    });
}

// ---------------- fused RoPE: Q in-place fp32, K -> bf16 hi/lo ------------------
__global__ void rope_qk(float* __restrict__ qd, const float* __restrict__ kd) {
    int idx = blockIdx.x * blockDim.x + threadIdx.x;
    const int pairs_per_head = DHEAD / 2;              // 64
    const int per_tensor = B_SZ * SEQ * NHEAD * pairs_per_head;
    const bool is_k = idx >= per_tensor;
    if (is_k) idx -= per_tensor;

    int i = idx % pairs_per_head;
    int h = (idx / pairs_per_head) % NHEAD;
    int s = (idx / (pairs_per_head * NHEAD)) % SEQ;
    int b = idx / (pairs_per_head * NHEAD * SEQ);

    float2 cssn = g_rope[s * pairs_per_head + i];
    float cs = cssn.x, sn = cssn.y;

    size_t off = ((size_t)(b * SEQ + s)) * DMODEL + h * DHEAD + 2 * i;
    if (!is_k) {
        float e = qd[off], o = qd[off + 1];
        qd[off]     = e * cs - o * sn;
        qd[off + 1] = e * sn + o * cs;
    } else {
        float e = kd[off], o = kd[off + 1];
        float r0 = e * cs - o * sn;
        float r1 = e * sn + o * cs;
        uint32_t hh, ll;
        split_pair(r0, r1, hh, ll);
        *(uint32_t*)&g_kh[off] = hh;
        *(uint32_t*)&g_kl[off] = ll;
    }
}

// ================= HMMA flash attention (causal) ================================
#define FBM 128
#define FBN 64
#define FCH (64 * 80)
#define FARR (4 * FCH)
#define FSTAGE (4 * FARR)
#define FSMEM (2 * FSTAGE)       // 163840

__global__ void __launch_bounds__(256) flash_hmma(const float* __restrict__ Qf) {
    extern __shared__ char smem[];
    const uint32_t sbase = smem_to_u32(smem);
    const int tid = threadIdx.x;
    const int wid = tid >> 5;
    const int lid = tid & 31;
    const int qb = blockIdx.x;
    const int h  = blockIdx.y;
    const int b  = blockIdx.z;
    const int q0 = qb * FBM;
    const int wm = wid * 16;

    const int lrow  = (lid & 7) + ((lid >> 3) & 1) * 8;
    const int lcolb = ((lid >> 4) & 1) * 16;
    const int r4  = lid >> 2;
    const int c2  = (lid & 3) * 2;

    const float scale = 0.08838834764831845f;   // 1/sqrt(128)

    uint32_t qh[8][4], ql[8][4];
    {
        const float* qr0 = Qf + ((size_t)(b * SEQ + q0 + wm + r4)) * DMODEL + h * DHEAD;
        const float* qr1 = qr0 + (size_t)8 * DMODEL;
#pragma unroll
        for (int ks = 0; ks < 8; ks++) {
#pragma unroll
            for (int half = 0; half < 2; half++) {
                float2 v0 = *(const float2*)(qr0 + ks * 16 + half * 8 + c2);
                float2 v1 = *(const float2*)(qr1 + ks * 16 + half * 8 + c2);
                uint32_t h0, l0, h1, l1;
                split_pair(v0.x * scale, v0.y * scale, h0, l0);
                split_pair(v1.x * scale, v1.y * scale, h1, l1);
                qh[ks][half * 2 + 0] = h0; qh[ks][half * 2 + 1] = h1;
                ql[ks][half * 2 + 0] = l0; ql[ks][half * 2 + 1] = l1;
            }
        }
    }

    float Oa[16][4];
#pragma unroll
    for (int t = 0; t < 16; t++)
#pragma unroll
        for (int c = 0; c < 4; c++) Oa[t][c] = 0.f;
    float m_i[2] = {-1e30f, -1e30f};
    float l_i[2] = {0.f, 0.f};

    const int ntile = (q0 + FBM) / FBN;

    const __nv_bfloat16* asrc[4] = {
        g_kh + ((size_t)(b * SEQ)) * DMODEL + h * DHEAD,
        g_kl + ((size_t)(b * SEQ)) * DMODEL + h * DHEAD,
        g_vh + ((size_t)(b * SEQ)) * DMODEL + h * DHEAD,
        g_vl + ((size_t)(b * SEQ)) * DMODEL + h * DHEAD };

    auto issue_loads = [&](int t) {
        const uint32_t so = sbase + (t & 1) * FSTAGE;
        const int k0 = t * FBN;
#pragma unroll
        for (int j = 0; j < 16; j++) {
            int idx = j * 256 + tid;
            int arr  = idx >> 10;
            int g    = idx & 1023;
            int row  = g >> 4;
            int gran = g & 15;
            const __nv_bfloat16* src = asrc[arr] + (size_t)(k0 + row) * DMODEL + gran * 8;
            uint32_t dst = so + arr * FARR + (gran >> 2) * FCH + row * 80 + (gran & 3) * 16;
            CP_ASYNC16(dst, src);
        }
        CP_COMMIT();
    };

    issue_loads(0);

    for (int t = 0; t < ntile; t++) {
        if (t + 1 < ntile) {
            issue_loads(t + 1);
            CP_WAIT(1);
        } else {
            CP_WAIT(0);
        }
        __syncthreads();

        const int k0 = t * FBN;
        const bool skip = (k0 > q0 + wm + 15);

        if (!skip) {
            const uint32_t so = sbase + (t & 1) * FSTAGE;
            const uint32_t kh_s = so + 0 * FARR;
            const uint32_t kl_s = so + 1 * FARR;
            const uint32_t vh_s = so + 2 * FARR;
            const uint32_t vl_s = so + 3 * FARR;

            float S[8][4];
#pragma unroll
            for (int j = 0; j < 8; j++)
#pragma unroll
                for (int c = 0; c < 4; c++) S[j][c] = 0.f;

#pragma unroll
            for (int ks = 0; ks < 8; ks++) {
                const uint32_t co = (ks >> 1) * FCH + (ks & 1) * 32 + lcolb;
                uint32_t khf[8][2], klf[8][2];
#pragma unroll
                for (int g = 0; g < 4; g++) {
                    uint32_t r0, r1, r2, r3;
                    ldsm_x4(r0, r1, r2, r3, kh_s + co + (g * 16 + lrow) * 80);
                    khf[g * 2 + 0][0] = r0; khf[g * 2 + 0][1] = r2;
                    khf[g * 2 + 1][0] = r1; khf[g * 2 + 1][1] = r3;
                    ldsm_x4(r0, r1, r2, r3, kl_s + co + (g * 16 + lrow) * 80);
                    klf[g * 2 + 0][0] = r0; klf[g * 2 + 0][1] = r2;
                    klf[g * 2 + 1][0] = r1; klf[g * 2 + 1][1] = r3;
                }
                // term-major: same-acc MMAs are 8 issues apart
#pragma unroll
                for (int j = 0; j < 8; j++) mma_bf16(S[j], qh[ks], khf[j]);
#pragma unroll
                for (int j = 0; j < 8; j++) mma_bf16(S[j], qh[ks], klf[j]);
#pragma unroll
                for (int j = 0; j < 8; j++) mma_bf16(S[j], ql[ks], khf[j]);
            }

            const int qg0 = q0 + wm + r4;
            const int qg1 = qg0 + 8;
            if (k0 + FBN - 1 > q0 + wm) {
#pragma unroll
                for (int j = 0; j < 8; j++) {
                    int kc = k0 + j * 8 + c2;
                    if (kc     > qg0) S[j][0] = -1e30f;
                    if (kc + 1 > qg0) S[j][1] = -1e30f;
                    if (kc     > qg1) S[j][2] = -1e30f;
                    if (kc + 1 > qg1) S[j][3] = -1e30f;
                }
            }

            float mx0 = -1e30f, mx1 = -1e30f;
#pragma unroll
            for (int j = 0; j < 8; j++) {
                mx0 = fmaxf(mx0, fmaxf(S[j][0], S[j][1]));
                mx1 = fmaxf(mx1, fmaxf(S[j][2], S[j][3]));
            }
            mx0 = fmaxf(mx0, __shfl_xor_sync(0xffffffffu, mx0, 1));
            mx0 = fmaxf(mx0, __shfl_xor_sync(0xffffffffu, mx0, 2));
            mx1 = fmaxf(mx1, __shfl_xor_sync(0xffffffffu, mx1, 1));
            mx1 = fmaxf(mx1, __shfl_xor_sync(0xffffffffu, mx1, 2));

            float mn0 = fmaxf(m_i[0], mx0);
            float mn1 = fmaxf(m_i[1], mx1);
            float a0 = __expf(m_i[0] - mn0);
            float a1 = __expf(m_i[1] - mn1);

            float s0 = 0.f, s1 = 0.f;
#pragma unroll
            for (int j = 0; j < 8; j++) {
                float e0 = (S[j][0] > -5e29f) ? __expf(S[j][0] - mn0) : 0.f;
                float e1 = (S[j][1] > -5e29f) ? __expf(S[j][1] - mn0) : 0.f;
                float e2 = (S[j][2] > -5e29f) ? __expf(S[j][2] - mn1) : 0.f;
                float e3 = (S[j][3] > -5e29f) ? __expf(S[j][3] - mn1) : 0.f;
                S[j][0] = e0; S[j][1] = e1; S[j][2] = e2; S[j][3] = e3;
                s0 += e0 + e1; s1 += e2 + e3;
            }
            s0 += __shfl_xor_sync(0xffffffffu, s0, 1);
            s0 += __shfl_xor_sync(0xffffffffu, s0, 2);
            s1 += __shfl_xor_sync(0xffffffffu, s1, 1);
            s1 += __shfl_xor_sync(0xffffffffu, s1, 2);

            l_i[0] = l_i[0] * a0 + s0;
            l_i[1] = l_i[1] * a1 + s1;
            m_i[0] = mn0; m_i[1] = mn1;
#pragma unroll
            for (int tt = 0; tt < 16; tt++) {
                Oa[tt][0] *= a0; Oa[tt][1] *= a0;
                Oa[tt][2] *= a1; Oa[tt][3] *= a1;
            }

            uint32_t ph[4][4], pl[4][4];
#pragma unroll
            for (int ks = 0; ks < 4; ks++) {
#pragma unroll
                for (int half = 0; half < 2; half++) {
                    uint32_t h0, l0, h1, l1;
                    split_pair(S[2 * ks + half][0], S[2 * ks + half][1], h0, l0);
                    split_pair(S[2 * ks + half][2], S[2 * ks + half][3], h1, l1);
                    ph[ks][half * 2 + 0] = h0; ph[ks][half * 2 + 1] = h1;
                    pl[ks][half * 2 + 0] = l0; pl[ks][half * 2 + 1] = l1;
                }
            }

            // ---- P @ V: process d-tile pairs (4 accumulators interleaved) ----
#pragma unroll
            for (int ks = 0; ks < 4; ks++) {
#pragma unroll
                for (int tp2 = 0; tp2 < 8; tp2 += 2) {
                    uint32_t vhf[4][2], vlf[4][2];
#pragma unroll
                    for (int u = 0; u < 2; u++) {
                        int tp = tp2 + u;
                        int dbase = tp * 16;
                        int g2 = lid >> 3;
                        int rr = lid & 7;
                        int seqrow = ks * 16 + (g2 & 1) * 8 + rr;
                        int de = dbase + (g2 >> 1) * 8;
                        uint32_t addr_off = (de >> 5) * FCH + seqrow * 80 + ((de & 31) >> 3) * 16;
                        uint32_t b0, b1, b2, b3;
                        ldsm_x4_t(b0, b1, b2, b3, vh_s + addr_off);
                        vhf[2 * u][0] = b0; vhf[2 * u][1] = b1;
                        vhf[2 * u + 1][0] = b2; vhf[2 * u + 1][1] = b3;
                        ldsm_x4_t(b0, b1, b2, b3, vl_s + addr_off);
                        vlf[2 * u][0] = b0; vlf[2 * u][1] = b1;
                        vlf[2 * u + 1][0] = b2; vlf[2 * u + 1][1] = b3;
                    }
                    // term-major over 4 accumulators (4 issues apart per acc)
#pragma unroll
                    for (int dt = 0; dt < 4; dt++) mma_bf16(Oa[2 * tp2 + dt], ph[ks], vhf[dt]);
#pragma unroll
                    for (int dt = 0; dt < 4; dt++) mma_bf16(Oa[2 * tp2 + dt], pl[ks], vhf[dt]);
#pragma unroll
                    for (int dt = 0; dt < 4; dt++) mma_bf16(Oa[2 * tp2 + dt], ph[ks], vlf[dt]);
                }
            }
        }
        __syncthreads();
    }

    // ---- write out as bf16 hi/lo (feeds gemm_out directly) ----
    float inv0 = 1.0f / l_i[0];
    float inv1 = 1.0f / l_i[1];
    size_t off0 = ((size_t)(b * SEQ + q0 + wm + r4)) * DMODEL + h * DHEAD;
    size_t off1 = off0 + (size_t)8 * DMODEL;
#pragma unroll
    for (int tt = 0; tt < 16; tt++) {
        uint32_t h0, l0, h1, l1;
        split_pair(Oa[tt][0] * inv0, Oa[tt][1] * inv0, h0, l0);
        split_pair(Oa[tt][2] * inv1, Oa[tt][3] * inv1, h1, l1);
        *(uint32_t*)&g_oh[off0 + tt * 8 + c2] = h0;
        *(uint32_t*)&g_ol[off0 + tt * 8 + c2] = l0;
        *(uint32_t*)&g_oh[off1 + tt * 8 + c2] = h1;
        *(uint32_t*)&g_ol[off1 + tt * 8 + c2] = l1;
    }
}

// ---------------- launch --------------------------------------------------------
extern "C" void kernel_launch(void* const* d_in, const int* in_sizes, int n_in,
                              void* d_out, int out_size) {
    const float* x  = (const float*)d_in[0];
    const float* wq = (const float*)d_in[1];
    const float* wk = (const float*)d_in[2];
    const float* wv = (const float*)d_in[3];
    const float* wo = (const float*)d_in[4];
    float* out = (float*)d_out;

    float *q, *k;
    __nv_bfloat16 *xh, *xl;
    cudaGetSymbolAddress((void**)&q, g_q);
    cudaGetSymbolAddress((void**)&k, g_k);
    cudaGetSymbolAddress((void**)&xh, g_xh);
    cudaGetSymbolAddress((void**)&xl, g_xl);

    const int NX4 = MTOT * DMODEL / 4;     // 2097152
    const int NW4 = DMODEL * DMODEL / 4;   // 1048576

    // 1: split x
    split_bf16<<<NX4 / 256, 256>>>(x, xh, xl, NX4);
    // 2: split 4 weights (fused)
    split_weights<<<4 * NW4 / 256, 256>>>(wq, wk, wv, wo);
    // 3: rope LUT (also positions gemm_qkv as the profiled launch)
    rope_table<<<SEQ * (DHEAD / 2) / 256, 256>>>();

    // 4: fused QKV GEMM
    cudaFuncSetAttribute(gemm_qkv, cudaFuncAttributeMaxDynamicSharedMemorySize, GSMEM);
    gemm_qkv<<<dim3(3 * DMODEL / GBN, MTOT / GBM), 256, GSMEM>>>(xh, xl);

    // 5: fused rope
    int rope_total = 2 * B_SZ * SEQ * NHEAD * (DHEAD / 2);
    rope_qk<<<rope_total / 256, 256>>>(q, k);

    // 6: flash attention -> bf16 hi/lo O
    cudaFuncSetAttribute(flash_hmma, cudaFuncAttributeMaxDynamicSharedMemorySize, FSMEM);
    flash_hmma<<<dim3(SEQ / FBM, NHEAD, B_SZ), 256, FSMEM>>>(q);

    // 7: output projection
    cudaFuncSetAttribute(gemm_out, cudaFuncAttributeMaxDynamicSharedMemorySize, GSMEM);
    gemm_out<<<dim3(DMODEL / GBN, MTOT / GBM), 256, GSMEM>>>(out);
}

// round 8
// speedup vs baseline: 1.1055x; 1.1042x over previous
#include <cuda_runtime.h>
#include <cuda_bf16.h>
#include <math.h>
#include <stdint.h>

// Problem constants
#define B_SZ 2
#define SEQ 2048
#define DMODEL 2048
#define NHEAD 16
#define DHEAD 128
#define MTOT (B_SZ * SEQ)   // 4096

// ---------------- scratch (device globals; no allocation allowed) ---------------
__device__ float g_q[(size_t)MTOT * DMODEL];
__device__ float g_k[(size_t)MTOT * DMODEL];
__device__ float2 g_rope[(size_t)SEQ * (DHEAD / 2)];   // cos/sin LUT

__device__ __nv_bfloat16 g_xh[(size_t)MTOT * DMODEL];
__device__ __nv_bfloat16 g_xl[(size_t)MTOT * DMODEL];
__device__ __nv_bfloat16 g_oh[(size_t)MTOT * DMODEL];
__device__ __nv_bfloat16 g_ol[(size_t)MTOT * DMODEL];
__device__ __nv_bfloat16 g_kh[(size_t)MTOT * DMODEL];
__device__ __nv_bfloat16 g_kl[(size_t)MTOT * DMODEL];
__device__ __nv_bfloat16 g_vh[(size_t)MTOT * DMODEL];
__device__ __nv_bfloat16 g_vl[(size_t)MTOT * DMODEL];
__device__ __nv_bfloat16 g_wqh[(size_t)DMODEL * DMODEL];
__device__ __nv_bfloat16 g_wql[(size_t)DMODEL * DMODEL];
__device__ __nv_bfloat16 g_wkh[(size_t)DMODEL * DMODEL];
__device__ __nv_bfloat16 g_wkl[(size_t)DMODEL * DMODEL];
__device__ __nv_bfloat16 g_wvh[(size_t)DMODEL * DMODEL];
__device__ __nv_bfloat16 g_wvl[(size_t)DMODEL * DMODEL];
__device__ __nv_bfloat16 g_woh[(size_t)DMODEL * DMODEL];
__device__ __nv_bfloat16 g_wol[(size_t)DMODEL * DMODEL];

// ================= helpers ======================================================
__device__ __forceinline__ uint32_t smem_to_u32(const void* p) {
    uint32_t a;
    asm("{ .reg .u64 t; cvta.to.shared.u64 t, %1; cvt.u32.u64 %0, t; }" : "=r"(a) : "l"(p));
    return a;
}
#define CP_ASYNC16(dst, src) \
    asm volatile("cp.async.cg.shared.global [%0], [%1], 16;" :: "r"(dst), "l"(src) : "memory")
#define CP_COMMIT() asm volatile("cp.async.commit_group;" ::: "memory")
#define CP_WAIT(n)  asm volatile("cp.async.wait_group %0;" :: "n"(n) : "memory")

__device__ __forceinline__ void ldsm_x4(uint32_t& r0, uint32_t& r1, uint32_t& r2, uint32_t& r3,
                                        uint32_t addr) {
    asm volatile("ldmatrix.sync.aligned.m8n8.x4.shared.b16 {%0,%1,%2,%3}, [%4];"
                 : "=r"(r0), "=r"(r1), "=r"(r2), "=r"(r3) : "r"(addr));
}
__device__ __forceinline__ void ldsm_x4_t(uint32_t& r0, uint32_t& r1, uint32_t& r2, uint32_t& r3,
                                          uint32_t addr) {
    asm volatile("ldmatrix.sync.aligned.m8n8.x4.trans.shared.b16 {%0,%1,%2,%3}, [%4];"
                 : "=r"(r0), "=r"(r1), "=r"(r2), "=r"(r3) : "r"(addr));
}
__device__ __forceinline__ void mma_bf16(float* c, const uint32_t* a, const uint32_t* b) {
    asm volatile(
        "mma.sync.aligned.m16n8k16.row.col.f32.bf16.bf16.f32 "
        "{%0,%1,%2,%3}, {%4,%5,%6,%7}, {%8,%9}, {%0,%1,%2,%3};"
        : "+f"(c[0]), "+f"(c[1]), "+f"(c[2]), "+f"(c[3])
        : "r"(a[0]), "r"(a[1]), "r"(a[2]), "r"(a[3]), "r"(b[0]), "r"(b[1]));
}
__device__ __forceinline__ uint32_t pack_bf16x2(float lo, float hi) {
    uint32_t r;
    asm("cvt.rn.bf16x2.f32 %0, %1, %2;" : "=r"(r) : "f"(hi), "f"(lo));
    return r;
}
__device__ __forceinline__ void split_pair(float v0, float v1, uint32_t& h, uint32_t& l) {
    h = pack_bf16x2(v0, v1);
    __nv_bfloat162 hb = *(__nv_bfloat162*)&h;
    l = pack_bf16x2(v0 - __bfloat162float(hb.x), v1 - __bfloat162float(hb.y));
}

// ================= fp32 -> bf16 hi/lo split (x) =================================
__global__ void __launch_bounds__(256) split_bf16(const float* __restrict__ in,
                                                  __nv_bfloat16* __restrict__ hi,
                                                  __nv_bfloat16* __restrict__ lo,
                                                  int n4) {
    int i = blockIdx.x * blockDim.x + threadIdx.x;
    if (i >= n4) return;
    float4 v = ((const float4*)in)[i];
    uint32_t h0, l0, h1, l1;
    split_pair(v.x, v.y, h0, l0);
    split_pair(v.z, v.w, h1, l1);
    ((uint32_t*)hi)[2 * i]     = h0;
    ((uint32_t*)hi)[2 * i + 1] = h1;
    ((uint32_t*)lo)[2 * i]     = l0;
    ((uint32_t*)lo)[2 * i + 1] = l1;
}

// ================= fused split of 4 weight matrices =============================
__global__ void __launch_bounds__(256) split_weights(const float* __restrict__ w0,
                                                     const float* __restrict__ w1,
                                                     const float* __restrict__ w2,
                                                     const float* __restrict__ w3) {
    const int NW4 = DMODEL * DMODEL / 4;
    int gi = blockIdx.x * blockDim.x + threadIdx.x;
    int which = gi / NW4;
    int i = gi - which * NW4;
    const float* in;
    __nv_bfloat16 *hi, *lo;
    switch (which) {
        case 0:  in = w0; hi = g_wqh; lo = g_wql; break;
        case 1:  in = w1; hi = g_wkh; lo = g_wkl; break;
        case 2:  in = w2; hi = g_wvh; lo = g_wvl; break;
        default: in = w3; hi = g_woh; lo = g_wol; break;
    }
    float4 v = ((const float4*)in)[i];
    uint32_t h0, l0, h1, l1;
    split_pair(v.x, v.y, h0, l0);
    split_pair(v.z, v.w, h1, l1);
    ((uint32_t*)hi)[2 * i]     = h0;
    ((uint32_t*)hi)[2 * i + 1] = h1;
    ((uint32_t*)lo)[2 * i]     = l0;
    ((uint32_t*)lo)[2 * i + 1] = l1;
}

// ================= rope LUT =====================================================
__global__ void rope_table() {
    int idx = blockIdx.x * blockDim.x + threadIdx.x;   // s*64 + i
    if (idx >= SEQ * (DHEAD / 2)) return;
    int i = idx & 63;
    int s = idx >> 6;
    float inv_freq = powf(10000.0f, -(float)(2 * i) / (float)DHEAD);
    float ang = (float)s * inv_freq;
    float sn, cs;
    sincosf(ang, &sn, &cs);
    g_rope[idx] = make_float2(cs, sn);
}

// ================= HMMA GEMM core ==============================================
#define GBM 128
#define GBN 128
#define GBK 32
#define PITCHB 80
#define TILE_B (128 * PITCHB)
#define STAGE_B (4 * TILE_B)
#define GSMEM (2 * STAGE_B)

template <typename EPI>
__device__ __forceinline__ void gemm_body(const __nv_bfloat16* Ah, const __nv_bfloat16* Al,
                                          const __nv_bfloat16* Bh, const __nv_bfloat16* Bl,
                                          int m0, int n0, int Kd, char* smem, EPI epi) {
    const uint32_t sbase = smem_to_u32(smem);
    const int tid = threadIdx.x;
    const int wid = tid >> 5;
    const int lid = tid & 31;

    const int wm = (wid >> 2) * 64;
    const int wn = (wid & 3) * 32;

    const int lrow = (lid & 7) + ((lid >> 3) & 1) * 8;
    const int lcolb = ((lid >> 4) & 1) * 16;

    const __nv_bfloat16* srcs[4] = {
        Ah + (size_t)m0 * Kd, Al + (size_t)m0 * Kd,
        Bh + (size_t)n0 * Kd, Bl + (size_t)n0 * Kd };

    const int nchunk = Kd / GBK;

    float acc[4][4][4];
#pragma unroll
    for (int a = 0; a < 4; a++)
#pragma unroll
        for (int b = 0; b < 4; b++)
#pragma unroll
            for (int cc = 0; cc < 4; cc++) acc[a][b][cc] = 0.f;

    auto issue_loads = [&](int c) {
        const int buf = c & 1;
        const uint32_t so = sbase + buf * STAGE_B;
        const int kc = c * GBK;
#pragma unroll
        for (int j = 0; j < 8; j++) {
            int idx = j * 256 + tid;
            int tile = idx >> 9;
            int row = (idx >> 2) & 127;
            int ck = idx & 3;
            const __nv_bfloat16* src = srcs[tile] + (size_t)row * Kd + kc + ck * 8;
            uint32_t dst = so + tile * TILE_B + row * PITCHB + ck * 16;
            CP_ASYNC16(dst, src);
        }
        CP_COMMIT();
    };

    issue_loads(0);

    for (int c = 0; c < nchunk; c++) {
        const int buf = c & 1;
        if (c + 1 < nchunk) {
            issue_loads(c + 1);
            CP_WAIT(1);
        } else {
            CP_WAIT(0);
        }
        __syncthreads();

        const uint32_t so = sbase + buf * STAGE_B;
        const uint32_t t_ah = so + 0 * TILE_B;
        const uint32_t t_al = so + 1 * TILE_B;
        const uint32_t t_bh = so + 2 * TILE_B;
        const uint32_t t_bl = so + 3 * TILE_B;

#pragma unroll
        for (int kk = 0; kk < 2; kk++) {
            const uint32_t kb = kk * 32 + lcolb;

            uint32_t bh[4][2], bl[4][2];
#pragma unroll
            for (int g = 0; g < 2; g++) {
                uint32_t addr = t_bh + (wn + g * 16 + lrow) * PITCHB + kb;
                uint32_t r0, r1, r2, r3;
                ldsm_x4(r0, r1, r2, r3, addr);
                bh[g * 2 + 0][0] = r0; bh[g * 2 + 0][1] = r2;
                bh[g * 2 + 1][0] = r1; bh[g * 2 + 1][1] = r3;
                addr = t_bl + (wn + g * 16 + lrow) * PITCHB + kb;
                ldsm_x4(r0, r1, r2, r3, addr);
                bl[g * 2 + 0][0] = r0; bl[g * 2 + 0][1] = r2;
                bl[g * 2 + 1][0] = r1; bl[g * 2 + 1][1] = r3;
            }

#pragma unroll
            for (int mt = 0; mt < 4; mt++) {
                uint32_t ah[4], al[4];
                uint32_t addr = t_ah + (wm + mt * 16 + lrow) * PITCHB + kb;
                ldsm_x4(ah[0], ah[1], ah[2], ah[3], addr);
                addr = t_al + (wm + mt * 16 + lrow) * PITCHB + kb;
                ldsm_x4(al[0], al[1], al[2], al[3], addr);
#pragma unroll
                for (int nt = 0; nt < 4; nt++) mma_bf16(acc[mt][nt], ah, bh[nt]);
#pragma unroll
                for (int nt = 0; nt < 4; nt++) mma_bf16(acc[mt][nt], ah, bl[nt]);
#pragma unroll
                for (int nt = 0; nt < 4; nt++) mma_bf16(acc[mt][nt], al, bh[nt]);
            }
        }
        __syncthreads();
    }

    const int er = lid >> 2;
    const int ec = (lid & 3) * 2;
#pragma unroll
    for (int mt = 0; mt < 4; mt++) {
#pragma unroll
        for (int nt = 0; nt < 4; nt++) {
            int m = wm + mt * 16 + er;
            int n = wn + nt * 8 + ec;
            epi(m,     n, acc[mt][nt][0], acc[mt][nt][1]);
            epi(m + 8, n, acc[mt][nt][2], acc[mt][nt][3]);
        }
    }
}

// QKV fused GEMM — 2 CTAs/SM (reg cap 128)
__global__ void __launch_bounds__(256, 2) gemm_qkv(const __nv_bfloat16* __restrict__ xh,
                                                   const __nv_bfloat16* __restrict__ xl) {
    extern __shared__ char smem[];
    const int wsel = blockIdx.x >> 4;
    const int n0 = (blockIdx.x & 15) * GBN;
    const int m0 = blockIdx.y * GBM;

    const __nv_bfloat16* Bh = (wsel == 0) ? g_wqh : (wsel == 1) ? g_wkh : g_wvh;
    const __nv_bfloat16* Bl = (wsel == 0) ? g_wql : (wsel == 1) ? g_wkl : g_wvl;

    if (wsel < 2) {
        float* C = (wsel == 0) ? g_q : g_k;
        gemm_body(xh, xl, Bh, Bl, m0, n0, DMODEL,
                  smem, [&](int m, int n, float v0, float v1) {
            *(float2*)&C[(size_t)(m0 + m) * DMODEL + n0 + n] = make_float2(v0, v1);
        });
    } else {
        gemm_body(xh, xl, Bh, Bl, m0, n0, DMODEL,
                  smem, [&](int m, int n, float v0, float v1) {
            uint32_t h, l;
            split_pair(v0, v1, h, l);
            size_t off = (size_t)(m0 + m) * DMODEL + n0 + n;
            *(uint32_t*)&g_vh[off] = h;
            *(uint32_t*)&g_vl[off] = l;
        });
    }
}

// O projection GEMM — 2 CTAs/SM (reg cap 128)
__global__ void __launch_bounds__(256, 2) gemm_out(float* __restrict__ out) {
    extern __shared__ char smem[];
    const int n0 = blockIdx.x * GBN;
    const int m0 = blockIdx.y * GBM;
    gemm_body(g_oh, g_ol, g_woh, g_wol, m0, n0, DMODEL,
              smem, [&](int m, int n, float v0, float v1) {
        *(float2*)&out[(size_t)(m0 + m) * DMODEL + n0 + n] = make_float2(v0, v1);
    });
}

// ---------------- fused RoPE: Q in-place fp32, K -> bf16 hi/lo ------------------
__global__ void rope_qk(float* __restrict__ qd, const float* __restrict__ kd) {
    int idx = blockIdx.x * blockDim.x + threadIdx.x;
    const int pairs_per_head = DHEAD / 2;              // 64
    const int per_tensor = B_SZ * SEQ * NHEAD * pairs_per_head;
    const bool is_k = idx >= per_tensor;
    if (is_k) idx -= per_tensor;

    int i = idx % pairs_per_head;
    int h = (idx / pairs_per_head) % NHEAD;
    int s = (idx / (pairs_per_head * NHEAD)) % SEQ;
    int b = idx / (pairs_per_head * NHEAD * SEQ);

    float2 cssn = g_rope[s * pairs_per_head + i];
    float cs = cssn.x, sn = cssn.y;

    size_t off = ((size_t)(b * SEQ + s)) * DMODEL + h * DHEAD + 2 * i;
    if (!is_k) {
        float e = qd[off], o = qd[off + 1];
        qd[off]     = e * cs - o * sn;
        qd[off + 1] = e * sn + o * cs;
    } else {
        float e = kd[off], o = kd[off + 1];
        float r0 = e * cs - o * sn;
        float r1 = e * sn + o * cs;
        uint32_t hh, ll;
        split_pair(r0, r1, hh, ll);
        *(uint32_t*)&g_kh[off] = hh;
        *(uint32_t*)&g_kl[off] = ll;
    }
}

// ================= HMMA flash attention (causal) ================================
#define FBM 128
#define FBN 64
#define FCH (64 * 80)
#define FARR (4 * FCH)
#define FSTAGE (4 * FARR)
#define FSMEM (2 * FSTAGE)       // 163840

__global__ void __launch_bounds__(256) flash_hmma(const float* __restrict__ Qf) {
    extern __shared__ char smem[];
    const uint32_t sbase = smem_to_u32(smem);
    const int tid = threadIdx.x;
    const int wid = tid >> 5;
    const int lid = tid & 31;
    const int qb = blockIdx.x;
    const int h  = blockIdx.y;
    const int b  = blockIdx.z;
    const int q0 = qb * FBM;
    const int wm = wid * 16;

    const int lrow  = (lid & 7) + ((lid >> 3) & 1) * 8;
    const int lcolb = ((lid >> 4) & 1) * 16;
    const int r4  = lid >> 2;
    const int c2  = (lid & 3) * 2;

    const float scale = 0.08838834764831845f;   // 1/sqrt(128)

    uint32_t qh[8][4], ql[8][4];
    {
        const float* qr0 = Qf + ((size_t)(b * SEQ + q0 + wm + r4)) * DMODEL + h * DHEAD;
        const float* qr1 = qr0 + (size_t)8 * DMODEL;
#pragma unroll
        for (int ks = 0; ks < 8; ks++) {
#pragma unroll
            for (int half = 0; half < 2; half++) {
                float2 v0 = *(const float2*)(qr0 + ks * 16 + half * 8 + c2);
                float2 v1 = *(const float2*)(qr1 + ks * 16 + half * 8 + c2);
                uint32_t h0, l0, h1, l1;
                split_pair(v0.x * scale, v0.y * scale, h0, l0);
                split_pair(v1.x * scale, v1.y * scale, h1, l1);
                qh[ks][half * 2 + 0] = h0; qh[ks][half * 2 + 1] = h1;
                ql[ks][half * 2 + 0] = l0; ql[ks][half * 2 + 1] = l1;
            }
        }
    }

    float Oa[16][4];
#pragma unroll
    for (int t = 0; t < 16; t++)
#pragma unroll
        for (int c = 0; c < 4; c++) Oa[t][c] = 0.f;
    float m_i[2] = {-1e30f, -1e30f};
    float l_i[2] = {0.f, 0.f};

    const int ntile = (q0 + FBM) / FBN;

    const __nv_bfloat16* asrc[4] = {
        g_kh + ((size_t)(b * SEQ)) * DMODEL + h * DHEAD,
        g_kl + ((size_t)(b * SEQ)) * DMODEL + h * DHEAD,
        g_vh + ((size_t)(b * SEQ)) * DMODEL + h * DHEAD,
        g_vl + ((size_t)(b * SEQ)) * DMODEL + h * DHEAD };

    auto issue_loads = [&](int t) {
        const uint32_t so = sbase + (t & 1) * FSTAGE;
        const int k0 = t * FBN;
#pragma unroll
        for (int j = 0; j < 16; j++) {
            int idx = j * 256 + tid;
            int arr  = idx >> 10;
            int g    = idx & 1023;
            int row  = g >> 4;
            int gran = g & 15;
            const __nv_bfloat16* src = asrc[arr] + (size_t)(k0 + row) * DMODEL + gran * 8;
            uint32_t dst = so + arr * FARR + (gran >> 2) * FCH + row * 80 + (gran & 3) * 16;
            CP_ASYNC16(dst, src);
        }
        CP_COMMIT();
    };

    issue_loads(0);

    for (int t = 0; t < ntile; t++) {
        if (t + 1 < ntile) {
            issue_loads(t + 1);
            CP_WAIT(1);
        } else {
            CP_WAIT(0);
        }
        __syncthreads();

        const int k0 = t * FBN;
        const bool skip = (k0 > q0 + wm + 15);

        if (!skip) {
            const uint32_t so = sbase + (t & 1) * FSTAGE;
            const uint32_t kh_s = so + 0 * FARR;
            const uint32_t kl_s = so + 1 * FARR;
            const uint32_t vh_s = so + 2 * FARR;
            const uint32_t vl_s = so + 3 * FARR;

            float S[8][4];
#pragma unroll
            for (int j = 0; j < 8; j++)
#pragma unroll
                for (int c = 0; c < 4; c++) S[j][c] = 0.f;

#pragma unroll
            for (int ks = 0; ks < 8; ks++) {
                const uint32_t co = (ks >> 1) * FCH + (ks & 1) * 32 + lcolb;
                uint32_t khf[8][2], klf[8][2];
#pragma unroll
                for (int g = 0; g < 4; g++) {
                    uint32_t r0, r1, r2, r3;
                    ldsm_x4(r0, r1, r2, r3, kh_s + co + (g * 16 + lrow) * 80);
                    khf[g * 2 + 0][0] = r0; khf[g * 2 + 0][1] = r2;
                    khf[g * 2 + 1][0] = r1; khf[g * 2 + 1][1] = r3;
                    ldsm_x4(r0, r1, r2, r3, kl_s + co + (g * 16 + lrow) * 80);
                    klf[g * 2 + 0][0] = r0; klf[g * 2 + 0][1] = r2;
                    klf[g * 2 + 1][0] = r1; klf[g * 2 + 1][1] = r3;
                }
#pragma unroll
                for (int j = 0; j < 8; j++) mma_bf16(S[j], qh[ks], khf[j]);
#pragma unroll
                for (int j = 0; j < 8; j++) mma_bf16(S[j], qh[ks], klf[j]);
#pragma unroll
                for (int j = 0; j < 8; j++) mma_bf16(S[j], ql[ks], khf[j]);
            }

            const int qg0 = q0 + wm + r4;
            const int qg1 = qg0 + 8;
            if (k0 + FBN - 1 > q0 + wm) {
#pragma unroll
                for (int j = 0; j < 8; j++) {
                    int kc = k0 + j * 8 + c2;
                    if (kc     > qg0) S[j][0] = -1e30f;
                    if (kc + 1 > qg0) S[j][1] = -1e30f;
                    if (kc     > qg1) S[j][2] = -1e30f;
                    if (kc + 1 > qg1) S[j][3] = -1e30f;
                }
            }

            float mx0 = -1e30f, mx1 = -1e30f;
#pragma unroll
            for (int j = 0; j < 8; j++) {
                mx0 = fmaxf(mx0, fmaxf(S[j][0], S[j][1]));
                mx1 = fmaxf(mx1, fmaxf(S[j][2], S[j][3]));
            }
            mx0 = fmaxf(mx0, __shfl_xor_sync(0xffffffffu, mx0, 1));
            mx0 = fmaxf(mx0, __shfl_xor_sync(0xffffffffu, mx0, 2));
            mx1 = fmaxf(mx1, __shfl_xor_sync(0xffffffffu, mx1, 1));
            mx1 = fmaxf(mx1, __shfl_xor_sync(0xffffffffu, mx1, 2));

            float mn0 = fmaxf(m_i[0], mx0);
            float mn1 = fmaxf(m_i[1], mx1);
            float a0 = __expf(m_i[0] - mn0);
            float a1 = __expf(m_i[1] - mn1);

            float s0 = 0.f, s1 = 0.f;
#pragma unroll
            for (int j = 0; j < 8; j++) {
                float e0 = (S[j][0] > -5e29f) ? __expf(S[j][0] - mn0) : 0.f;
                float e1 = (S[j][1] > -5e29f) ? __expf(S[j][1] - mn0) : 0.f;
                float e2 = (S[j][2] > -5e29f) ? __expf(S[j][2] - mn1) : 0.f;
                float e3 = (S[j][3] > -5e29f) ? __expf(S[j][3] - mn1) : 0.f;
                S[j][0] = e0; S[j][1] = e1; S[j][2] = e2; S[j][3] = e3;
                s0 += e0 + e1; s1 += e2 + e3;
            }
            s0 += __shfl_xor_sync(0xffffffffu, s0, 1);
            s0 += __shfl_xor_sync(0xffffffffu, s0, 2);
            s1 += __shfl_xor_sync(0xffffffffu, s1, 1);
            s1 += __shfl_xor_sync(0xffffffffu, s1, 2);

            l_i[0] = l_i[0] * a0 + s0;
            l_i[1] = l_i[1] * a1 + s1;
            m_i[0] = mn0; m_i[1] = mn1;
#pragma unroll
            for (int tt = 0; tt < 16; tt++) {
                Oa[tt][0] *= a0; Oa[tt][1] *= a0;
                Oa[tt][2] *= a1; Oa[tt][3] *= a1;
            }

            uint32_t ph[4][4], pl[4][4];
#pragma unroll
            for (int ks = 0; ks < 4; ks++) {
#pragma unroll
                for (int half = 0; half < 2; half++) {
                    uint32_t h0, l0, h1, l1;
                    split_pair(S[2 * ks + half][0], S[2 * ks + half][1], h0, l0);
                    split_pair(S[2 * ks + half][2], S[2 * ks + half][3], h1, l1);
                    ph[ks][half * 2 + 0] = h0; ph[ks][half * 2 + 1] = h1;
                    pl[ks][half * 2 + 0] = l0; pl[ks][half * 2 + 1] = l1;
                }
            }

#pragma unroll
            for (int ks = 0; ks < 4; ks++) {
#pragma unroll
                for (int tp2 = 0; tp2 < 8; tp2 += 2) {
                    uint32_t vhf[4][2], vlf[4][2];
#pragma unroll
                    for (int u = 0; u < 2; u++) {
                        int tp = tp2 + u;
                        int dbase = tp * 16;
                        int g2 = lid >> 3;
                        int rr = lid & 7;
                        int seqrow = ks * 16 + (g2 & 1) * 8 + rr;
                        int de = dbase + (g2 >> 1) * 8;
                        uint32_t addr_off = (de >> 5) * FCH + seqrow * 80 + ((de & 31) >> 3) * 16;
                        uint32_t b0, b1, b2, b3;
                        ldsm_x4_t(b0, b1, b2, b3, vh_s + addr_off);
                        vhf[2 * u][0] = b0; vhf[2 * u][1] = b1;
                        vhf[2 * u + 1][0] = b2; vhf[2 * u + 1][1] = b3;
                        ldsm_x4_t(b0, b1, b2, b3, vl_s + addr_off);
                        vlf[2 * u][0] = b0; vlf[2 * u][1] = b1;
                        vlf[2 * u + 1][0] = b2; vlf[2 * u + 1][1] = b3;
                    }
#pragma unroll
                    for (int dt = 0; dt < 4; dt++) mma_bf16(Oa[2 * tp2 + dt], ph[ks], vhf[dt]);
#pragma unroll
                    for (int dt = 0; dt < 4; dt++) mma_bf16(Oa[2 * tp2 + dt], pl[ks], vhf[dt]);
#pragma unroll
                    for (int dt = 0; dt < 4; dt++) mma_bf16(Oa[2 * tp2 + dt], ph[ks], vlf[dt]);
                }
            }
        }
        __syncthreads();
    }

    // ---- write out as bf16 hi/lo (feeds gemm_out directly) ----
    float inv0 = 1.0f / l_i[0];
    float inv1 = 1.0f / l_i[1];
    size_t off0 = ((size_t)(b * SEQ + q0 + wm + r4)) * DMODEL + h * DHEAD;
    size_t off1 = off0 + (size_t)8 * DMODEL;
#pragma unroll
    for (int tt = 0; tt < 16; tt++) {
        uint32_t h0, l0, h1, l1;
        split_pair(Oa[tt][0] * inv0, Oa[tt][1] * inv0, h0, l0);
        split_pair(Oa[tt][2] * inv1, Oa[tt][3] * inv1, h1, l1);
        *(uint32_t*)&g_oh[off0 + tt * 8 + c2] = h0;
        *(uint32_t*)&g_ol[off0 + tt * 8 + c2] = l0;
        *(uint32_t*)&g_oh[off1 + tt * 8 + c2] = h1;
        *(uint32_t*)&g_ol[off1 + tt * 8 + c2] = l1;
    }
}

// ---------------- launch --------------------------------------------------------
extern "C" void kernel_launch(void* const* d_in, const int* in_sizes, int n_in,
                              void* d_out, int out_size) {
    const float* x  = (const float*)d_in[0];
    const float* wq = (const float*)d_in[1];
    const float* wk = (const float*)d_in[2];
    const float* wv = (const float*)d_in[3];
    const float* wo = (const float*)d_in[4];
    float* out = (float*)d_out;

    float *q, *k;
    __nv_bfloat16 *xh, *xl;
    cudaGetSymbolAddress((void**)&q, g_q);
    cudaGetSymbolAddress((void**)&k, g_k);
    cudaGetSymbolAddress((void**)&xh, g_xh);
    cudaGetSymbolAddress((void**)&xl, g_xl);

    const int NX4 = MTOT * DMODEL / 4;     // 2097152
    const int NW4 = DMODEL * DMODEL / 4;   // 1048576

    // 1: split x
    split_bf16<<<NX4 / 256, 256>>>(x, xh, xl, NX4);
    // 2: split 4 weights (fused)
    split_weights<<<4 * NW4 / 256, 256>>>(wq, wk, wv, wo);
    // 3: rope LUT
    rope_table<<<SEQ * (DHEAD / 2) / 256, 256>>>();

    // 4: fused QKV GEMM (2 CTAs/SM)
    cudaFuncSetAttribute(gemm_qkv, cudaFuncAttributeMaxDynamicSharedMemorySize, GSMEM);
    gemm_qkv<<<dim3(3 * DMODEL / GBN, MTOT / GBM), 256, GSMEM>>>(xh, xl);

    // 5: fused rope
    int rope_total = 2 * B_SZ * SEQ * NHEAD * (DHEAD / 2);
    rope_qk<<<rope_total / 256, 256>>>(q, k);

    // 6: flash attention -> bf16 hi/lo O
    cudaFuncSetAttribute(flash_hmma, cudaFuncAttributeMaxDynamicSharedMemorySize, FSMEM);
    flash_hmma<<<dim3(SEQ / FBM, NHEAD, B_SZ), 256, FSMEM>>>(q);

    // 7: output projection (2 CTAs/SM)
    cudaFuncSetAttribute(gemm_out, cudaFuncAttributeMaxDynamicSharedMemorySize, GSMEM);
    gemm_out<<<dim3(DMODEL / GBN, MTOT / GBM), 256, GSMEM>>>(out);
}

// round 9
// speedup vs baseline: 1.2530x; 1.1334x over previous
#include <cuda_runtime.h>
#include <cuda_bf16.h>
#include <math.h>
#include <stdint.h>

// Problem constants
#define B_SZ 2
#define SEQ 2048
#define DMODEL 2048
#define NHEAD 16
#define DHEAD 128
#define MTOT (B_SZ * SEQ)   // 4096

// ---------------- scratch (device globals; no allocation allowed) ---------------
__device__ float g_q[(size_t)MTOT * DMODEL];
__device__ float g_k[(size_t)MTOT * DMODEL];
__device__ float2 g_rope[(size_t)SEQ * (DHEAD / 2)];   // cos/sin LUT

__device__ __nv_bfloat16 g_xh[(size_t)MTOT * DMODEL];
__device__ __nv_bfloat16 g_xl[(size_t)MTOT * DMODEL];
__device__ __nv_bfloat16 g_oh[(size_t)MTOT * DMODEL];
__device__ __nv_bfloat16 g_ol[(size_t)MTOT * DMODEL];
__device__ __nv_bfloat16 g_kh[(size_t)MTOT * DMODEL];
__device__ __nv_bfloat16 g_kl[(size_t)MTOT * DMODEL];
__device__ __nv_bfloat16 g_vh[(size_t)MTOT * DMODEL];
__device__ __nv_bfloat16 g_vl[(size_t)MTOT * DMODEL];
__device__ __nv_bfloat16 g_wqh[(size_t)DMODEL * DMODEL];
__device__ __nv_bfloat16 g_wql[(size_t)DMODEL * DMODEL];
__device__ __nv_bfloat16 g_wkh[(size_t)DMODEL * DMODEL];
__device__ __nv_bfloat16 g_wkl[(size_t)DMODEL * DMODEL];
__device__ __nv_bfloat16 g_wvh[(size_t)DMODEL * DMODEL];
__device__ __nv_bfloat16 g_wvl[(size_t)DMODEL * DMODEL];
__device__ __nv_bfloat16 g_woh[(size_t)DMODEL * DMODEL];
__device__ __nv_bfloat16 g_wol[(size_t)DMODEL * DMODEL];

// ================= helpers ======================================================
__device__ __forceinline__ uint32_t smem_to_u32(const void* p) {
    uint32_t a;
    asm("{ .reg .u64 t; cvta.to.shared.u64 t, %1; cvt.u32.u64 %0, t; }" : "=r"(a) : "l"(p));
    return a;
}
#define CP_ASYNC16(dst, src) \
    asm volatile("cp.async.cg.shared.global [%0], [%1], 16;" :: "r"(dst), "l"(src) : "memory")
#define CP_COMMIT() asm volatile("cp.async.commit_group;" ::: "memory")
#define CP_WAIT(n)  asm volatile("cp.async.wait_group %0;" :: "n"(n) : "memory")

__device__ __forceinline__ void ldsm_x4(uint32_t& r0, uint32_t& r1, uint32_t& r2, uint32_t& r3,
                                        uint32_t addr) {
    asm volatile("ldmatrix.sync.aligned.m8n8.x4.shared.b16 {%0,%1,%2,%3}, [%4];"
                 : "=r"(r0), "=r"(r1), "=r"(r2), "=r"(r3) : "r"(addr));
}
__device__ __forceinline__ void ldsm_x4_t(uint32_t& r0, uint32_t& r1, uint32_t& r2, uint32_t& r3,
                                          uint32_t addr) {
    asm volatile("ldmatrix.sync.aligned.m8n8.x4.trans.shared.b16 {%0,%1,%2,%3}, [%4];"
                 : "=r"(r0), "=r"(r1), "=r"(r2), "=r"(r3) : "r"(addr));
}
__device__ __forceinline__ void mma_bf16(float* c, const uint32_t* a, const uint32_t* b) {
    asm volatile(
        "mma.sync.aligned.m16n8k16.row.col.f32.bf16.bf16.f32 "
        "{%0,%1,%2,%3}, {%4,%5,%6,%7}, {%8,%9}, {%0,%1,%2,%3};"
        : "+f"(c[0]), "+f"(c[1]), "+f"(c[2]), "+f"(c[3])
        : "r"(a[0]), "r"(a[1]), "r"(a[2]), "r"(a[3]), "r"(b[0]), "r"(b[1]));
}
__device__ __forceinline__ uint32_t pack_bf16x2(float lo, float hi) {
    uint32_t r;
    asm("cvt.rn.bf16x2.f32 %0, %1, %2;" : "=r"(r) : "f"(hi), "f"(lo));
    return r;
}
__device__ __forceinline__ void split_pair(float v0, float v1, uint32_t& h, uint32_t& l) {
    h = pack_bf16x2(v0, v1);
    __nv_bfloat162 hb = *(__nv_bfloat162*)&h;
    l = pack_bf16x2(v0 - __bfloat162float(hb.x), v1 - __bfloat162float(hb.y));
}

// compact GEMM smem layout: logical row L (64B of data), two per 128B phys row,
// swizzled so any 8 consecutive L at fixed col hit 8 distinct 16B granules.
__device__ __forceinline__ uint32_t sw_off(int L, int c) {
    return ((uint32_t)(L >> 1) << 7) +
           ((((uint32_t)(L & 1) << 6) + (uint32_t)c) ^ (((uint32_t)(L >> 1) & 3) << 4));
}

// ================= fp32 -> bf16 hi/lo split (x) =================================
__global__ void __launch_bounds__(256) split_bf16(const float* __restrict__ in,
                                                  __nv_bfloat16* __restrict__ hi,
                                                  __nv_bfloat16* __restrict__ lo,
                                                  int n4) {
    int i = blockIdx.x * blockDim.x + threadIdx.x;
    if (i >= n4) return;
    float4 v = ((const float4*)in)[i];
    uint32_t h0, l0, h1, l1;
    split_pair(v.x, v.y, h0, l0);
    split_pair(v.z, v.w, h1, l1);
    ((uint32_t*)hi)[2 * i]     = h0;
    ((uint32_t*)hi)[2 * i + 1] = h1;
    ((uint32_t*)lo)[2 * i]     = l0;
    ((uint32_t*)lo)[2 * i + 1] = l1;
}

// ================= fused split of 4 weight matrices =============================
__global__ void __launch_bounds__(256) split_weights(const float* __restrict__ w0,
                                                     const float* __restrict__ w1,
                                                     const float* __restrict__ w2,
                                                     const float* __restrict__ w3) {
    const int NW4 = DMODEL * DMODEL / 4;
    int gi = blockIdx.x * blockDim.x + threadIdx.x;
    int which = gi / NW4;
    int i = gi - which * NW4;
    const float* in;
    __nv_bfloat16 *hi, *lo;
    switch (which) {
        case 0:  in = w0; hi = g_wqh; lo = g_wql; break;
        case 1:  in = w1; hi = g_wkh; lo = g_wkl; break;
        case 2:  in = w2; hi = g_wvh; lo = g_wvl; break;
        default: in = w3; hi = g_woh; lo = g_wol; break;
    }
    float4 v = ((const float4*)in)[i];
    uint32_t h0, l0, h1, l1;
    split_pair(v.x, v.y, h0, l0);
    split_pair(v.z, v.w, h1, l1);
    ((uint32_t*)hi)[2 * i]     = h0;
    ((uint32_t*)hi)[2 * i + 1] = h1;
    ((uint32_t*)lo)[2 * i]     = l0;
    ((uint32_t*)lo)[2 * i + 1] = l1;
}

// ================= rope LUT =====================================================
__global__ void rope_table() {
    int idx = blockIdx.x * blockDim.x + threadIdx.x;   // s*64 + i
    if (idx >= SEQ * (DHEAD / 2)) return;
    int i = idx & 63;
    int s = idx >> 6;
    float inv_freq = powf(10000.0f, -(float)(2 * i) / (float)DHEAD);
    float ang = (float)s * inv_freq;
    float sn, cs;
    sincosf(ang, &sn, &cs);
    g_rope[idx] = make_float2(cs, sn);
}

// ================= HMMA GEMM core (3-stage, single-sync) ========================
#define GBM 128
#define GBN 128
#define GBK 32
#define TILE_B 8192                 // 128 logical rows x 64B, packed
#define STAGE_B (4 * TILE_B)        // Ah, Al, Bh, Bl = 32KB
#define NSTAGE 3
#define GSMEM (NSTAGE * STAGE_B)    // 98304

template <typename EPI>
__device__ __forceinline__ void gemm_body(const __nv_bfloat16* Ah, const __nv_bfloat16* Al,
                                          const __nv_bfloat16* Bh, const __nv_bfloat16* Bl,
                                          int m0, int n0, int Kd, char* smem, EPI epi) {
    const uint32_t sbase = smem_to_u32(smem);
    const int tid = threadIdx.x;
    const int wid = tid >> 5;
    const int lid = tid & 31;

    const int wm = (wid >> 2) * 64;
    const int wn = (wid & 3) * 32;

    const int lrow = (lid & 7) + ((lid >> 3) & 1) * 8;
    const int lcolb = ((lid >> 4) & 1) * 16;

    const __nv_bfloat16* srcs[4] = {
        Ah + (size_t)m0 * Kd, Al + (size_t)m0 * Kd,
        Bh + (size_t)n0 * Kd, Bl + (size_t)n0 * Kd };

    // precompute per-thread cp.async slots (8 granules/thread/stage)
    const char* sp[8];
    uint32_t doff[8];
#pragma unroll
    for (int j = 0; j < 8; j++) {
        int idx = j * 256 + tid;          // 0..2047
        int tile = idx >> 9;              // 0..3
        int L = (idx >> 2) & 127;         // logical row
        int g = idx & 3;                  // 16B granule in 64B row
        sp[j] = (const char*)(srcs[tile] + (size_t)L * Kd + g * 8);
        doff[j] = (uint32_t)(tile * TILE_B) + sw_off(L, g * 16);
    }

    const int nchunk = Kd / GBK;          // 64

    float acc[4][4][4];
#pragma unroll
    for (int a = 0; a < 4; a++)
#pragma unroll
        for (int b = 0; b < 4; b++)
#pragma unroll
            for (int cc = 0; cc < 4; cc++) acc[a][b][cc] = 0.f;

    auto issue = [&](int c, int buf) {
        const uint32_t so = sbase + buf * STAGE_B;
        const int kcb = c * (GBK * 2);    // bytes along K
#pragma unroll
        for (int j = 0; j < 8; j++) CP_ASYNC16(so + doff[j], sp[j] + kcb);
        CP_COMMIT();
    };

    issue(0, 0);
    issue(1, 1);

    int buf = 0;        // buffer of chunk c
    int nbuf = 2;       // buffer for chunk c+2
    for (int c = 0; c < nchunk; c++) {
        if (c + 1 < nchunk) { CP_WAIT(1); } else { CP_WAIT(0); }
        __syncthreads();
        if (c + 2 < nchunk) issue(c + 2, nbuf);

        const uint32_t so = sbase + buf * STAGE_B;
        const uint32_t t_ah = so + 0 * TILE_B;
        const uint32_t t_al = so + 1 * TILE_B;
        const uint32_t t_bh = so + 2 * TILE_B;
        const uint32_t t_bl = so + 3 * TILE_B;

#pragma unroll
        for (int kk = 0; kk < 2; kk++) {
            const int kb = kk * 32 + lcolb;

            uint32_t bh[4][2], bl[4][2];
#pragma unroll
            for (int g = 0; g < 2; g++) {
                int L = wn + g * 16 + lrow;
                uint32_t r0, r1, r2, r3;
                ldsm_x4(r0, r1, r2, r3, t_bh + sw_off(L, kb));
                bh[g * 2 + 0][0] = r0; bh[g * 2 + 0][1] = r2;
                bh[g * 2 + 1][0] = r1; bh[g * 2 + 1][1] = r3;
                ldsm_x4(r0, r1, r2, r3, t_bl + sw_off(L, kb));
                bl[g * 2 + 0][0] = r0; bl[g * 2 + 0][1] = r2;
                bl[g * 2 + 1][0] = r1; bl[g * 2 + 1][1] = r3;
            }

#pragma unroll
            for (int mt = 0; mt < 4; mt++) {
                int L = wm + mt * 16 + lrow;
                uint32_t ah[4], al[4];
                ldsm_x4(ah[0], ah[1], ah[2], ah[3], t_ah + sw_off(L, kb));
                ldsm_x4(al[0], al[1], al[2], al[3], t_al + sw_off(L, kb));
#pragma unroll
                for (int nt = 0; nt < 4; nt++) mma_bf16(acc[mt][nt], ah, bh[nt]);
#pragma unroll
                for (int nt = 0; nt < 4; nt++) mma_bf16(acc[mt][nt], ah, bl[nt]);
#pragma unroll
                for (int nt = 0; nt < 4; nt++) mma_bf16(acc[mt][nt], al, bh[nt]);
            }
        }

        buf = (buf == 2) ? 0 : buf + 1;
        nbuf = (nbuf == 2) ? 0 : nbuf + 1;
    }

    const int er = lid >> 2;
    const int ec = (lid & 3) * 2;
#pragma unroll
    for (int mt = 0; mt < 4; mt++) {
#pragma unroll
        for (int nt = 0; nt < 4; nt++) {
            int m = wm + mt * 16 + er;
            int n = wn + nt * 8 + ec;
            epi(m,     n, acc[mt][nt][0], acc[mt][nt][1]);
            epi(m + 8, n, acc[mt][nt][2], acc[mt][nt][3]);
        }
    }
}

// QKV fused GEMM — 2 CTAs/SM (reg cap 128)
__global__ void __launch_bounds__(256, 2) gemm_qkv(const __nv_bfloat16* __restrict__ xh,
                                                   const __nv_bfloat16* __restrict__ xl) {
    extern __shared__ char smem[];
    const int wsel = blockIdx.x >> 4;
    const int n0 = (blockIdx.x & 15) * GBN;
    const int m0 = blockIdx.y * GBM;

    const __nv_bfloat16* Bh = (wsel == 0) ? g_wqh : (wsel == 1) ? g_wkh : g_wvh;
    const __nv_bfloat16* Bl = (wsel == 0) ? g_wql : (wsel == 1) ? g_wkl : g_wvl;

    if (wsel < 2) {
        float* C = (wsel == 0) ? g_q : g_k;
        gemm_body(xh, xl, Bh, Bl, m0, n0, DMODEL,
                  smem, [&](int m, int n, float v0, float v1) {
            *(float2*)&C[(size_t)(m0 + m) * DMODEL + n0 + n] = make_float2(v0, v1);
        });
    } else {
        gemm_body(xh, xl, Bh, Bl, m0, n0, DMODEL,
                  smem, [&](int m, int n, float v0, float v1) {
            uint32_t h, l;
            split_pair(v0, v1, h, l);
            size_t off = (size_t)(m0 + m) * DMODEL + n0 + n;
            *(uint32_t*)&g_vh[off] = h;
            *(uint32_t*)&g_vl[off] = l;
        });
    }
}

// O projection GEMM — 2 CTAs/SM (reg cap 128)
__global__ void __launch_bounds__(256, 2) gemm_out(float* __restrict__ out) {
    extern __shared__ char smem[];
    const int n0 = blockIdx.x * GBN;
    const int m0 = blockIdx.y * GBM;
    gemm_body(g_oh, g_ol, g_woh, g_wol, m0, n0, DMODEL,
              smem, [&](int m, int n, float v0, float v1) {
        *(float2*)&out[(size_t)(m0 + m) * DMODEL + n0 + n] = make_float2(v0, v1);
    });
}

// ---------------- fused RoPE: Q in-place fp32, K -> bf16 hi/lo ------------------
__global__ void rope_qk(float* __restrict__ qd, const float* __restrict__ kd) {
    int idx = blockIdx.x * blockDim.x + threadIdx.x;
    const int pairs_per_head = DHEAD / 2;              // 64
    const int per_tensor = B_SZ * SEQ * NHEAD * pairs_per_head;
    const bool is_k = idx >= per_tensor;
    if (is_k) idx -= per_tensor;

    int i = idx % pairs_per_head;
    int h = (idx / pairs_per_head) % NHEAD;
    int s = (idx / (pairs_per_head * NHEAD)) % SEQ;
    int b = idx / (pairs_per_head * NHEAD * SEQ);

    float2 cssn = g_rope[s * pairs_per_head + i];
    float cs = cssn.x, sn = cssn.y;

    size_t off = ((size_t)(b * SEQ + s)) * DMODEL + h * DHEAD + 2 * i;
    if (!is_k) {
        float e = qd[off], o = qd[off + 1];
        qd[off]     = e * cs - o * sn;
        qd[off + 1] = e * sn + o * cs;
    } else {
        float e = kd[off], o = kd[off + 1];
        float r0 = e * cs - o * sn;
        float r1 = e * sn + o * cs;
        uint32_t hh, ll;
        split_pair(r0, r1, hh, ll);
        *(uint32_t*)&g_kh[off] = hh;
        *(uint32_t*)&g_kl[off] = ll;
    }
}

// ================= HMMA flash attention (causal) ================================
#define FBM 128
#define FBN 64
#define FCH (64 * 80)
#define FARR (4 * FCH)
#define FSTAGE (4 * FARR)
#define FSMEM (2 * FSTAGE)       // 163840

__global__ void __launch_bounds__(256) flash_hmma(const float* __restrict__ Qf) {
    extern __shared__ char smem[];
    const uint32_t sbase = smem_to_u32(smem);
    const int tid = threadIdx.x;
    const int wid = tid >> 5;
    const int lid = tid & 31;
    const int qb = blockIdx.x;
    const int h  = blockIdx.y;
    const int b  = blockIdx.z;
    const int q0 = qb * FBM;
    const int wm = wid * 16;

    const int lrow  = (lid & 7) + ((lid >> 3) & 1) * 8;
    const int lcolb = ((lid >> 4) & 1) * 16;
    const int r4  = lid >> 2;
    const int c2  = (lid & 3) * 2;

    const float scale = 0.08838834764831845f;   // 1/sqrt(128)

    uint32_t qh[8][4], ql[8][4];
    {
        const float* qr0 = Qf + ((size_t)(b * SEQ + q0 + wm + r4)) * DMODEL + h * DHEAD;
        const float* qr1 = qr0 + (size_t)8 * DMODEL;
#pragma unroll
        for (int ks = 0; ks < 8; ks++) {
#pragma unroll
            for (int half = 0; half < 2; half++) {
                float2 v0 = *(const float2*)(qr0 + ks * 16 + half * 8 + c2);
                float2 v1 = *(const float2*)(qr1 + ks * 16 + half * 8 + c2);
                uint32_t h0, l0, h1, l1;
                split_pair(v0.x * scale, v0.y * scale, h0, l0);
                split_pair(v1.x * scale, v1.y * scale, h1, l1);
                qh[ks][half * 2 + 0] = h0; qh[ks][half * 2 + 1] = h1;
                ql[ks][half * 2 + 0] = l0; ql[ks][half * 2 + 1] = l1;
            }
        }
    }

    float Oa[16][4];
#pragma unroll
    for (int t = 0; t < 16; t++)
#pragma unroll
        for (int c = 0; c < 4; c++) Oa[t][c] = 0.f;
    float m_i[2] = {-1e30f, -1e30f};
    float l_i[2] = {0.f, 0.f};

    const int ntile = (q0 + FBM) / FBN;

    const __nv_bfloat16* asrc[4] = {
        g_kh + ((size_t)(b * SEQ)) * DMODEL + h * DHEAD,
        g_kl + ((size_t)(b * SEQ)) * DMODEL + h * DHEAD,
        g_vh + ((size_t)(b * SEQ)) * DMODEL + h * DHEAD,
        g_vl + ((size_t)(b * SEQ)) * DMODEL + h * DHEAD };

    auto issue_loads = [&](int t) {
        const uint32_t so = sbase + (t & 1) * FSTAGE;
        const int k0 = t * FBN;
#pragma unroll
        for (int j = 0; j < 16; j++) {
            int idx = j * 256 + tid;
            int arr  = idx >> 10;
            int g    = idx & 1023;
            int row  = g >> 4;
            int gran = g & 15;
            const __nv_bfloat16* src = asrc[arr] + (size_t)(k0 + row) * DMODEL + gran * 8;
            uint32_t dst = so + arr * FARR + (gran >> 2) * FCH + row * 80 + (gran & 3) * 16;
            CP_ASYNC16(dst, src);
        }
        CP_COMMIT();
    };

    issue_loads(0);

    for (int t = 0; t < ntile; t++) {
        if (t + 1 < ntile) {
            issue_loads(t + 1);
            CP_WAIT(1);
        } else {
            CP_WAIT(0);
        }
        __syncthreads();

        const int k0 = t * FBN;
        const bool skip = (k0 > q0 + wm + 15);

        if (!skip) {
            const uint32_t so = sbase + (t & 1) * FSTAGE;
            const uint32_t kh_s = so + 0 * FARR;
            const uint32_t kl_s = so + 1 * FARR;
            const uint32_t vh_s = so + 2 * FARR;
            const uint32_t vl_s = so + 3 * FARR;

            float S[8][4];
#pragma unroll
            for (int j = 0; j < 8; j++)
#pragma unroll
                for (int c = 0; c < 4; c++) S[j][c] = 0.f;

#pragma unroll
            for (int ks = 0; ks < 8; ks++) {
                const uint32_t co = (ks >> 1) * FCH + (ks & 1) * 32 + lcolb;
                uint32_t khf[8][2], klf[8][2];
#pragma unroll
                for (int g = 0; g < 4; g++) {
                    uint32_t r0, r1, r2, r3;
                    ldsm_x4(r0, r1, r2, r3, kh_s + co + (g * 16 + lrow) * 80);
                    khf[g * 2 + 0][0] = r0; khf[g * 2 + 0][1] = r2;
                    khf[g * 2 + 1][0] = r1; khf[g * 2 + 1][1] = r3;
                    ldsm_x4(r0, r1, r2, r3, kl_s + co + (g * 16 + lrow) * 80);
                    klf[g * 2 + 0][0] = r0; klf[g * 2 + 0][1] = r2;
                    klf[g * 2 + 1][0] = r1; klf[g * 2 + 1][1] = r3;
                }
#pragma unroll
                for (int j = 0; j < 8; j++) mma_bf16(S[j], qh[ks], khf[j]);
#pragma unroll
                for (int j = 0; j < 8; j++) mma_bf16(S[j], qh[ks], klf[j]);
#pragma unroll
                for (int j = 0; j < 8; j++) mma_bf16(S[j], ql[ks], khf[j]);
            }

            const int qg0 = q0 + wm + r4;
            const int qg1 = qg0 + 8;
            if (k0 + FBN - 1 > q0 + wm) {
#pragma unroll
                for (int j = 0; j < 8; j++) {
                    int kc = k0 + j * 8 + c2;
                    if (kc     > qg0) S[j][0] = -1e30f;
                    if (kc + 1 > qg0) S[j][1] = -1e30f;
                    if (kc     > qg1) S[j][2] = -1e30f;
                    if (kc + 1 > qg1) S[j][3] = -1e30f;
                }
            }

            float mx0 = -1e30f, mx1 = -1e30f;
#pragma unroll
            for (int j = 0; j < 8; j++) {
                mx0 = fmaxf(mx0, fmaxf(S[j][0], S[j][1]));
                mx1 = fmaxf(mx1, fmaxf(S[j][2], S[j][3]));
            }
            mx0 = fmaxf(mx0, __shfl_xor_sync(0xffffffffu, mx0, 1));
            mx0 = fmaxf(mx0, __shfl_xor_sync(0xffffffffu, mx0, 2));
            mx1 = fmaxf(mx1, __shfl_xor_sync(0xffffffffu, mx1, 1));
            mx1 = fmaxf(mx1, __shfl_xor_sync(0xffffffffu, mx1, 2));

            float mn0 = fmaxf(m_i[0], mx0);
            float mn1 = fmaxf(m_i[1], mx1);
            float a0 = __expf(m_i[0] - mn0);
            float a1 = __expf(m_i[1] - mn1);

            float s0 = 0.f, s1 = 0.f;
#pragma unroll
            for (int j = 0; j < 8; j++) {
                float e0 = (S[j][0] > -5e29f) ? __expf(S[j][0] - mn0) : 0.f;
                float e1 = (S[j][1] > -5e29f) ? __expf(S[j][1] - mn0) : 0.f;
                float e2 = (S[j][2] > -5e29f) ? __expf(S[j][2] - mn1) : 0.f;
                float e3 = (S[j][3] > -5e29f) ? __expf(S[j][3] - mn1) : 0.f;
                S[j][0] = e0; S[j][1] = e1; S[j][2] = e2; S[j][3] = e3;
                s0 += e0 + e1; s1 += e2 + e3;
            }
            s0 += __shfl_xor_sync(0xffffffffu, s0, 1);
            s0 += __shfl_xor_sync(0xffffffffu, s0, 2);
            s1 += __shfl_xor_sync(0xffffffffu, s1, 1);
            s1 += __shfl_xor_sync(0xffffffffu, s1, 2);

            l_i[0] = l_i[0] * a0 + s0;
            l_i[1] = l_i[1] * a1 + s1;
            m_i[0] = mn0; m_i[1] = mn1;
#pragma unroll
            for (int tt = 0; tt < 16; tt++) {
                Oa[tt][0] *= a0; Oa[tt][1] *= a0;
                Oa[tt][2] *= a1; Oa[tt][3] *= a1;
            }

            uint32_t ph[4][4], pl[4][4];
#pragma unroll
            for (int ks = 0; ks < 4; ks++) {
#pragma unroll
                for (int half = 0; half < 2; half++) {
                    uint32_t h0, l0, h1, l1;
                    split_pair(S[2 * ks + half][0], S[2 * ks + half][1], h0, l0);
                    split_pair(S[2 * ks + half][2], S[2 * ks + half][3], h1, l1);
                    ph[ks][half * 2 + 0] = h0; ph[ks][half * 2 + 1] = h1;
                    pl[ks][half * 2 + 0] = l0; pl[ks][half * 2 + 1] = l1;
                }
            }

#pragma unroll
            for (int ks = 0; ks < 4; ks++) {
#pragma unroll
                for (int tp2 = 0; tp2 < 8; tp2 += 2) {
                    uint32_t vhf[4][2], vlf[4][2];
#pragma unroll
                    for (int u = 0; u < 2; u++) {
                        int tp = tp2 + u;
                        int dbase = tp * 16;
                        int g2 = lid >> 3;
                        int rr = lid & 7;
                        int seqrow = ks * 16 + (g2 & 1) * 8 + rr;
                        int de = dbase + (g2 >> 1) * 8;
                        uint32_t addr_off = (de >> 5) * FCH + seqrow * 80 + ((de & 31) >> 3) * 16;
                        uint32_t b0, b1, b2, b3;
                        ldsm_x4_t(b0, b1, b2, b3, vh_s + addr_off);
                        vhf[2 * u][0] = b0; vhf[2 * u][1] = b1;
                        vhf[2 * u + 1][0] = b2; vhf[2 * u + 1][1] = b3;
                        ldsm_x4_t(b0, b1, b2, b3, vl_s + addr_off);
                        vlf[2 * u][0] = b0; vlf[2 * u][1] = b1;
                        vlf[2 * u + 1][0] = b2; vlf[2 * u + 1][1] = b3;
                    }
#pragma unroll
                    for (int dt = 0; dt < 4; dt++) mma_bf16(Oa[2 * tp2 + dt], ph[ks], vhf[dt]);
#pragma unroll
                    for (int dt = 0; dt < 4; dt++) mma_bf16(Oa[2 * tp2 + dt], pl[ks], vhf[dt]);
#pragma unroll
                    for (int dt = 0; dt < 4; dt++) mma_bf16(Oa[2 * tp2 + dt], ph[ks], vlf[dt]);
                }
            }
        }
        __syncthreads();
    }

    // ---- write out as bf16 hi/lo (feeds gemm_out directly) ----
    float inv0 = 1.0f / l_i[0];
    float inv1 = 1.0f / l_i[1];
    size_t off0 = ((size_t)(b * SEQ + q0 + wm + r4)) * DMODEL + h * DHEAD;
    size_t off1 = off0 + (size_t)8 * DMODEL;
#pragma unroll
    for (int tt = 0; tt < 16; tt++) {
        uint32_t h0, l0, h1, l1;
        split_pair(Oa[tt][0] * inv0, Oa[tt][1] * inv0, h0, l0);
        split_pair(Oa[tt][2] * inv1, Oa[tt][3] * inv1, h1, l1);
        *(uint32_t*)&g_oh[off0 + tt * 8 + c2] = h0;
        *(uint32_t*)&g_ol[off0 + tt * 8 + c2] = l0;
        *(uint32_t*)&g_oh[off1 + tt * 8 + c2] = h1;
        *(uint32_t*)&g_ol[off1 + tt * 8 + c2] = l1;
    }
}

// ---------------- launch --------------------------------------------------------
extern "C" void kernel_launch(void* const* d_in, const int* in_sizes, int n_in,
                              void* d_out, int out_size) {
    const float* x  = (const float*)d_in[0];
    const float* wq = (const float*)d_in[1];
    const float* wk = (const float*)d_in[2];
    const float* wv = (const float*)d_in[3];
    const float* wo = (const float*)d_in[4];
    float* out = (float*)d_out;

    float *q, *k;
    __nv_bfloat16 *xh, *xl;
    cudaGetSymbolAddress((void**)&q, g_q);
    cudaGetSymbolAddress((void**)&k, g_k);
    cudaGetSymbolAddress((void**)&xh, g_xh);
    cudaGetSymbolAddress((void**)&xl, g_xl);

    const int NX4 = MTOT * DMODEL / 4;     // 2097152
    const int NW4 = DMODEL * DMODEL / 4;   // 1048576

    // 1: split x
    split_bf16<<<NX4 / 256, 256>>>(x, xh, xl, NX4);
    // 2: split 4 weights (fused)
    split_weights<<<4 * NW4 / 256, 256>>>(wq, wk, wv, wo);
    // 3: rope LUT
    rope_table<<<SEQ * (DHEAD / 2) / 256, 256>>>();

    // 4: fused QKV GEMM (2 CTAs/SM, 3-stage pipeline)
    cudaFuncSetAttribute(gemm_qkv, cudaFuncAttributeMaxDynamicSharedMemorySize, GSMEM);
    gemm_qkv<<<dim3(3 * DMODEL / GBN, MTOT / GBM), 256, GSMEM>>>(xh, xl);

    // 5: fused rope
    int rope_total = 2 * B_SZ * SEQ * NHEAD * (DHEAD / 2);
    rope_qk<<<rope_total / 256, 256>>>(q, k);

    // 6: flash attention -> bf16 hi/lo O
    cudaFuncSetAttribute(flash_hmma, cudaFuncAttributeMaxDynamicSharedMemorySize, FSMEM);
    flash_hmma<<<dim3(SEQ / FBM, NHEAD, B_SZ), 256, FSMEM>>>(q);

    // 7: output projection (2 CTAs/SM, 3-stage pipeline)
    cudaFuncSetAttribute(gemm_out, cudaFuncAttributeMaxDynamicSharedMemorySize, GSMEM);
    gemm_out<<<dim3(DMODEL / GBN, MTOT / GBM), 256, GSMEM>>>(out);
}

// round 11
// speedup vs baseline: 1.2555x; 1.0020x over previous
#include <cuda_runtime.h>
#include <cuda_bf16.h>
#include <math.h>
#include <stdint.h>

// Problem constants
#define B_SZ 2
#define SEQ 2048
#define DMODEL 2048
#define NHEAD 16
#define DHEAD 128
#define MTOT (B_SZ * SEQ)   // 4096

// ---------------- scratch (device globals; no allocation allowed) ---------------
__device__ float2 g_rope[(size_t)SEQ * (DHEAD / 2)];   // cos/sin LUT

__device__ __nv_bfloat16 g_xh[(size_t)MTOT * DMODEL];
__device__ __nv_bfloat16 g_xl[(size_t)MTOT * DMODEL];
__device__ __nv_bfloat16 g_qh[(size_t)MTOT * DMODEL];
__device__ __nv_bfloat16 g_ql[(size_t)MTOT * DMODEL];
__device__ __nv_bfloat16 g_oh[(size_t)MTOT * DMODEL];
__device__ __nv_bfloat16 g_ol[(size_t)MTOT * DMODEL];
__device__ __nv_bfloat16 g_kh[(size_t)MTOT * DMODEL];
__device__ __nv_bfloat16 g_kl[(size_t)MTOT * DMODEL];
__device__ __nv_bfloat16 g_vh[(size_t)MTOT * DMODEL];
__device__ __nv_bfloat16 g_vl[(size_t)MTOT * DMODEL];
__device__ __nv_bfloat16 g_wqh[(size_t)DMODEL * DMODEL];
__device__ __nv_bfloat16 g_wql[(size_t)DMODEL * DMODEL];
__device__ __nv_bfloat16 g_wkh[(size_t)DMODEL * DMODEL];
__device__ __nv_bfloat16 g_wkl[(size_t)DMODEL * DMODEL];
__device__ __nv_bfloat16 g_wvh[(size_t)DMODEL * DMODEL];
__device__ __nv_bfloat16 g_wvl[(size_t)DMODEL * DMODEL];
__device__ __nv_bfloat16 g_woh[(size_t)DMODEL * DMODEL];
__device__ __nv_bfloat16 g_wol[(size_t)DMODEL * DMODEL];

// ================= helpers ======================================================
__device__ __forceinline__ uint32_t smem_to_u32(const void* p) {
    uint32_t a;
    asm("{ .reg .u64 t; cvta.to.shared.u64 t, %1; cvt.u32.u64 %0, t; }" : "=r"(a) : "l"(p));
    return a;
}
#define CP_ASYNC16(dst, src) \
    asm volatile("cp.async.cg.shared.global [%0], [%1], 16;" :: "r"(dst), "l"(src) : "memory")
#define CP_COMMIT() asm volatile("cp.async.commit_group;" ::: "memory")
#define CP_WAIT(n)  asm volatile("cp.async.wait_group %0;" :: "n"(n) : "memory")

__device__ __forceinline__ void ldsm_x4(uint32_t& r0, uint32_t& r1, uint32_t& r2, uint32_t& r3,
                                        uint32_t addr) {
    asm volatile("ldmatrix.sync.aligned.m8n8.x4.shared.b16 {%0,%1,%2,%3}, [%4];"
                 : "=r"(r0), "=r"(r1), "=r"(r2), "=r"(r3) : "r"(addr));
}
__device__ __forceinline__ void ldsm_x4_t(uint32_t& r0, uint32_t& r1, uint32_t& r2, uint32_t& r3,
                                          uint32_t addr) {
    asm volatile("ldmatrix.sync.aligned.m8n8.x4.trans.shared.b16 {%0,%1,%2,%3}, [%4];"
                 : "=r"(r0), "=r"(r1), "=r"(r2), "=r"(r3) : "r"(addr));
}
__device__ __forceinline__ void mma_bf16(float* c, const uint32_t* a, const uint32_t* b) {
    asm volatile(
        "mma.sync.aligned.m16n8k16.row.col.f32.bf16.bf16.f32 "
        "{%0,%1,%2,%3}, {%4,%5,%6,%7}, {%8,%9}, {%0,%1,%2,%3};"
        : "+f"(c[0]), "+f"(c[1]), "+f"(c[2]), "+f"(c[3])
        : "r"(a[0]), "r"(a[1]), "r"(a[2]), "r"(a[3]), "r"(b[0]), "r"(b[1]));
}
__device__ __forceinline__ uint32_t pack_bf16x2(float lo, float hi) {
    uint32_t r;
    asm("cvt.rn.bf16x2.f32 %0, %1, %2;" : "=r"(r) : "f"(hi), "f"(lo));
    return r;
}
__device__ __forceinline__ void split_pair(float v0, float v1, uint32_t& h, uint32_t& l) {
    h = pack_bf16x2(v0, v1);
    __nv_bfloat162 hb = *(__nv_bfloat162*)&h;
    l = pack_bf16x2(v0 - __bfloat162float(hb.x), v1 - __bfloat162float(hb.y));
}

// compact GEMM smem layout: logical row L (64B of data), two per 128B phys row,
// swizzled so any 8 consecutive L at fixed col hit 8 distinct 16B granules.
__device__ __forceinline__ uint32_t sw_off(int L, int c) {
    return ((uint32_t)(L >> 1) << 7) +
           ((((uint32_t)(L & 1) << 6) + (uint32_t)c) ^ (((uint32_t)(L >> 1) & 3) << 4));
}

// ================= fp32 -> bf16 hi/lo split (x) =================================
__global__ void __launch_bounds__(256) split_bf16(const float* __restrict__ in,
                                                  __nv_bfloat16* __restrict__ hi,
                                                  __nv_bfloat16* __restrict__ lo,
                                                  int n4) {
    int i = blockIdx.x * blockDim.x + threadIdx.x;
    if (i >= n4) return;
    float4 v = ((const float4*)in)[i];
    uint32_t h0, l0, h1, l1;
    split_pair(v.x, v.y, h0, l0);
    split_pair(v.z, v.w, h1, l1);
    ((uint32_t*)hi)[2 * i]     = h0;
    ((uint32_t*)hi)[2 * i + 1] = h1;
    ((uint32_t*)lo)[2 * i]     = l0;
    ((uint32_t*)lo)[2 * i + 1] = l1;
}

// ================= fused split of 4 weight matrices =============================
__global__ void __launch_bounds__(256) split_weights(const float* __restrict__ w0,
                                                     const float* __restrict__ w1,
                                                     const float* __restrict__ w2,
                                                     const float* __restrict__ w3) {
    const int NW4 = DMODEL * DMODEL / 4;
    int gi = blockIdx.x * blockDim.x + threadIdx.x;
    int which = gi / NW4;
    int i = gi - which * NW4;
    const float* in;
    __nv_bfloat16 *hi, *lo;
    switch (which) {
        case 0:  in = w0; hi = g_wqh; lo = g_wql; break;
        case 1:  in = w1; hi = g_wkh; lo = g_wkl; break;
        case 2:  in = w2; hi = g_wvh; lo = g_wvl; break;
        default: in = w3; hi = g_woh; lo = g_wol; break;
    }
    float4 v = ((const float4*)in)[i];
    uint32_t h0, l0, h1, l1;
    split_pair(v.x, v.y, h0, l0);
    split_pair(v.z, v.w, h1, l1);
    ((uint32_t*)hi)[2 * i]     = h0;
    ((uint32_t*)hi)[2 * i + 1] = h1;
    ((uint32_t*)lo)[2 * i]     = l0;
    ((uint32_t*)lo)[2 * i + 1] = l1;
}

// ================= rope LUT =====================================================
__global__ void rope_table() {
    int idx = blockIdx.x * blockDim.x + threadIdx.x;   // s*64 + i
    if (idx >= SEQ * (DHEAD / 2)) return;
    int i = idx & 63;
    int s = idx >> 6;
    float inv_freq = powf(10000.0f, -(float)(2 * i) / (float)DHEAD);
    float ang = (float)s * inv_freq;
    float sn, cs;
    sincosf(ang, &sn, &cs);
    g_rope[idx] = make_float2(cs, sn);
}

// ================= HMMA GEMM core (3-stage, single-sync) ========================
#define GBM 128
#define GBN 128
#define GBK 32
#define TILE_B 8192                 // 128 logical rows x 64B, packed
#define STAGE_B (4 * TILE_B)        // Ah, Al, Bh, Bl = 32KB
#define NSTAGE 3
#define GSMEM (NSTAGE * STAGE_B)    // 98304

template <typename EPI>
__device__ __forceinline__ void gemm_body(const __nv_bfloat16* Ah, const __nv_bfloat16* Al,
                                          const __nv_bfloat16* Bh, const __nv_bfloat16* Bl,
                                          int m0, int n0, int Kd, char* smem, EPI epi) {
    const uint32_t sbase = smem_to_u32(smem);
    const int tid = threadIdx.x;
    const int wid = tid >> 5;
    const int lid = tid & 31;

    const int wm = (wid >> 2) * 64;
    const int wn = (wid & 3) * 32;

    const int lrow = (lid & 7) + ((lid >> 3) & 1) * 8;
    const int lcolb = ((lid >> 4) & 1) * 16;

    const __nv_bfloat16* srcs[4] = {
        Ah + (size_t)m0 * Kd, Al + (size_t)m0 * Kd,
        Bh + (size_t)n0 * Kd, Bl + (size_t)n0 * Kd };

    // precompute per-thread cp.async slots (8 granules/thread/stage)
    const char* sp[8];
    uint32_t doff[8];
#pragma unroll
    for (int j = 0; j < 8; j++) {
        int idx = j * 256 + tid;          // 0..2047
        int tile = idx >> 9;              // 0..3
        int L = (idx >> 2) & 127;         // logical row
        int g = idx & 3;                  // 16B granule in 64B row
        sp[j] = (const char*)(srcs[tile] + (size_t)L * Kd + g * 8);
        doff[j] = (uint32_t)(tile * TILE_B) + sw_off(L, g * 16);
    }

    const int nchunk = Kd / GBK;          // 64

    float acc[4][4][4];
#pragma unroll
    for (int a = 0; a < 4; a++)
#pragma unroll
        for (int b = 0; b < 4; b++)
#pragma unroll
            for (int cc = 0; cc < 4; cc++) acc[a][b][cc] = 0.f;

    auto issue = [&](int c, int buf) {
        const uint32_t so = sbase + buf * STAGE_B;
        const int kcb = c * (GBK * 2);    // bytes along K
#pragma unroll
        for (int j = 0; j < 8; j++) CP_ASYNC16(so + doff[j], sp[j] + kcb);
        CP_COMMIT();
    };

    issue(0, 0);
    issue(1, 1);

    int buf = 0;        // buffer of chunk c
    int nbuf = 2;       // buffer for chunk c+2
    for (int c = 0; c < nchunk; c++) {
        if (c + 1 < nchunk) { CP_WAIT(1); } else { CP_WAIT(0); }
        __syncthreads();
        if (c + 2 < nchunk) issue(c + 2, nbuf);

        const uint32_t so = sbase + buf * STAGE_B;
        const uint32_t t_ah = so + 0 * TILE_B;
        const uint32_t t_al = so + 1 * TILE_B;
        const uint32_t t_bh = so + 2 * TILE_B;
        const uint32_t t_bl = so + 3 * TILE_B;

#pragma unroll
        for (int kk = 0; kk < 2; kk++) {
            const int kb = kk * 32 + lcolb;

            uint32_t bh[4][2], bl[4][2];
#pragma unroll
            for (int g = 0; g < 2; g++) {
                int L = wn + g * 16 + lrow;
                uint32_t r0, r1, r2, r3;
                ldsm_x4(r0, r1, r2, r3, t_bh + sw_off(L, kb));
                bh[g * 2 + 0][0] = r0; bh[g * 2 + 0][1] = r2;
                bh[g * 2 + 1][0] = r1; bh[g * 2 + 1][1] = r3;
                ldsm_x4(r0, r1, r2, r3, t_bl + sw_off(L, kb));
                bl[g * 2 + 0][0] = r0; bl[g * 2 + 0][1] = r2;
                bl[g * 2 + 1][0] = r1; bl[g * 2 + 1][1] = r3;
            }

#pragma unroll
            for (int mt = 0; mt < 4; mt++) {
                int L = wm + mt * 16 + lrow;
                uint32_t ah[4], al[4];
                ldsm_x4(ah[0], ah[1], ah[2], ah[3], t_ah + sw_off(L, kb));
                ldsm_x4(al[0], al[1], al[2], al[3], t_al + sw_off(L, kb));
#pragma unroll
                for (int nt = 0; nt < 4; nt++) mma_bf16(acc[mt][nt], ah, bh[nt]);
#pragma unroll
                for (int nt = 0; nt < 4; nt++) mma_bf16(acc[mt][nt], ah, bl[nt]);
#pragma unroll
                for (int nt = 0; nt < 4; nt++) mma_bf16(acc[mt][nt], al, bh[nt]);
            }
        }

        buf = (buf == 2) ? 0 : buf + 1;
        nbuf = (nbuf == 2) ? 0 : nbuf + 1;
    }

    const int er = lid >> 2;
    const int ec = (lid & 3) * 2;
#pragma unroll
    for (int mt = 0; mt < 4; mt++) {
#pragma unroll
        for (int nt = 0; nt < 4; nt++) {
            int m = wm + mt * 16 + er;
            int n = wn + nt * 8 + ec;
            epi(m,     n, acc[mt][nt][0], acc[mt][nt][1]);
            epi(m + 8, n, acc[mt][nt][2], acc[mt][nt][3]);
        }
    }
}

// QKV fused GEMM — 2 CTAs/SM. Epilogues: Q -> rope+scale+split bf16,
// K -> rope+split bf16, V -> split bf16.
__global__ void __launch_bounds__(256, 2) gemm_qkv(const __nv_bfloat16* __restrict__ xh,
                                                   const __nv_bfloat16* __restrict__ xl) {
    extern __shared__ char smem[];
    const int wsel = blockIdx.x >> 4;
    const int n0 = (blockIdx.x & 15) * GBN;
    const int m0 = blockIdx.y * GBM;

    const __nv_bfloat16* Bh = (wsel == 0) ? g_wqh : (wsel == 1) ? g_wkh : g_wvh;
    const __nv_bfloat16* Bl = (wsel == 0) ? g_wql : (wsel == 1) ? g_wkl : g_wvl;

    const float scale = 0.08838834764831845f;  // 1/sqrt(128)

    if (wsel == 0) {
        gemm_body(xh, xl, Bh, Bl, m0, n0, DMODEL,
                  smem, [&](int m, int n, float v0, float v1) {
            int grow = m0 + m;
            int col = n0 + n;
            float2 cssn = g_rope[(grow & (SEQ - 1)) * 64 + ((col & 127) >> 1)];
            float r0 = (v0 * cssn.x - v1 * cssn.y) * scale;
            float r1 = (v0 * cssn.y + v1 * cssn.x) * scale;
            uint32_t h, l;
            split_pair(r0, r1, h, l);
            size_t off = (size_t)grow * DMODEL + col;
            *(uint32_t*)&g_qh[off] = h;
            *(uint32_t*)&g_ql[off] = l;
        });
    } else if (wsel == 1) {
        gemm_body(xh, xl, Bh, Bl, m0, n0, DMODEL,
                  smem, [&](int m, int n, float v0, float v1) {
            int grow = m0 + m;
            int col = n0 + n;
            float2 cssn = g_rope[(grow & (SEQ - 1)) * 64 + ((col & 127) >> 1)];
            float r0 = v0 * cssn.x - v1 * cssn.y;
            float r1 = v0 * cssn.y + v1 * cssn.x;
            uint32_t h, l;
            split_pair(r0, r1, h, l);
            size_t off = (size_t)grow * DMODEL + col;
            *(uint32_t*)&g_kh[off] = h;
            *(uint32_t*)&g_kl[off] = l;
        });
    } else {
        gemm_body(xh, xl, Bh, Bl, m0, n0, DMODEL,
                  smem, [&](int m, int n, float v0, float v1) {
            uint32_t h, l;
            split_pair(v0, v1, h, l);
            size_t off = (size_t)(m0 + m) * DMODEL + n0 + n;
            *(uint32_t*)&g_vh[off] = h;
            *(uint32_t*)&g_vl[off] = l;
        });
    }
}

// O projection GEMM — 2 CTAs/SM (reg cap 128)
__global__ void __launch_bounds__(256, 2) gemm_out(float* __restrict__ out) {
    extern __shared__ char smem[];
    const int n0 = blockIdx.x * GBN;
    const int m0 = blockIdx.y * GBM;
    gemm_body(g_oh, g_ol, g_woh, g_wol, m0, n0, DMODEL,
              smem, [&](int m, int n, float v0, float v1) {
        *(float2*)&out[(size_t)(m0 + m) * DMODEL + n0 + n] = make_float2(v0, v1);
    });
}

// ================= HMMA flash attention (causal) ================================
#define FBM 128
#define FBN 64
#define FCH (64 * 80)
#define FARR (4 * FCH)
#define FSTAGE (4 * FARR)
#define FSMEM (2 * FSTAGE)       // 163840

__global__ void __launch_bounds__(256) flash_hmma() {
    extern __shared__ char smem[];
    const uint32_t sbase = smem_to_u32(smem);
    const int tid = threadIdx.x;
    const int wid = tid >> 5;
    const int lid = tid & 31;
    const int qb = (gridDim.x - 1) - blockIdx.x;   // heavy tiles first
    const int h  = blockIdx.y;
    const int b  = blockIdx.z;
    const int q0 = qb * FBM;
    const int wm = wid * 16;

    const int lrow  = (lid & 7) + ((lid >> 3) & 1) * 8;
    const int lcolb = ((lid >> 4) & 1) * 16;
    const int r4  = lid >> 2;
    const int c2  = (lid & 3) * 2;

    // ---- load prepacked Q fragments (bf16 hi/lo, already roped+scaled) ----
    uint32_t qh[8][4], ql[8][4];
    {
        const __nv_bfloat16* qh0 = g_qh + ((size_t)(b * SEQ + q0 + wm + r4)) * DMODEL + h * DHEAD;
        const __nv_bfloat16* ql0 = g_ql + ((size_t)(b * SEQ + q0 + wm + r4)) * DMODEL + h * DHEAD;
#pragma unroll
        for (int ks = 0; ks < 8; ks++) {
#pragma unroll
            for (int half = 0; half < 2; half++) {
                int e = ks * 16 + half * 8 + c2;
                qh[ks][half * 2 + 0] = *(const uint32_t*)(qh0 + e);
                qh[ks][half * 2 + 1] = *(const uint32_t*)(qh0 + 8 * DMODEL + e);
                ql[ks][half * 2 + 0] = *(const uint32_t*)(ql0 + e);
                ql[ks][half * 2 + 1] = *(const uint32_t*)(ql0 + 8 * DMODEL + e);
            }
        }
    }

    float Oa[16][4];
#pragma unroll
    for (int t = 0; t < 16; t++)
#pragma unroll
        for (int c = 0; c < 4; c++) Oa[t][c] = 0.f;
    float m_i[2] = {-1e30f, -1e30f};
    float l_i[2] = {0.f, 0.f};

    const int ntile = (q0 + FBM) / FBN;

    const __nv_bfloat16* asrc[4] = {
        g_kh + ((size_t)(b * SEQ)) * DMODEL + h * DHEAD,
        g_kl + ((size_t)(b * SEQ)) * DMODEL + h * DHEAD,
        g_vh + ((size_t)(b * SEQ)) * DMODEL + h * DHEAD,
        g_vl + ((size_t)(b * SEQ)) * DMODEL + h * DHEAD };

    auto issue_loads = [&](int t) {
        const uint32_t so = sbase + (t & 1) * FSTAGE;
        const int k0 = t * FBN;
#pragma unroll
        for (int j = 0; j < 16; j++) {
            int idx = j * 256 + tid;
            int arr  = idx >> 10;
            int g    = idx & 1023;
            int row  = g >> 4;
            int gran = g & 15;
            const __nv_bfloat16* src = asrc[arr] + (size_t)(k0 + row) * DMODEL + gran * 8;
            uint32_t dst = so + arr * FARR + (gran >> 2) * FCH + row * 80 + (gran & 3) * 16;
            CP_ASYNC16(dst, src);
        }
        CP_COMMIT();
    };

    issue_loads(0);

    for (int t = 0; t < ntile; t++) {
        if (t + 1 < ntile) {
            issue_loads(t + 1);
            CP_WAIT(1);
        } else {
            CP_WAIT(0);
        }
        __syncthreads();

        const int k0 = t * FBN;
        const bool skip = (k0 > q0 + wm + 15);

        if (!skip) {
            const uint32_t so = sbase + (t & 1) * FSTAGE;
            const uint32_t kh_s = so + 0 * FARR;
            const uint32_t kl_s = so + 1 * FARR;
            const uint32_t vh_s = so + 2 * FARR;
            const uint32_t vl_s = so + 3 * FARR;

            float S[8][4];
#pragma unroll
            for (int j = 0; j < 8; j++)
#pragma unroll
                for (int c = 0; c < 4; c++) S[j][c] = 0.f;

#pragma unroll
            for (int ks = 0; ks < 8; ks++) {
                const uint32_t co = (ks >> 1) * FCH + (ks & 1) * 32 + lcolb;
                uint32_t khf[8][2], klf[8][2];
#pragma unroll
                for (int g = 0; g < 4; g++) {
                    uint32_t r0, r1, r2, r3;
                    ldsm_x4(r0, r1, r2, r3, kh_s + co + (g * 16 + lrow) * 80);
                    khf[g * 2 + 0][0] = r0; khf[g * 2 + 0][1] = r2;
                    khf[g * 2 + 1][0] = r1; khf[g * 2 + 1][1] = r3;
                    ldsm_x4(r0, r1, r2, r3, kl_s + co + (g * 16 + lrow) * 80);
                    klf[g * 2 + 0][0] = r0; klf[g * 2 + 0][1] = r2;
                    klf[g * 2 + 1][0] = r1; klf[g * 2 + 1][1] = r3;
                }
#pragma unroll
                for (int j = 0; j < 8; j++) mma_bf16(S[j], qh[ks], khf[j]);
#pragma unroll
                for (int j = 0; j < 8; j++) mma_bf16(S[j], qh[ks], klf[j]);
#pragma unroll
                for (int j = 0; j < 8; j++) mma_bf16(S[j], ql[ks], khf[j]);
            }

            const int qg0 = q0 + wm + r4;
            const int qg1 = qg0 + 8;
            if (k0 + FBN - 1 > q0 + wm) {
#pragma unroll
                for (int j = 0; j < 8; j++) {
                    int kc = k0 + j * 8 + c2;
                    if (kc     > qg0) S[j][0] = -1e30f;
                    if (kc + 1 > qg0) S[j][1] = -1e30f;
                    if (kc     > qg1) S[j][2] = -1e30f;
                    if (kc + 1 > qg1) S[j][3] = -1e30f;
                }
            }

            float mx0 = -1e30f, mx1 = -1e30f;
#pragma unroll
            for (int j = 0; j < 8; j++) {
                mx0 = fmaxf(mx0, fmaxf(S[j][0], S[j][1]));
                mx1 = fmaxf(mx1, fmaxf(S[j][2], S[j][3]));
            }
            mx0 = fmaxf(mx0, __shfl_xor_sync(0xffffffffu, mx0, 1));
            mx0 = fmaxf(mx0, __shfl_xor_sync(0xffffffffu, mx0, 2));
            mx1 = fmaxf(mx1, __shfl_xor_sync(0xffffffffu, mx1, 1));
            mx1 = fmaxf(mx1, __shfl_xor_sync(0xffffffffu, mx1, 2));

            float mn0 = fmaxf(m_i[0], mx0);
            float mn1 = fmaxf(m_i[1], mx1);
            float a0 = __expf(m_i[0] - mn0);
            float a1 = __expf(m_i[1] - mn1);

            float s0 = 0.f, s1 = 0.f;
#pragma unroll
            for (int j = 0; j < 8; j++) {
                float e0 = (S[j][0] > -5e29f) ? __expf(S[j][0] - mn0) : 0.f;
                float e1 = (S[j][1] > -5e29f) ? __expf(S[j][1] - mn0) : 0.f;
                float e2 = (S[j][2] > -5e29f) ? __expf(S[j][2] - mn1) : 0.f;
                float e3 = (S[j][3] > -5e29f) ? __expf(S[j][3] - mn1) : 0.f;
                S[j][0] = e0; S[j][1] = e1; S[j][2] = e2; S[j][3] = e3;
                s0 += e0 + e1; s1 += e2 + e3;
            }
            s0 += __shfl_xor_sync(0xffffffffu, s0, 1);
            s0 += __shfl_xor_sync(0xffffffffu, s0, 2);
            s1 += __shfl_xor_sync(0xffffffffu, s1, 1);
            s1 += __shfl_xor_sync(0xffffffffu, s1, 2);

            l_i[0] = l_i[0] * a0 + s0;
            l_i[1] = l_i[1] * a1 + s1;
            m_i[0] = mn0; m_i[1] = mn1;
#pragma unroll
            for (int tt = 0; tt < 16; tt++) {
                Oa[tt][0] *= a0; Oa[tt][1] *= a0;
                Oa[tt][2] *= a1; Oa[tt][3] *= a1;
            }

            uint32_t ph[4][4], pl[4][4];
#pragma unroll
            for (int ks = 0; ks < 4; ks++) {
#pragma unroll
                for (int half = 0; half < 2; half++) {
                    uint32_t h0, l0, h1, l1;
                    split_pair(S[2 * ks + half][0], S[2 * ks + half][1], h0, l0);
                    split_pair(S[2 * ks + half][2], S[2 * ks + half][3], h1, l1);
                    ph[ks][half * 2 + 0] = h0; ph[ks][half * 2 + 1] = h1;
                    pl[ks][half * 2 + 0] = l0; pl[ks][half * 2 + 1] = l1;
                }
            }

#pragma unroll
            for (int ks = 0; ks < 4; ks++) {
#pragma unroll
                for (int tp2 = 0; tp2 < 8; tp2 += 2) {
                    uint32_t vhf[4][2], vlf[4][2];
#pragma unroll
                    for (int u = 0; u < 2; u++) {
                        int tp = tp2 + u;
                        int dbase = tp * 16;
                        int g2 = lid >> 3;
                        int rr = lid & 7;
                        int seqrow = ks * 16 + (g2 & 1) * 8 + rr;
                        int de = dbase + (g2 >> 1) * 8;
                        uint32_t addr_off = (de >> 5) * FCH + seqrow * 80 + ((de & 31) >> 3) * 16;
                        uint32_t b0, b1, b2, b3;
                        ldsm_x4_t(b0, b1, b2, b3, vh_s + addr_off);
                        vhf[2 * u][0] = b0; vhf[2 * u][1] = b1;
                        vhf[2 * u + 1][0] = b2; vhf[2 * u + 1][1] = b3;
                        ldsm_x4_t(b0, b1, b2, b3, vl_s + addr_off);
                        vlf[2 * u][0] = b0; vlf[2 * u][1] = b1;
                        vlf[2 * u + 1][0] = b2; vlf[2 * u + 1][1] = b3;
                    }
#pragma unroll
                    for (int dt = 0; dt < 4; dt++) mma_bf16(Oa[2 * tp2 + dt], ph[ks], vhf[dt]);
#pragma unroll
                    for (int dt = 0; dt < 4; dt++) mma_bf16(Oa[2 * tp2 + dt], pl[ks], vhf[dt]);
#pragma unroll
                    for (int dt = 0; dt < 4; dt++) mma_bf16(Oa[2 * tp2 + dt], ph[ks], vlf[dt]);
                }
            }
        }
        __syncthreads();
    }

    // ---- write out as bf16 hi/lo (feeds gemm_out directly) ----
    float inv0 = 1.0f / l_i[0];
    float inv1 = 1.0f / l_i[1];
    size_t off0 = ((size_t)(b * SEQ + q0 + wm + r4)) * DMODEL + h * DHEAD;
    size_t off1 = off0 + (size_t)8 * DMODEL;
#pragma unroll
    for (int tt = 0; tt < 16; tt++) {
        uint32_t h0, l0, h1, l1;
        split_pair(Oa[tt][0] * inv0, Oa[tt][1] * inv0, h0, l0);
        split_pair(Oa[tt][2] * inv1, Oa[tt][3] * inv1, h1, l1);
        *(uint32_t*)&g_oh[off0 + tt * 8 + c2] = h0;
        *(uint32_t*)&g_ol[off0 + tt * 8 + c2] = l0;
        *(uint32_t*)&g_oh[off1 + tt * 8 + c2] = h1;
        *(uint32_t*)&g_ol[off1 + tt * 8 + c2] = l1;
    }
}

// ---------------- launch --------------------------------------------------------
extern "C" void kernel_launch(void* const* d_in, const int* in_sizes, int n_in,
                              void* d_out, int out_size) {
    const float* x  = (const float*)d_in[0];
    const float* wq = (const float*)d_in[1];
    const float* wk = (const float*)d_in[2];
    const float* wv = (const float*)d_in[3];
    const float* wo = (const float*)d_in[4];
    float* out = (float*)d_out;

    __nv_bfloat16 *xh, *xl;
    cudaGetSymbolAddress((void**)&xh, g_xh);
    cudaGetSymbolAddress((void**)&xl, g_xl);

    const int NX4 = MTOT * DMODEL / 4;     // 2097152
    const int NW4 = DMODEL * DMODEL / 4;   // 1048576

    // 1: split x
    split_bf16<<<NX4 / 256, 256>>>(x, xh, xl, NX4);
    // 2: split 4 weights (fused)
    split_weights<<<4 * NW4 / 256, 256>>>(wq, wk, wv, wo);
    // 3: rope LUT (must precede gemm_qkv epilogue rope)
    rope_table<<<SEQ * (DHEAD / 2) / 256, 256>>>();

    // 4: fused QKV GEMM with rope/scale/split epilogues
    cudaFuncSetAttribute(gemm_qkv, cudaFuncAttributeMaxDynamicSharedMemorySize, GSMEM);
    gemm_qkv<<<dim3(3 * DMODEL / GBN, MTOT / GBM), 256, GSMEM>>>(xh, xl);

    // 5: flash attention -> bf16 hi/lo O
    cudaFuncSetAttribute(flash_hmma, cudaFuncAttributeMaxDynamicSharedMemorySize, FSMEM);
    flash_hmma<<<dim3(SEQ / FBM, NHEAD, B_SZ), 256, FSMEM>>>();

    // 6: output projection
    cudaFuncSetAttribute(gemm_out, cudaFuncAttributeMaxDynamicSharedMemorySize, GSMEM);
    gemm_out<<<dim3(DMODEL / GBN, MTOT / GBM), 256, GSMEM>>>(out);
}

// round 12
// speedup vs baseline: 1.2783x; 1.0181x over previous
#include <cuda_runtime.h>
#include <cuda_bf16.h>
#include <math.h>
#include <stdint.h>

// Problem constants
#define B_SZ 2
#define SEQ 2048
#define DMODEL 2048
#define NHEAD 16
#define DHEAD 128
#define MTOT (B_SZ * SEQ)   // 4096

// ---------------- scratch (device globals; no allocation allowed) ---------------
__device__ float2 g_rope[(size_t)SEQ * (DHEAD / 2)];   // cos/sin LUT

__device__ __nv_bfloat16 g_xh[(size_t)MTOT * DMODEL];
__device__ __nv_bfloat16 g_xl[(size_t)MTOT * DMODEL];
__device__ __nv_bfloat16 g_qh[(size_t)MTOT * DMODEL];
__device__ __nv_bfloat16 g_ql[(size_t)MTOT * DMODEL];
__device__ __nv_bfloat16 g_oh[(size_t)MTOT * DMODEL];
__device__ __nv_bfloat16 g_ol[(size_t)MTOT * DMODEL];
__device__ __nv_bfloat16 g_kh[(size_t)MTOT * DMODEL];
__device__ __nv_bfloat16 g_kl[(size_t)MTOT * DMODEL];
__device__ __nv_bfloat16 g_vh[(size_t)MTOT * DMODEL];
__device__ __nv_bfloat16 g_vl[(size_t)MTOT * DMODEL];
__device__ __nv_bfloat16 g_wqh[(size_t)DMODEL * DMODEL];
__device__ __nv_bfloat16 g_wql[(size_t)DMODEL * DMODEL];
__device__ __nv_bfloat16 g_wkh[(size_t)DMODEL * DMODEL];
__device__ __nv_bfloat16 g_wkl[(size_t)DMODEL * DMODEL];
__device__ __nv_bfloat16 g_wvh[(size_t)DMODEL * DMODEL];
__device__ __nv_bfloat16 g_wvl[(size_t)DMODEL * DMODEL];
__device__ __nv_bfloat16 g_woh[(size_t)DMODEL * DMODEL];
__device__ __nv_bfloat16 g_wol[(size_t)DMODEL * DMODEL];

// ================= helpers ======================================================
__device__ __forceinline__ uint32_t smem_to_u32(const void* p) {
    uint32_t a;
    asm("{ .reg .u64 t; cvta.to.shared.u64 t, %1; cvt.u32.u64 %0, t; }" : "=r"(a) : "l"(p));
    return a;
}
#define CP_ASYNC16(dst, src) \
    asm volatile("cp.async.cg.shared.global [%0], [%1], 16;" :: "r"(dst), "l"(src) : "memory")
#define CP_COMMIT() asm volatile("cp.async.commit_group;" ::: "memory")
#define CP_WAIT(n)  asm volatile("cp.async.wait_group %0;" :: "n"(n) : "memory")

__device__ __forceinline__ void ldsm_x4(uint32_t& r0, uint32_t& r1, uint32_t& r2, uint32_t& r3,
                                        uint32_t addr) {
    asm volatile("ldmatrix.sync.aligned.m8n8.x4.shared.b16 {%0,%1,%2,%3}, [%4];"
                 : "=r"(r0), "=r"(r1), "=r"(r2), "=r"(r3) : "r"(addr));
}
__device__ __forceinline__ void ldsm_x4_t(uint32_t& r0, uint32_t& r1, uint32_t& r2, uint32_t& r3,
                                          uint32_t addr) {
    asm volatile("ldmatrix.sync.aligned.m8n8.x4.trans.shared.b16 {%0,%1,%2,%3}, [%4];"
                 : "=r"(r0), "=r"(r1), "=r"(r2), "=r"(r3) : "r"(addr));
}
__device__ __forceinline__ void mma_bf16(float* c, const uint32_t* a, const uint32_t* b) {
    asm volatile(
        "mma.sync.aligned.m16n8k16.row.col.f32.bf16.bf16.f32 "
        "{%0,%1,%2,%3}, {%4,%5,%6,%7}, {%8,%9}, {%0,%1,%2,%3};"
        : "+f"(c[0]), "+f"(c[1]), "+f"(c[2]), "+f"(c[3])
        : "r"(a[0]), "r"(a[1]), "r"(a[2]), "r"(a[3]), "r"(b[0]), "r"(b[1]));
}
__device__ __forceinline__ uint32_t pack_bf16x2(float lo, float hi) {
    uint32_t r;
    asm("cvt.rn.bf16x2.f32 %0, %1, %2;" : "=r"(r) : "f"(hi), "f"(lo));
    return r;
}
__device__ __forceinline__ void split_pair(float v0, float v1, uint32_t& h, uint32_t& l) {
    h = pack_bf16x2(v0, v1);
    __nv_bfloat162 hb = *(__nv_bfloat162*)&h;
    l = pack_bf16x2(v0 - __bfloat162float(hb.x), v1 - __bfloat162float(hb.y));
}

// compact GEMM smem layout: logical row L (64B of data), two per 128B phys row,
// swizzled so any 8 consecutive L at fixed col hit 8 distinct 16B granules.
__device__ __forceinline__ uint32_t sw_off(int L, int c) {
    return ((uint32_t)(L >> 1) << 7) +
           ((((uint32_t)(L & 1) << 6) + (uint32_t)c) ^ (((uint32_t)(L >> 1) & 3) << 4));
}

// ================= fused preprocessing: x split + 4 weight splits + rope LUT ====
// grid: [0, NX4/256)        -> x split
//       [NX4/256, +4*NW4/256) -> weight splits
//       last 512 blocks     -> rope LUT
#define NX4 (MTOT * DMODEL / 4)          // 2097152
#define NW4 (DMODEL * DMODEL / 4)        // 1048576
#define XBLK (NX4 / 256)                 // 8192
#define WBLK (4 * NW4 / 256)             // 16384
#define RBLK (SEQ * (DHEAD / 2) / 256)   // 512
#define PRE_GRID (XBLK + WBLK + RBLK)

__global__ void __launch_bounds__(256) preproc(const float* __restrict__ x,
                                               const float* __restrict__ w0,
                                               const float* __restrict__ w1,
                                               const float* __restrict__ w2,
                                               const float* __restrict__ w3) {
    int blk = blockIdx.x;
    if (blk < XBLK) {
        int i = blk * 256 + threadIdx.x;
        float4 v = ((const float4*)x)[i];
        uint32_t h0, l0, h1, l1;
        split_pair(v.x, v.y, h0, l0);
        split_pair(v.z, v.w, h1, l1);
        ((uint32_t*)g_xh)[2 * i]     = h0;
        ((uint32_t*)g_xh)[2 * i + 1] = h1;
        ((uint32_t*)g_xl)[2 * i]     = l0;
        ((uint32_t*)g_xl)[2 * i + 1] = l1;
    } else if (blk < XBLK + WBLK) {
        int gi = (blk - XBLK) * 256 + threadIdx.x;
        int which = gi / NW4;
        int i = gi - which * NW4;
        const float* in;
        __nv_bfloat16 *hi, *lo;
        switch (which) {
            case 0:  in = w0; hi = g_wqh; lo = g_wql; break;
            case 1:  in = w1; hi = g_wkh; lo = g_wkl; break;
            case 2:  in = w2; hi = g_wvh; lo = g_wvl; break;
            default: in = w3; hi = g_woh; lo = g_wol; break;
        }
        float4 v = ((const float4*)in)[i];
        uint32_t h0, l0, h1, l1;
        split_pair(v.x, v.y, h0, l0);
        split_pair(v.z, v.w, h1, l1);
        ((uint32_t*)hi)[2 * i]     = h0;
        ((uint32_t*)hi)[2 * i + 1] = h1;
        ((uint32_t*)lo)[2 * i]     = l0;
        ((uint32_t*)lo)[2 * i + 1] = l1;
    } else {
        int idx = (blk - XBLK - WBLK) * 256 + threadIdx.x;   // s*64 + i
        int i = idx & 63;
        int s = idx >> 6;
        float inv_freq = powf(10000.0f, -(float)(2 * i) / (float)DHEAD);
        float ang = (float)s * inv_freq;
        float sn, cs;
        sincosf(ang, &sn, &cs);
        g_rope[idx] = make_float2(cs, sn);
    }
}

// ================= HMMA GEMM core (3-stage, single-sync) ========================
#define GBM 128
#define GBN 128
#define GBK 32
#define TILE_B 8192                 // 128 logical rows x 64B, packed
#define STAGE_B (4 * TILE_B)        // Ah, Al, Bh, Bl = 32KB
#define NSTAGE 3
#define GSMEM (NSTAGE * STAGE_B)    // 98304

template <typename EPI>
__device__ __forceinline__ void gemm_body(const __nv_bfloat16* Ah, const __nv_bfloat16* Al,
                                          const __nv_bfloat16* Bh, const __nv_bfloat16* Bl,
                                          int m0, int n0, int Kd, char* smem, EPI epi) {
    const uint32_t sbase = smem_to_u32(smem);
    const int tid = threadIdx.x;
    const int wid = tid >> 5;
    const int lid = tid & 31;

    const int wm = (wid >> 2) * 64;
    const int wn = (wid & 3) * 32;

    const int lrow = (lid & 7) + ((lid >> 3) & 1) * 8;
    const int lcolb = ((lid >> 4) & 1) * 16;

    const __nv_bfloat16* srcs[4] = {
        Ah + (size_t)m0 * Kd, Al + (size_t)m0 * Kd,
        Bh + (size_t)n0 * Kd, Bl + (size_t)n0 * Kd };

    // precompute per-thread cp.async slots (8 granules/thread/stage)
    const char* sp[8];
    uint32_t doff[8];
#pragma unroll
    for (int j = 0; j < 8; j++) {
        int idx = j * 256 + tid;          // 0..2047
        int tile = idx >> 9;              // 0..3
        int L = (idx >> 2) & 127;         // logical row
        int g = idx & 3;                  // 16B granule in 64B row
        sp[j] = (const char*)(srcs[tile] + (size_t)L * Kd + g * 8);
        doff[j] = (uint32_t)(tile * TILE_B) + sw_off(L, g * 16);
    }

    const int nchunk = Kd / GBK;          // 64

    float acc[4][4][4];
#pragma unroll
    for (int a = 0; a < 4; a++)
#pragma unroll
        for (int b = 0; b < 4; b++)
#pragma unroll
            for (int cc = 0; cc < 4; cc++) acc[a][b][cc] = 0.f;

    auto issue = [&](int c, int buf) {
        const uint32_t so = sbase + buf * STAGE_B;
        const int kcb = c * (GBK * 2);    // bytes along K
#pragma unroll
        for (int j = 0; j < 8; j++) CP_ASYNC16(so + doff[j], sp[j] + kcb);
        CP_COMMIT();
    };

    issue(0, 0);
    issue(1, 1);

    int buf = 0;        // buffer of chunk c
    int nbuf = 2;       // buffer for chunk c+2
    for (int c = 0; c < nchunk; c++) {
        if (c + 1 < nchunk) { CP_WAIT(1); } else { CP_WAIT(0); }
        __syncthreads();
        if (c + 2 < nchunk) issue(c + 2, nbuf);

        const uint32_t so = sbase + buf * STAGE_B;
        const uint32_t t_ah = so + 0 * TILE_B;
        const uint32_t t_al = so + 1 * TILE_B;
        const uint32_t t_bh = so + 2 * TILE_B;
        const uint32_t t_bl = so + 3 * TILE_B;

#pragma unroll
        for (int kk = 0; kk < 2; kk++) {
            const int kb = kk * 32 + lcolb;

            uint32_t bh[4][2], bl[4][2];
#pragma unroll
            for (int g = 0; g < 2; g++) {
                int L = wn + g * 16 + lrow;
                uint32_t r0, r1, r2, r3;
                ldsm_x4(r0, r1, r2, r3, t_bh + sw_off(L, kb));
                bh[g * 2 + 0][0] = r0; bh[g * 2 + 0][1] = r2;
                bh[g * 2 + 1][0] = r1; bh[g * 2 + 1][1] = r3;
                ldsm_x4(r0, r1, r2, r3, t_bl + sw_off(L, kb));
                bl[g * 2 + 0][0] = r0; bl[g * 2 + 0][1] = r2;
                bl[g * 2 + 1][0] = r1; bl[g * 2 + 1][1] = r3;
            }

#pragma unroll
            for (int mt = 0; mt < 4; mt++) {
                int L = wm + mt * 16 + lrow;
                uint32_t ah[4], al[4];
                ldsm_x4(ah[0], ah[1], ah[2], ah[3], t_ah + sw_off(L, kb));
                ldsm_x4(al[0], al[1], al[2], al[3], t_al + sw_off(L, kb));
#pragma unroll
                for (int nt = 0; nt < 4; nt++) mma_bf16(acc[mt][nt], ah, bh[nt]);
#pragma unroll
                for (int nt = 0; nt < 4; nt++) mma_bf16(acc[mt][nt], ah, bl[nt]);
#pragma unroll
                for (int nt = 0; nt < 4; nt++) mma_bf16(acc[mt][nt], al, bh[nt]);
            }
        }

        buf = (buf == 2) ? 0 : buf + 1;
        nbuf = (nbuf == 2) ? 0 : nbuf + 1;
    }

    const int er = lid >> 2;
    const int ec = (lid & 3) * 2;
#pragma unroll
    for (int mt = 0; mt < 4; mt++) {
#pragma unroll
        for (int nt = 0; nt < 4; nt++) {
            int m = wm + mt * 16 + er;
            int n = wn + nt * 8 + ec;
            epi(m,     n, acc[mt][nt][0], acc[mt][nt][1]);
            epi(m + 8, n, acc[mt][nt][2], acc[mt][nt][3]);
        }
    }
}

// QKV fused GEMM — 2 CTAs/SM. Epilogues: Q -> rope+scale+split bf16,
// K -> rope+split bf16, V -> split bf16.
__global__ void __launch_bounds__(256, 2) gemm_qkv(const __nv_bfloat16* __restrict__ xh,
                                                   const __nv_bfloat16* __restrict__ xl) {
    extern __shared__ char smem[];
    const int wsel = blockIdx.x >> 4;
    const int n0 = (blockIdx.x & 15) * GBN;
    const int m0 = blockIdx.y * GBM;

    const __nv_bfloat16* Bh = (wsel == 0) ? g_wqh : (wsel == 1) ? g_wkh : g_wvh;
    const __nv_bfloat16* Bl = (wsel == 0) ? g_wql : (wsel == 1) ? g_wkl : g_wvl;

    const float scale = 0.08838834764831845f;  // 1/sqrt(128)

    if (wsel == 0) {
        gemm_body(xh, xl, Bh, Bl, m0, n0, DMODEL,
                  smem, [&](int m, int n, float v0, float v1) {
            int grow = m0 + m;
            int col = n0 + n;
            float2 cssn = g_rope[(grow & (SEQ - 1)) * 64 + ((col & 127) >> 1)];
            float r0 = (v0 * cssn.x - v1 * cssn.y) * scale;
            float r1 = (v0 * cssn.y + v1 * cssn.x) * scale;
            uint32_t h, l;
            split_pair(r0, r1, h, l);
            size_t off = (size_t)grow * DMODEL + col;
            *(uint32_t*)&g_qh[off] = h;
            *(uint32_t*)&g_ql[off] = l;
        });
    } else if (wsel == 1) {
        gemm_body(xh, xl, Bh, Bl, m0, n0, DMODEL,
                  smem, [&](int m, int n, float v0, float v1) {
            int grow = m0 + m;
            int col = n0 + n;
            float2 cssn = g_rope[(grow & (SEQ - 1)) * 64 + ((col & 127) >> 1)];
            float r0 = v0 * cssn.x - v1 * cssn.y;
            float r1 = v0 * cssn.y + v1 * cssn.x;
            uint32_t h, l;
            split_pair(r0, r1, h, l);
            size_t off = (size_t)grow * DMODEL + col;
            *(uint32_t*)&g_kh[off] = h;
            *(uint32_t*)&g_kl[off] = l;
        });
    } else {
        gemm_body(xh, xl, Bh, Bl, m0, n0, DMODEL,
                  smem, [&](int m, int n, float v0, float v1) {
            uint32_t h, l;
            split_pair(v0, v1, h, l);
            size_t off = (size_t)(m0 + m) * DMODEL + n0 + n;
            *(uint32_t*)&g_vh[off] = h;
            *(uint32_t*)&g_vl[off] = l;
        });
    }
}

// O projection GEMM — 2 CTAs/SM (reg cap 128)
__global__ void __launch_bounds__(256, 2) gemm_out(float* __restrict__ out) {
    extern __shared__ char smem[];
    const int n0 = blockIdx.x * GBN;
    const int m0 = blockIdx.y * GBM;
    gemm_body(g_oh, g_ol, g_woh, g_wol, m0, n0, DMODEL,
              smem, [&](int m, int n, float v0, float v1) {
        *(float2*)&out[(size_t)(m0 + m) * DMODEL + n0 + n] = make_float2(v0, v1);
    });
}

// ================= HMMA flash attention (causal) ================================
#define FBM 128
#define FBN 64
#define FCH (64 * 80)
#define FARR (4 * FCH)
#define FSTAGE (4 * FARR)
#define FSMEM (2 * FSTAGE)       // 163840

__global__ void __launch_bounds__(256) flash_hmma() {
    extern __shared__ char smem[];
    const uint32_t sbase = smem_to_u32(smem);
    const int tid = threadIdx.x;
    const int wid = tid >> 5;
    const int lid = tid & 31;
    const int qb = (gridDim.x - 1) - blockIdx.x;   // heavy tiles first
    const int h  = blockIdx.y;
    const int b  = blockIdx.z;
    const int q0 = qb * FBM;
    const int wm = wid * 16;

    const int lrow  = (lid & 7) + ((lid >> 3) & 1) * 8;
    const int lcolb = ((lid >> 4) & 1) * 16;
    const int r4  = lid >> 2;
    const int c2  = (lid & 3) * 2;

    // ---- load prepacked Q fragments (bf16 hi/lo, already roped+scaled) ----
    uint32_t qh[8][4], ql[8][4];
    {
        const __nv_bfloat16* qh0 = g_qh + ((size_t)(b * SEQ + q0 + wm + r4)) * DMODEL + h * DHEAD;
        const __nv_bfloat16* ql0 = g_ql + ((size_t)(b * SEQ + q0 + wm + r4)) * DMODEL + h * DHEAD;
#pragma unroll
        for (int ks = 0; ks < 8; ks++) {
#pragma unroll
            for (int half = 0; half < 2; half++) {
                int e = ks * 16 + half * 8 + c2;
                qh[ks][half * 2 + 0] = *(const uint32_t*)(qh0 + e);
                qh[ks][half * 2 + 1] = *(const uint32_t*)(qh0 + 8 * DMODEL + e);
                ql[ks][half * 2 + 0] = *(const uint32_t*)(ql0 + e);
                ql[ks][half * 2 + 1] = *(const uint32_t*)(ql0 + 8 * DMODEL + e);
            }
        }
    }

    float Oa[16][4];
#pragma unroll
    for (int t = 0; t < 16; t++)
#pragma unroll
        for (int c = 0; c < 4; c++) Oa[t][c] = 0.f;
    float m_i[2] = {-1e30f, -1e30f};
    float l_i[2] = {0.f, 0.f};

    const int ntile = (q0 + FBM) / FBN;

    const __nv_bfloat16* asrc[4] = {
        g_kh + ((size_t)(b * SEQ)) * DMODEL + h * DHEAD,
        g_kl + ((size_t)(b * SEQ)) * DMODEL + h * DHEAD,
        g_vh + ((size_t)(b * SEQ)) * DMODEL + h * DHEAD,
        g_vl + ((size_t)(b * SEQ)) * DMODEL + h * DHEAD };

    auto issue_loads = [&](int t) {
        const uint32_t so = sbase + (t & 1) * FSTAGE;
        const int k0 = t * FBN;
#pragma unroll
        for (int j = 0; j < 16; j++) {
            int idx = j * 256 + tid;
            int arr  = idx >> 10;
            int g    = idx & 1023;
            int row  = g >> 4;
            int gran = g & 15;
            const __nv_bfloat16* src = asrc[arr] + (size_t)(k0 + row) * DMODEL + gran * 8;
            uint32_t dst = so + arr * FARR + (gran >> 2) * FCH + row * 80 + (gran & 3) * 16;
            CP_ASYNC16(dst, src);
        }
        CP_COMMIT();
    };

    issue_loads(0);

    for (int t = 0; t < ntile; t++) {
        if (t + 1 < ntile) {
            issue_loads(t + 1);
            CP_WAIT(1);
        } else {
            CP_WAIT(0);
        }
        __syncthreads();

        const int k0 = t * FBN;
        const bool skip = (k0 > q0 + wm + 15);

        if (!skip) {
            const uint32_t so = sbase + (t & 1) * FSTAGE;
            const uint32_t kh_s = so + 0 * FARR;
            const uint32_t kl_s = so + 1 * FARR;
            const uint32_t vh_s = so + 2 * FARR;
            const uint32_t vl_s = so + 3 * FARR;

            float S[8][4];
#pragma unroll
            for (int j = 0; j < 8; j++)
#pragma unroll
                for (int c = 0; c < 4; c++) S[j][c] = 0.f;

#pragma unroll
            for (int ks = 0; ks < 8; ks++) {
                const uint32_t co = (ks >> 1) * FCH + (ks & 1) * 32 + lcolb;
                uint32_t khf[8][2], klf[8][2];
#pragma unroll
                for (int g = 0; g < 4; g++) {
                    uint32_t r0, r1, r2, r3;
                    ldsm_x4(r0, r1, r2, r3, kh_s + co + (g * 16 + lrow) * 80);
                    khf[g * 2 + 0][0] = r0; khf[g * 2 + 0][1] = r2;
                    khf[g * 2 + 1][0] = r1; khf[g * 2 + 1][1] = r3;
                    ldsm_x4(r0, r1, r2, r3, kl_s + co + (g * 16 + lrow) * 80);
                    klf[g * 2 + 0][0] = r0; klf[g * 2 + 0][1] = r2;
                    klf[g * 2 + 1][0] = r1; klf[g * 2 + 1][1] = r3;
                }
#pragma unroll
                for (int j = 0; j < 8; j++) mma_bf16(S[j], qh[ks], khf[j]);
#pragma unroll
                for (int j = 0; j < 8; j++) mma_bf16(S[j], qh[ks], klf[j]);
#pragma unroll
                for (int j = 0; j < 8; j++) mma_bf16(S[j], ql[ks], khf[j]);
            }

            const int qg0 = q0 + wm + r4;
            const int qg1 = qg0 + 8;
            if (k0 + FBN - 1 > q0 + wm) {
#pragma unroll
                for (int j = 0; j < 8; j++) {
                    int kc = k0 + j * 8 + c2;
                    if (kc     > qg0) S[j][0] = -1e30f;
                    if (kc + 1 > qg0) S[j][1] = -1e30f;
                    if (kc     > qg1) S[j][2] = -1e30f;
                    if (kc + 1 > qg1) S[j][3] = -1e30f;
                }
            }

            float mx0 = -1e30f, mx1 = -1e30f;
#pragma unroll
            for (int j = 0; j < 8; j++) {
                mx0 = fmaxf(mx0, fmaxf(S[j][0], S[j][1]));
                mx1 = fmaxf(mx1, fmaxf(S[j][2], S[j][3]));
            }
            mx0 = fmaxf(mx0, __shfl_xor_sync(0xffffffffu, mx0, 1));
            mx0 = fmaxf(mx0, __shfl_xor_sync(0xffffffffu, mx0, 2));
            mx1 = fmaxf(mx1, __shfl_xor_sync(0xffffffffu, mx1, 1));
            mx1 = fmaxf(mx1, __shfl_xor_sync(0xffffffffu, mx1, 2));

            float mn0 = fmaxf(m_i[0], mx0);
            float mn1 = fmaxf(m_i[1], mx1);
            float a0 = __expf(m_i[0] - mn0);
            float a1 = __expf(m_i[1] - mn1);

            // NOTE: masked entries hold -1e30; mn is always finite after tile 0
            // (diagonal guarantees >=1 unmasked entry per row), so
            // __expf(-1e30 - mn) underflows to exactly 0 — no guards needed.
            float s0 = 0.f, s1 = 0.f;
#pragma unroll
            for (int j = 0; j < 8; j++) {
                float e0 = __expf(S[j][0] - mn0);
                float e1 = __expf(S[j][1] - mn0);
                float e2 = __expf(S[j][2] - mn1);
                float e3 = __expf(S[j][3] - mn1);
                S[j][0] = e0; S[j][1] = e1; S[j][2] = e2; S[j][3] = e3;
                s0 += e0 + e1; s1 += e2 + e3;
            }
            s0 += __shfl_xor_sync(0xffffffffu, s0, 1);
            s0 += __shfl_xor_sync(0xffffffffu, s0, 2);
            s1 += __shfl_xor_sync(0xffffffffu, s1, 1);
            s1 += __shfl_xor_sync(0xffffffffu, s1, 2);

            l_i[0] = l_i[0] * a0 + s0;
            l_i[1] = l_i[1] * a1 + s1;
            m_i[0] = mn0; m_i[1] = mn1;
#pragma unroll
            for (int tt = 0; tt < 16; tt++) {
                Oa[tt][0] *= a0; Oa[tt][1] *= a0;
                Oa[tt][2] *= a1; Oa[tt][3] *= a1;
            }

            uint32_t ph[4][4], pl[4][4];
#pragma unroll
            for (int ks = 0; ks < 4; ks++) {
#pragma unroll
                for (int half = 0; half < 2; half++) {
                    uint32_t h0, l0, h1, l1;
                    split_pair(S[2 * ks + half][0], S[2 * ks + half][1], h0, l0);
                    split_pair(S[2 * ks + half][2], S[2 * ks + half][3], h1, l1);
                    ph[ks][half * 2 + 0] = h0; ph[ks][half * 2 + 1] = h1;
                    pl[ks][half * 2 + 0] = l0; pl[ks][half * 2 + 1] = l1;
                }
            }

#pragma unroll
            for (int ks = 0; ks < 4; ks++) {
#pragma unroll
                for (int tp2 = 0; tp2 < 8; tp2 += 2) {
                    uint32_t vhf[4][2], vlf[4][2];
#pragma unroll
                    for (int u = 0; u < 2; u++) {
                        int tp = tp2 + u;
                        int dbase = tp * 16;
                        int g2 = lid >> 3;
                        int rr = lid & 7;
                        int seqrow = ks * 16 + (g2 & 1) * 8 + rr;
                        int de = dbase + (g2 >> 1) * 8;
                        uint32_t addr_off = (de >> 5) * FCH + seqrow * 80 + ((de & 31) >> 3) * 16;
                        uint32_t b0, b1, b2, b3;
                        ldsm_x4_t(b0, b1, b2, b3, vh_s + addr_off);
                        vhf[2 * u][0] = b0; vhf[2 * u][1] = b1;
                        vhf[2 * u + 1][0] = b2; vhf[2 * u + 1][1] = b3;
                        ldsm_x4_t(b0, b1, b2, b3, vl_s + addr_off);
                        vlf[2 * u][0] = b0; vlf[2 * u][1] = b1;
                        vlf[2 * u + 1][0] = b2; vlf[2 * u + 1][1] = b3;
                    }
#pragma unroll
                    for (int dt = 0; dt < 4; dt++) mma_bf16(Oa[2 * tp2 + dt], ph[ks], vhf[dt]);
#pragma unroll
                    for (int dt = 0; dt < 4; dt++) mma_bf16(Oa[2 * tp2 + dt], pl[ks], vhf[dt]);
#pragma unroll
                    for (int dt = 0; dt < 4; dt++) mma_bf16(Oa[2 * tp2 + dt], ph[ks], vlf[dt]);
                }
            }
        }
        __syncthreads();
    }

    // ---- write out as bf16 hi/lo (feeds gemm_out directly) ----
    float inv0 = 1.0f / l_i[0];
    float inv1 = 1.0f / l_i[1];
    size_t off0 = ((size_t)(b * SEQ + q0 + wm + r4)) * DMODEL + h * DHEAD;
    size_t off1 = off0 + (size_t)8 * DMODEL;
#pragma unroll
    for (int tt = 0; tt < 16; tt++) {
        uint32_t h0, l0, h1, l1;
        split_pair(Oa[tt][0] * inv0, Oa[tt][1] * inv0, h0, l0);
        split_pair(Oa[tt][2] * inv1, Oa[tt][3] * inv1, h1, l1);
        *(uint32_t*)&g_oh[off0 + tt * 8 + c2] = h0;
        *(uint32_t*)&g_ol[off0 + tt * 8 + c2] = l0;
        *(uint32_t*)&g_oh[off1 + tt * 8 + c2] = h1;
        *(uint32_t*)&g_ol[off1 + tt * 8 + c2] = l1;
    }
}

// ---------------- launch --------------------------------------------------------
extern "C" void kernel_launch(void* const* d_in, const int* in_sizes, int n_in,
                              void* d_out, int out_size) {
    const float* x  = (const float*)d_in[0];
    const float* wq = (const float*)d_in[1];
    const float* wk = (const float*)d_in[2];
    const float* wv = (const float*)d_in[3];
    const float* wo = (const float*)d_in[4];
    float* out = (float*)d_out;

    __nv_bfloat16 *xh, *xl;
    cudaGetSymbolAddress((void**)&xh, g_xh);
    cudaGetSymbolAddress((void**)&xl, g_xl);

    // 1: fused preprocessing (x split + weight splits + rope LUT)
    preproc<<<PRE_GRID, 256>>>(x, wq, wk, wv, wo);

    // 2: fused QKV GEMM with rope/scale/split epilogues
    cudaFuncSetAttribute(gemm_qkv, cudaFuncAttributeMaxDynamicSharedMemorySize, GSMEM);
    gemm_qkv<<<dim3(3 * DMODEL / GBN, MTOT / GBM), 256, GSMEM>>>(xh, xl);

    // 3: flash attention -> bf16 hi/lo O
    cudaFuncSetAttribute(flash_hmma, cudaFuncAttributeMaxDynamicSharedMemorySize, FSMEM);
    flash_hmma<<<dim3(SEQ / FBM, NHEAD, B_SZ), 256, FSMEM>>>();

    // 4: output projection
    cudaFuncSetAttribute(gemm_out, cudaFuncAttributeMaxDynamicSharedMemorySize, GSMEM);
    gemm_out<<<dim3(DMODEL / GBN, MTOT / GBM), 256, GSMEM>>>(out);
}

// round 13
// speedup vs baseline: 1.2830x; 1.0037x over previous
#include <cuda_runtime.h>
#include <cuda_bf16.h>
#include <math.h>
#include <stdint.h>

// Problem constants
#define B_SZ 2
#define SEQ 2048
#define DMODEL 2048
#define NHEAD 16
#define DHEAD 128
#define MTOT (B_SZ * SEQ)   // 4096

// ---------------- scratch (device globals; no allocation allowed) ---------------
__device__ float2 g_rope[(size_t)SEQ * (DHEAD / 2)];   // cos/sin LUT

__device__ __nv_bfloat16 g_xh[(size_t)MTOT * DMODEL];
__device__ __nv_bfloat16 g_xl[(size_t)MTOT * DMODEL];
__device__ __nv_bfloat16 g_qh[(size_t)MTOT * DMODEL];
__device__ __nv_bfloat16 g_ql[(size_t)MTOT * DMODEL];
__device__ __nv_bfloat16 g_oh[(size_t)MTOT * DMODEL];
__device__ __nv_bfloat16 g_ol[(size_t)MTOT * DMODEL];
__device__ __nv_bfloat16 g_kh[(size_t)MTOT * DMODEL];
__device__ __nv_bfloat16 g_kl[(size_t)MTOT * DMODEL];
__device__ __nv_bfloat16 g_vh[(size_t)MTOT * DMODEL];
__device__ __nv_bfloat16 g_vl[(size_t)MTOT * DMODEL];
__device__ __nv_bfloat16 g_wqh[(size_t)DMODEL * DMODEL];
__device__ __nv_bfloat16 g_wql[(size_t)DMODEL * DMODEL];
__device__ __nv_bfloat16 g_wkh[(size_t)DMODEL * DMODEL];
__device__ __nv_bfloat16 g_wkl[(size_t)DMODEL * DMODEL];
__device__ __nv_bfloat16 g_wvh[(size_t)DMODEL * DMODEL];
__device__ __nv_bfloat16 g_wvl[(size_t)DMODEL * DMODEL];
__device__ __nv_bfloat16 g_woh[(size_t)DMODEL * DMODEL];
__device__ __nv_bfloat16 g_wol[(size_t)DMODEL * DMODEL];

// ================= helpers ======================================================
__device__ __forceinline__ uint32_t smem_to_u32(const void* p) {
    uint32_t a;
    asm("{ .reg .u64 t; cvta.to.shared.u64 t, %1; cvt.u32.u64 %0, t; }" : "=r"(a) : "l"(p));
    return a;
}
#define CP_ASYNC16(dst, src) \
    asm volatile("cp.async.cg.shared.global [%0], [%1], 16;" :: "r"(dst), "l"(src) : "memory")
#define CP_COMMIT() asm volatile("cp.async.commit_group;" ::: "memory")
#define CP_WAIT(n)  asm volatile("cp.async.wait_group %0;" :: "n"(n) : "memory")

__device__ __forceinline__ void ldsm_x4(uint32_t& r0, uint32_t& r1, uint32_t& r2, uint32_t& r3,
                                        uint32_t addr) {
    asm volatile("ldmatrix.sync.aligned.m8n8.x4.shared.b16 {%0,%1,%2,%3}, [%4];"
                 : "=r"(r0), "=r"(r1), "=r"(r2), "=r"(r3) : "r"(addr));
}
__device__ __forceinline__ void ldsm_x4_t(uint32_t& r0, uint32_t& r1, uint32_t& r2, uint32_t& r3,
                                          uint32_t addr) {
    asm volatile("ldmatrix.sync.aligned.m8n8.x4.trans.shared.b16 {%0,%1,%2,%3}, [%4];"
                 : "=r"(r0), "=r"(r1), "=r"(r2), "=r"(r3) : "r"(addr));
}
__device__ __forceinline__ void mma_bf16(float* c, const uint32_t* a, const uint32_t* b) {
    asm volatile(
        "mma.sync.aligned.m16n8k16.row.col.f32.bf16.bf16.f32 "
        "{%0,%1,%2,%3}, {%4,%5,%6,%7}, {%8,%9}, {%0,%1,%2,%3};"
        : "+f"(c[0]), "+f"(c[1]), "+f"(c[2]), "+f"(c[3])
        : "r"(a[0]), "r"(a[1]), "r"(a[2]), "r"(a[3]), "r"(b[0]), "r"(b[1]));
}
__device__ __forceinline__ uint32_t pack_bf16x2(float lo, float hi) {
    uint32_t r;
    asm("cvt.rn.bf16x2.f32 %0, %1, %2;" : "=r"(r) : "f"(hi), "f"(lo));
    return r;
}
__device__ __forceinline__ void split_pair(float v0, float v1, uint32_t& h, uint32_t& l) {
    h = pack_bf16x2(v0, v1);
    __nv_bfloat162 hb = *(__nv_bfloat162*)&h;
    l = pack_bf16x2(v0 - __bfloat162float(hb.x), v1 - __bfloat162float(hb.y));
}

// compact GEMM smem layout: logical row L (64B of data), two per 128B phys row,
// swizzled so any 8 consecutive L at fixed col hit 8 distinct 16B granules.
__device__ __forceinline__ uint32_t sw_off(int L, int c) {
    return ((uint32_t)(L >> 1) << 7) +
           ((((uint32_t)(L & 1) << 6) + (uint32_t)c) ^ (((uint32_t)(L >> 1) & 3) << 4));
}

// ================= fused preprocessing: x split + 4 weight splits + rope LUT ====
#define NX4 (MTOT * DMODEL / 4)          // 2097152
#define NW4 (DMODEL * DMODEL / 4)        // 1048576
#define XBLK (NX4 / 256)                 // 8192
#define WBLK (4 * NW4 / 256)             // 16384
#define RBLK (SEQ * (DHEAD / 2) / 256)   // 512
#define PRE_GRID (XBLK + WBLK + RBLK)

__global__ void __launch_bounds__(256) preproc(const float* __restrict__ x,
                                               const float* __restrict__ w0,
                                               const float* __restrict__ w1,
                                               const float* __restrict__ w2,
                                               const float* __restrict__ w3) {
    int blk = blockIdx.x;
    if (blk < XBLK) {
        int i = blk * 256 + threadIdx.x;
        float4 v = ((const float4*)x)[i];
        uint32_t h0, l0, h1, l1;
        split_pair(v.x, v.y, h0, l0);
        split_pair(v.z, v.w, h1, l1);
        ((uint32_t*)g_xh)[2 * i]     = h0;
        ((uint32_t*)g_xh)[2 * i + 1] = h1;
        ((uint32_t*)g_xl)[2 * i]     = l0;
        ((uint32_t*)g_xl)[2 * i + 1] = l1;
    } else if (blk < XBLK + WBLK) {
        int gi = (blk - XBLK) * 256 + threadIdx.x;
        int which = gi / NW4;
        int i = gi - which * NW4;
        const float* in;
        __nv_bfloat16 *hi, *lo;
        switch (which) {
            case 0:  in = w0; hi = g_wqh; lo = g_wql; break;
            case 1:  in = w1; hi = g_wkh; lo = g_wkl; break;
            case 2:  in = w2; hi = g_wvh; lo = g_wvl; break;
            default: in = w3; hi = g_woh; lo = g_wol; break;
        }
        float4 v = ((const float4*)in)[i];
        uint32_t h0, l0, h1, l1;
        split_pair(v.x, v.y, h0, l0);
        split_pair(v.z, v.w, h1, l1);
        ((uint32_t*)hi)[2 * i]     = h0;
        ((uint32_t*)hi)[2 * i + 1] = h1;
        ((uint32_t*)lo)[2 * i]     = l0;
        ((uint32_t*)lo)[2 * i + 1] = l1;
    } else {
        int idx = (blk - XBLK - WBLK) * 256 + threadIdx.x;   // s*64 + i
        int i = idx & 63;
        int s = idx >> 6;
        float inv_freq = powf(10000.0f, -(float)(2 * i) / (float)DHEAD);
        float ang = (float)s * inv_freq;
        float sn, cs;
        sincosf(ang, &sn, &cs);
        g_rope[idx] = make_float2(cs, sn);
    }
}

// ================= HMMA GEMM core (3-stage, single-sync, A-frag pipelined) ======
#define GBM 128
#define GBN 128
#define GBK 32
#define TILE_B 8192                 // 128 logical rows x 64B, packed
#define STAGE_B (4 * TILE_B)        // Ah, Al, Bh, Bl = 32KB
#define NSTAGE 3
#define GSMEM (NSTAGE * STAGE_B)    // 98304

template <typename EPI>
__device__ __forceinline__ void gemm_body(const __nv_bfloat16* Ah, const __nv_bfloat16* Al,
                                          const __nv_bfloat16* Bh, const __nv_bfloat16* Bl,
                                          int m0, int n0, int Kd, char* smem, EPI epi) {
    const uint32_t sbase = smem_to_u32(smem);
    const int tid = threadIdx.x;
    const int wid = tid >> 5;
    const int lid = tid & 31;

    const int wm = (wid >> 2) * 64;
    const int wn = (wid & 3) * 32;

    const int lrow = (lid & 7) + ((lid >> 3) & 1) * 8;
    const int lcolb = ((lid >> 4) & 1) * 16;

    const __nv_bfloat16* srcs[4] = {
        Ah + (size_t)m0 * Kd, Al + (size_t)m0 * Kd,
        Bh + (size_t)n0 * Kd, Bl + (size_t)n0 * Kd };

    // precompute per-thread cp.async slots (8 granules/thread/stage)
    const char* sp[8];
    uint32_t doff[8];
#pragma unroll
    for (int j = 0; j < 8; j++) {
        int idx = j * 256 + tid;          // 0..2047
        int tile = idx >> 9;              // 0..3
        int L = (idx >> 2) & 127;         // logical row
        int g = idx & 3;                  // 16B granule in 64B row
        sp[j] = (const char*)(srcs[tile] + (size_t)L * Kd + g * 8);
        doff[j] = (uint32_t)(tile * TILE_B) + sw_off(L, g * 16);
    }

    const int nchunk = Kd / GBK;          // 64

    float acc[4][4][4];
#pragma unroll
    for (int a = 0; a < 4; a++)
#pragma unroll
        for (int b = 0; b < 4; b++)
#pragma unroll
            for (int cc = 0; cc < 4; cc++) acc[a][b][cc] = 0.f;

    auto issue = [&](int c, int buf) {
        const uint32_t so = sbase + buf * STAGE_B;
        const int kcb = c * (GBK * 2);    // bytes along K
#pragma unroll
        for (int j = 0; j < 8; j++) CP_ASYNC16(so + doff[j], sp[j] + kcb);
        CP_COMMIT();
    };

    issue(0, 0);
    issue(1, 1);

    int buf = 0;        // buffer of chunk c
    int nbuf = 2;       // buffer for chunk c+2
    for (int c = 0; c < nchunk; c++) {
        if (c + 1 < nchunk) { CP_WAIT(1); } else { CP_WAIT(0); }
        __syncthreads();
        if (c + 2 < nchunk) issue(c + 2, nbuf);

        const uint32_t so = sbase + buf * STAGE_B;
        const uint32_t t_ah = so + 0 * TILE_B;
        const uint32_t t_al = so + 1 * TILE_B;
        const uint32_t t_bh = so + 2 * TILE_B;
        const uint32_t t_bl = so + 3 * TILE_B;

#pragma unroll
        for (int kk = 0; kk < 2; kk++) {
            const int kb = kk * 32 + lcolb;

            uint32_t bh[4][2], bl[4][2];
#pragma unroll
            for (int g = 0; g < 2; g++) {
                int L = wn + g * 16 + lrow;
                uint32_t r0, r1, r2, r3;
                ldsm_x4(r0, r1, r2, r3, t_bh + sw_off(L, kb));
                bh[g * 2 + 0][0] = r0; bh[g * 2 + 0][1] = r2;
                bh[g * 2 + 1][0] = r1; bh[g * 2 + 1][1] = r3;
                ldsm_x4(r0, r1, r2, r3, t_bl + sw_off(L, kb));
                bl[g * 2 + 0][0] = r0; bl[g * 2 + 0][1] = r2;
                bl[g * 2 + 1][0] = r1; bl[g * 2 + 1][1] = r3;
            }

            // software-pipelined A fragments: load mt+1 before mt's MMAs
            uint32_t ah[2][4], al[2][4];
            {
                int L = wm + lrow;
                ldsm_x4(ah[0][0], ah[0][1], ah[0][2], ah[0][3], t_ah + sw_off(L, kb));
                ldsm_x4(al[0][0], al[0][1], al[0][2], al[0][3], t_al + sw_off(L, kb));
            }
#pragma unroll
            for (int mt = 0; mt < 4; mt++) {
                const int cur = mt & 1;
                const int nxt = cur ^ 1;
                if (mt < 3) {
                    int L = wm + (mt + 1) * 16 + lrow;
                    ldsm_x4(ah[nxt][0], ah[nxt][1], ah[nxt][2], ah[nxt][3],
                            t_ah + sw_off(L, kb));
                    ldsm_x4(al[nxt][0], al[nxt][1], al[nxt][2], al[nxt][3],
                            t_al + sw_off(L, kb));
                }
#pragma unroll
                for (int nt = 0; nt < 4; nt++) mma_bf16(acc[mt][nt], ah[cur], bh[nt]);
#pragma unroll
                for (int nt = 0; nt < 4; nt++) mma_bf16(acc[mt][nt], ah[cur], bl[nt]);
#pragma unroll
                for (int nt = 0; nt < 4; nt++) mma_bf16(acc[mt][nt], al[cur], bh[nt]);
            }
        }

        buf = (buf == 2) ? 0 : buf + 1;
        nbuf = (nbuf == 2) ? 0 : nbuf + 1;
    }

    const int er = lid >> 2;
    const int ec = (lid & 3) * 2;
#pragma unroll
    for (int mt = 0; mt < 4; mt++) {
#pragma unroll
        for (int nt = 0; nt < 4; nt++) {
            int m = wm + mt * 16 + er;
            int n = wn + nt * 8 + ec;
            epi(m,     n, acc[mt][nt][0], acc[mt][nt][1]);
            epi(m + 8, n, acc[mt][nt][2], acc[mt][nt][3]);
        }
    }
}

// QKV fused GEMM — 2 CTAs/SM. Epilogues: Q -> rope+scale+split bf16,
// K -> rope+split bf16, V -> split bf16.
__global__ void __launch_bounds__(256, 2) gemm_qkv(const __nv_bfloat16* __restrict__ xh,
                                                   const __nv_bfloat16* __restrict__ xl) {
    extern __shared__ char smem[];
    const int wsel = blockIdx.x >> 4;
    const int n0 = (blockIdx.x & 15) * GBN;
    const int m0 = blockIdx.y * GBM;

    const __nv_bfloat16* Bh = (wsel == 0) ? g_wqh : (wsel == 1) ? g_wkh : g_wvh;
    const __nv_bfloat16* Bl = (wsel == 0) ? g_wql : (wsel == 1) ? g_wkl : g_wvl;

    const float scale = 0.08838834764831845f;  // 1/sqrt(128)

    if (wsel == 0) {
        gemm_body(xh, xl, Bh, Bl, m0, n0, DMODEL,
                  smem, [&](int m, int n, float v0, float v1) {
            int grow = m0 + m;
            int col = n0 + n;
            float2 cssn = g_rope[(grow & (SEQ - 1)) * 64 + ((col & 127) >> 1)];
            float r0 = (v0 * cssn.x - v1 * cssn.y) * scale;
            float r1 = (v0 * cssn.y + v1 * cssn.x) * scale;
            uint32_t h, l;
            split_pair(r0, r1, h, l);
            size_t off = (size_t)grow * DMODEL + col;
            *(uint32_t*)&g_qh[off] = h;
            *(uint32_t*)&g_ql[off] = l;
        });
    } else if (wsel == 1) {
        gemm_body(xh, xl, Bh, Bl, m0, n0, DMODEL,
                  smem, [&](int m, int n, float v0, float v1) {
            int grow = m0 + m;
            int col = n0 + n;
            float2 cssn = g_rope[(grow & (SEQ - 1)) * 64 + ((col & 127) >> 1)];
            float r0 = v0 * cssn.x - v1 * cssn.y;
            float r1 = v0 * cssn.y + v1 * cssn.x;
            uint32_t h, l;
            split_pair(r0, r1, h, l);
            size_t off = (size_t)grow * DMODEL + col;
            *(uint32_t*)&g_kh[off] = h;
            *(uint32_t*)&g_kl[off] = l;
        });
    } else {
        gemm_body(xh, xl, Bh, Bl, m0, n0, DMODEL,
                  smem, [&](int m, int n, float v0, float v1) {
            uint32_t h, l;
            split_pair(v0, v1, h, l);
            size_t off = (size_t)(m0 + m) * DMODEL + n0 + n;
            *(uint32_t*)&g_vh[off] = h;
            *(uint32_t*)&g_vl[off] = l;
        });
    }
}

// O projection GEMM — 2 CTAs/SM (reg cap 128)
__global__ void __launch_bounds__(256, 2) gemm_out(float* __restrict__ out) {
    extern __shared__ char smem[];
    const int n0 = blockIdx.x * GBN;
    const int m0 = blockIdx.y * GBM;
    gemm_body(g_oh, g_ol, g_woh, g_wol, m0, n0, DMODEL,
              smem, [&](int m, int n, float v0, float v1) {
        *(float2*)&out[(size_t)(m0 + m) * DMODEL + n0 + n] = make_float2(v0, v1);
    });
}

// ================= HMMA flash attention (causal) ================================
#define FBM 128
#define FBN 64
#define FCH (64 * 80)
#define FARR (4 * FCH)
#define FSTAGE (4 * FARR)
#define FSMEM (2 * FSTAGE)       // 163840

__global__ void __launch_bounds__(256) flash_hmma() {
    extern __shared__ char smem[];
    const uint32_t sbase = smem_to_u32(smem);
    const int tid = threadIdx.x;
    const int wid = tid >> 5;
    const int lid = tid & 31;
    const int qb = (gridDim.x - 1) - blockIdx.x;   // heavy tiles first
    const int h  = blockIdx.y;
    const int b  = blockIdx.z;
    const int q0 = qb * FBM;
    const int wm = wid * 16;

    const int lrow  = (lid & 7) + ((lid >> 3) & 1) * 8;
    const int lcolb = ((lid >> 4) & 1) * 16;
    const int r4  = lid >> 2;
    const int c2  = (lid & 3) * 2;

    // ---- load prepacked Q fragments (bf16 hi/lo, already roped+scaled) ----
    uint32_t qh[8][4], ql[8][4];
    {
        const __nv_bfloat16* qh0 = g_qh + ((size_t)(b * SEQ + q0 + wm + r4)) * DMODEL + h * DHEAD;
        const __nv_bfloat16* ql0 = g_ql + ((size_t)(b * SEQ + q0 + wm + r4)) * DMODEL + h * DHEAD;
#pragma unroll
        for (int ks = 0; ks < 8; ks++) {
#pragma unroll
            for (int half = 0; half < 2; half++) {
                int e = ks * 16 + half * 8 + c2;
                qh[ks][half * 2 + 0] = *(const uint32_t*)(qh0 + e);
                qh[ks][half * 2 + 1] = *(const uint32_t*)(qh0 + 8 * DMODEL + e);
                ql[ks][half * 2 + 0] = *(const uint32_t*)(ql0 + e);
                ql[ks][half * 2 + 1] = *(const uint32_t*)(ql0 + 8 * DMODEL + e);
            }
        }
    }

    float Oa[16][4];
#pragma unroll
    for (int t = 0; t < 16; t++)
#pragma unroll
        for (int c = 0; c < 4; c++) Oa[t][c] = 0.f;
    float m_i[2] = {-1e30f, -1e30f};
    float l_i[2] = {0.f, 0.f};

    const int ntile = (q0 + FBM) / FBN;

    const __nv_bfloat16* asrc[4] = {
        g_kh + ((size_t)(b * SEQ)) * DMODEL + h * DHEAD,
        g_kl + ((size_t)(b * SEQ)) * DMODEL + h * DHEAD,
        g_vh + ((size_t)(b * SEQ)) * DMODEL + h * DHEAD,
        g_vl + ((size_t)(b * SEQ)) * DMODEL + h * DHEAD };

    auto issue_loads = [&](int t) {
        const uint32_t so = sbase + (t & 1) * FSTAGE;
        const int k0 = t * FBN;
#pragma unroll
        for (int j = 0; j < 16; j++) {
            int idx = j * 256 + tid;
            int arr  = idx >> 10;
            int g    = idx & 1023;
            int row  = g >> 4;
            int gran = g & 15;
            const __nv_bfloat16* src = asrc[arr] + (size_t)(k0 + row) * DMODEL + gran * 8;
            uint32_t dst = so + arr * FARR + (gran >> 2) * FCH + row * 80 + (gran & 3) * 16;
            CP_ASYNC16(dst, src);
        }
        CP_COMMIT();
    };

    issue_loads(0);

    for (int t = 0; t < ntile; t++) {
        if (t + 1 < ntile) {
            issue_loads(t + 1);
            CP_WAIT(1);
        } else {
            CP_WAIT(0);
        }
        __syncthreads();

        const int k0 = t * FBN;
        const bool skip = (k0 > q0 + wm + 15);

        if (!skip) {
            const uint32_t so = sbase + (t & 1) * FSTAGE;
            const uint32_t kh_s = so + 0 * FARR;
            const uint32_t kl_s = so + 1 * FARR;
            const uint32_t vh_s = so + 2 * FARR;
            const uint32_t vl_s = so + 3 * FARR;

            float S[8][4];
#pragma unroll
            for (int j = 0; j < 8; j++)
#pragma unroll
                for (int c = 0; c < 4; c++) S[j][c] = 0.f;

#pragma unroll
            for (int ks = 0; ks < 8; ks++) {
                const uint32_t co = (ks >> 1) * FCH + (ks & 1) * 32 + lcolb;
                uint32_t khf[8][2], klf[8][2];
#pragma unroll
                for (int g = 0; g < 4; g++) {
                    uint32_t r0, r1, r2, r3;
                    ldsm_x4(r0, r1, r2, r3, kh_s + co + (g * 16 + lrow) * 80);
                    khf[g * 2 + 0][0] = r0; khf[g * 2 + 0][1] = r2;
                    khf[g * 2 + 1][0] = r1; khf[g * 2 + 1][1] = r3;
                    ldsm_x4(r0, r1, r2, r3, kl_s + co + (g * 16 + lrow) * 80);
                    klf[g * 2 + 0][0] = r0; klf[g * 2 + 0][1] = r2;
                    klf[g * 2 + 1][0] = r1; klf[g * 2 + 1][1] = r3;
                }
#pragma unroll
                for (int j = 0; j < 8; j++) mma_bf16(S[j], qh[ks], khf[j]);
#pragma unroll
                for (int j = 0; j < 8; j++) mma_bf16(S[j], qh[ks], klf[j]);
#pragma unroll
                for (int j = 0; j < 8; j++) mma_bf16(S[j], ql[ks], khf[j]);
            }

            const int qg0 = q0 + wm + r4;
            const int qg1 = qg0 + 8;
            if (k0 + FBN - 1 > q0 + wm) {
#pragma unroll
                for (int j = 0; j < 8; j++) {
                    int kc = k0 + j * 8 + c2;
                    if (kc     > qg0) S[j][0] = -1e30f;
                    if (kc + 1 > qg0) S[j][1] = -1e30f;
                    if (kc     > qg1) S[j][2] = -1e30f;
                    if (kc + 1 > qg1) S[j][3] = -1e30f;
                }
            }

            float mx0 = -1e30f, mx1 = -1e30f;
#pragma unroll
            for (int j = 0; j < 8; j++) {
                mx0 = fmaxf(mx0, fmaxf(S[j][0], S[j][1]));
                mx1 = fmaxf(mx1, fmaxf(S[j][2], S[j][3]));
            }
            mx0 = fmaxf(mx0, __shfl_xor_sync(0xffffffffu, mx0, 1));
            mx0 = fmaxf(mx0, __shfl_xor_sync(0xffffffffu, mx0, 2));
            mx1 = fmaxf(mx1, __shfl_xor_sync(0xffffffffu, mx1, 1));
            mx1 = fmaxf(mx1, __shfl_xor_sync(0xffffffffu, mx1, 2));

            float mn0 = fmaxf(m_i[0], mx0);
            float mn1 = fmaxf(m_i[1], mx1);
            float a0 = __expf(m_i[0] - mn0);
            float a1 = __expf(m_i[1] - mn1);

            // masked entries hold -1e30; __expf underflows to exactly 0.
            float s0 = 0.f, s1 = 0.f;
#pragma unroll
            for (int j = 0; j < 8; j++) {
                float e0 = __expf(S[j][0] - mn0);
                float e1 = __expf(S[j][1] - mn0);
                float e2 = __expf(S[j][2] - mn1);
                float e3 = __expf(S[j][3] - mn1);
                S[j][0] = e0; S[j][1] = e1; S[j][2] = e2; S[j][3] = e3;
                s0 += e0 + e1; s1 += e2 + e3;
            }
            s0 += __shfl_xor_sync(0xffffffffu, s0, 1);
            s0 += __shfl_xor_sync(0xffffffffu, s0, 2);
            s1 += __shfl_xor_sync(0xffffffffu, s1, 1);
            s1 += __shfl_xor_sync(0xffffffffu, s1, 2);

            l_i[0] = l_i[0] * a0 + s0;
            l_i[1] = l_i[1] * a1 + s1;
            m_i[0] = mn0; m_i[1] = mn1;
#pragma unroll
            for (int tt = 0; tt < 16; tt++) {
                Oa[tt][0] *= a0; Oa[tt][1] *= a0;
                Oa[tt][2] *= a1; Oa[tt][3] *= a1;
            }

            uint32_t ph[4][4], pl[4][4];
#pragma unroll
            for (int ks = 0; ks < 4; ks++) {
#pragma unroll
                for (int half = 0; half < 2; half++) {
                    uint32_t h0, l0, h1, l1;
                    split_pair(S[2 * ks + half][0], S[2 * ks + half][1], h0, l0);
                    split_pair(S[2 * ks + half][2], S[2 * ks + half][3], h1, l1);
                    ph[ks][half * 2 + 0] = h0; ph[ks][half * 2 + 1] = h1;
                    pl[ks][half * 2 + 0] = l0; pl[ks][half * 2 + 1] = l1;
                }
            }

#pragma unroll
            for (int ks = 0; ks < 4; ks++) {
#pragma unroll
                for (int tp2 = 0; tp2 < 8; tp2 += 2) {
                    uint32_t vhf[4][2], vlf[4][2];
#pragma unroll
                    for (int u = 0; u < 2; u++) {
                        int tp = tp2 + u;
                        int dbase = tp * 16;
                        int g2 = lid >> 3;
                        int rr = lid & 7;
                        int seqrow = ks * 16 + (g2 & 1) * 8 + rr;
                        int de = dbase + (g2 >> 1) * 8;
                        uint32_t addr_off = (de >> 5) * FCH + seqrow * 80 + ((de & 31) >> 3) * 16;
                        uint32_t b0, b1, b2, b3;
                        ldsm_x4_t(b0, b1, b2, b3, vh_s + addr_off);
                        vhf[2 * u][0] = b0; vhf[2 * u][1] = b1;
                        vhf[2 * u + 1][0] = b2; vhf[2 * u + 1][1] = b3;
                        ldsm_x4_t(b0, b1, b2, b3, vl_s + addr_off);
                        vlf[2 * u][0] = b0; vlf[2 * u][1] = b1;
                        vlf[2 * u + 1][0] = b2; vlf[2 * u + 1][1] = b3;
                    }
#pragma unroll
                    for (int dt = 0; dt < 4; dt++) mma_bf16(Oa[2 * tp2 + dt], ph[ks], vhf[dt]);
#pragma unroll
                    for (int dt = 0; dt < 4; dt++) mma_bf16(Oa[2 * tp2 + dt], pl[ks], vhf[dt]);
#pragma unroll
                    for (int dt = 0; dt < 4; dt++) mma_bf16(Oa[2 * tp2 + dt], ph[ks], vlf[dt]);
                }
            }
        }
        __syncthreads();
    }

    // ---- write out as bf16 hi/lo (feeds gemm_out directly) ----
    float inv0 = 1.0f / l_i[0];
    float inv1 = 1.0f / l_i[1];
    size_t off0 = ((size_t)(b * SEQ + q0 + wm + r4)) * DMODEL + h * DHEAD;
    size_t off1 = off0 + (size_t)8 * DMODEL;
#pragma unroll
    for (int tt = 0; tt < 16; tt++) {
        uint32_t h0, l0, h1, l1;
        split_pair(Oa[tt][0] * inv0, Oa[tt][1] * inv0, h0, l0);
        split_pair(Oa[tt][2] * inv1, Oa[tt][3] * inv1, h1, l1);
        *(uint32_t*)&g_oh[off0 + tt * 8 + c2] = h0;
        *(uint32_t*)&g_ol[off0 + tt * 8 + c2] = l0;
        *(uint32_t*)&g_oh[off1 + tt * 8 + c2] = h1;
        *(uint32_t*)&g_ol[off1 + tt * 8 + c2] = l1;
    }
}

// ---------------- launch --------------------------------------------------------
extern "C" void kernel_launch(void* const* d_in, const int* in_sizes, int n_in,
                              void* d_out, int out_size) {
    const float* x  = (const float*)d_in[0];
    const float* wq = (const float*)d_in[1];
    const float* wk = (const float*)d_in[2];
    const float* wv = (const float*)d_in[3];
    const float* wo = (const float*)d_in[4];
    float* out = (float*)d_out;

    __nv_bfloat16 *xh, *xl;
    cudaGetSymbolAddress((void**)&xh, g_xh);
    cudaGetSymbolAddress((void**)&xl, g_xl);

    // 1: fused preprocessing (x split + weight splits + rope LUT)
    preproc<<<PRE_GRID, 256>>>(x, wq, wk, wv, wo);

    // 2: fused QKV GEMM with rope/scale/split epilogues
    cudaFuncSetAttribute(gemm_qkv, cudaFuncAttributeMaxDynamicSharedMemorySize, GSMEM);
    gemm_qkv<<<dim3(3 * DMODEL / GBN, MTOT / GBM), 256, GSMEM>>>(xh, xl);

    // 3: flash attention -> bf16 hi/lo O
    cudaFuncSetAttribute(flash_hmma, cudaFuncAttributeMaxDynamicSharedMemorySize, FSMEM);
    flash_hmma<<<dim3(SEQ / FBM, NHEAD, B_SZ), 256, FSMEM>>>();

    // 4: output projection
    cudaFuncSetAttribute(gemm_out, cudaFuncAttributeMaxDynamicSharedMemorySize, GSMEM);
    gemm_out<<<dim3(DMODEL / GBN, MTOT / GBM), 256, GSMEM>>>(out);
}